// round 2
// baseline (speedup 1.0000x reference)
#include <cuda_runtime.h>
#include <math.h>

// ---------------- Problem constants ----------------
#define N_NODES 4096
#define N_EDGES 32768
#define E2      (N_EDGES + N_NODES)   // with self loops = 36864
#define IN_FEAT 256
#define HID     64
#define IN_HEAD 64
#define OUT_FEAT 128
#define OUT_HEAD 5
#define F1      (IN_HEAD * HID)       // 4096
#define F2      (OUT_HEAD * OUT_FEAT) // 640
#define NEG_SLOPE 0.2f
#define GAT_EPS 1e-16f

// ---------------- Device scratch (static allocation: allowed) ----------------
__device__ int   g_is64;
__device__ int   g_counts[N_NODES + 1];
__device__ int   g_offs[N_NODES + 1];
__device__ int   g_cursor[N_NODES];
__device__ int   g_esrc[E2];
__device__ float g_H1 [(size_t)N_NODES * F1];   // x @ W1            (64 MB)
__device__ float g_A1s[(size_t)N_NODES * IN_HEAD];
__device__ float g_A1d[(size_t)N_NODES * IN_HEAD];
__device__ float g_H1a[(size_t)N_NODES * F1];   // elu(agg1 + b1)    (64 MB)
__device__ float g_H2 [(size_t)N_NODES * F2];   // H1a @ W2          (10 MB)
__device__ float g_A2s[(size_t)N_NODES * OUT_HEAD];
__device__ float g_A2d[(size_t)N_NODES * OUT_HEAD];
__device__ float g_H2o[(size_t)N_NODES * OUT_FEAT];
__device__ float g_part[32 * OUT_FEAT];

// ---------------- Edge index helpers (int32 vs int64 detection) ----------------
__global__ void k_detect(const int* ei32) {
    // If the tensor is int64 (little-endian, values < 4096), every odd 32-bit
    // word in the first 64 words is zero. For int32 data these are random
    // node ids; P(all zero) ~ (1/4096)^32 ~ 0.
    int t = threadIdx.x;
    int v = ei32[2 * t + 1];
    unsigned any = __ballot_sync(0xffffffffu, v != 0);
    if (t == 0) g_is64 = (any == 0) ? 1 : 0;
}

__device__ __forceinline__ int load_ei(const void* ei, int idx) {
    if (g_is64) return (int)((const long long*)ei)[idx];
    return ((const int*)ei)[idx];
}

// ---------------- CSR build ----------------
__global__ void k_zero_counts() {
    int i = blockIdx.x * blockDim.x + threadIdx.x;
    if (i <= N_NODES) g_counts[i] = 0;
}

__global__ void k_count(const void* ei) {
    int i = blockIdx.x * blockDim.x + threadIdx.x;
    if (i >= E2) return;
    int dst = (i < N_EDGES) ? load_ei(ei, N_EDGES + i) : (i - N_EDGES);
    atomicAdd(&g_counts[dst], 1);
}

__global__ void k_scan() {   // 1 block, 1024 threads; scan 4096 counts
    __shared__ int buf[2][1024];
    int t = threadIdx.x;
    int c0 = g_counts[4 * t], c1 = g_counts[4 * t + 1];
    int c2 = g_counts[4 * t + 2], c3 = g_counts[4 * t + 3];
    int s = c0 + c1 + c2 + c3;
    buf[0][t] = s;
    __syncthreads();
    int pin = 0;
    for (int off = 1; off < 1024; off <<= 1) {
        int v = buf[pin][t];
        if (t >= off) v += buf[pin][t - off];
        buf[pin ^ 1][t] = v;
        pin ^= 1;
        __syncthreads();
    }
    int incl = buf[pin][t];
    int base = incl - s;
    g_offs[4 * t]     = base;
    g_offs[4 * t + 1] = base + c0;
    g_offs[4 * t + 2] = base + c0 + c1;
    g_offs[4 * t + 3] = base + c0 + c1 + c2;
    g_cursor[4 * t]     = base;
    g_cursor[4 * t + 1] = base + c0;
    g_cursor[4 * t + 2] = base + c0 + c1;
    g_cursor[4 * t + 3] = base + c0 + c1 + c2;
    if (t == 1023) g_offs[N_NODES] = incl;
}

__global__ void k_scatter(const void* ei) {
    int i = blockIdx.x * blockDim.x + threadIdx.x;
    if (i >= E2) return;
    int src, dst;
    if (i < N_EDGES) { src = load_ei(ei, i); dst = load_ei(ei, N_EDGES + i); }
    else             { src = i - N_EDGES;    dst = i - N_EDGES; }
    int pos = atomicAdd(&g_cursor[dst], 1);
    g_esrc[pos] = src;
}

// ---------------- Tiled fp32 GEMM: C[M,N] = A[M,K] * B[K,N] ----------------
// BM=BN=64, BK=16, 256 threads, 4x4 microtile. All dims divisible.
__global__ void sgemm64(const float* __restrict__ A, const float* __restrict__ B,
                        float* __restrict__ C, int M, int N, int K) {
    __shared__ float As[16][64];
    __shared__ float Bs[16][64];
    int t = threadIdx.x;
    int bx = blockIdx.x, by = blockIdx.y;
    int tx = t & 15, ty = t >> 4;
    const float* Ab = A + (size_t)(by * 64) * K;
    const float* Bb = B + bx * 64;
    int ar = t >> 2;          // 0..63
    int ac = (t & 3) * 4;     // 0,4,8,12
    int br = t >> 4;          // 0..15
    int bc = (t & 15) * 4;    // 0..60
    float acc[4][4] = {};
    for (int k0 = 0; k0 < K; k0 += 16) {
        float4 av = *(const float4*)(Ab + (size_t)ar * K + k0 + ac);
        As[ac + 0][ar] = av.x; As[ac + 1][ar] = av.y;
        As[ac + 2][ar] = av.z; As[ac + 3][ar] = av.w;
        float4 bv = *(const float4*)(Bb + (size_t)(k0 + br) * N + bc);
        *(float4*)&Bs[br][bc] = bv;
        __syncthreads();
#pragma unroll
        for (int k = 0; k < 16; k++) {
            float4 a4 = *(const float4*)&As[k][ty * 4];
            float4 b4 = *(const float4*)&Bs[k][tx * 4];
            acc[0][0] += a4.x * b4.x; acc[0][1] += a4.x * b4.y;
            acc[0][2] += a4.x * b4.z; acc[0][3] += a4.x * b4.w;
            acc[1][0] += a4.y * b4.x; acc[1][1] += a4.y * b4.y;
            acc[1][2] += a4.y * b4.z; acc[1][3] += a4.y * b4.w;
            acc[2][0] += a4.z * b4.x; acc[2][1] += a4.z * b4.y;
            acc[2][2] += a4.z * b4.z; acc[2][3] += a4.z * b4.w;
            acc[3][0] += a4.w * b4.x; acc[3][1] += a4.w * b4.y;
            acc[3][2] += a4.w * b4.z; acc[3][3] += a4.w * b4.w;
        }
        __syncthreads();
    }
    float* Cb = C + (size_t)(by * 64 + ty * 4) * N + bx * 64 + tx * 4;
#pragma unroll
    for (int i = 0; i < 4; i++) {
        float4 v = make_float4(acc[i][0], acc[i][1], acc[i][2], acc[i][3]);
        *(float4*)(Cb + (size_t)i * N) = v;
    }
}

// GEMM wrappers referencing device globals directly (no host symbol lookup).
__global__ void sgemm1_wrap(const float* __restrict__ A, const float* __restrict__ B);
__global__ void sgemm2_wrap(const float* __restrict__ B);

// ---------------- Attention dot products ----------------
__global__ void k_dots1(const float* __restrict__ att_src, const float* __restrict__ att_dst) {
    int warp = (blockIdx.x * blockDim.x + threadIdx.x) >> 5;
    int lane = threadIdx.x & 31;
    int n = warp >> 6, h = warp & 63;
    const float* row = g_H1 + (size_t)n * F1 + h * HID;
    float v1 = row[lane], v2 = row[lane + 32];
    float sa = v1 * att_src[h * HID + lane] + v2 * att_src[h * HID + lane + 32];
    float sd = v1 * att_dst[h * HID + lane] + v2 * att_dst[h * HID + lane + 32];
#pragma unroll
    for (int o = 16; o > 0; o >>= 1) {
        sa += __shfl_xor_sync(0xffffffffu, sa, o);
        sd += __shfl_xor_sync(0xffffffffu, sd, o);
    }
    if (lane == 0) {
        g_A1s[n * IN_HEAD + h] = sa;
        g_A1d[n * IN_HEAD + h] = sd;
    }
}

__global__ void k_dots2(const float* __restrict__ att_src, const float* __restrict__ att_dst) {
    int warp = (blockIdx.x * blockDim.x + threadIdx.x) >> 5;
    int lane = threadIdx.x & 31;
    if (warp >= N_NODES * OUT_HEAD) return;
    int n = warp / OUT_HEAD, h = warp % OUT_HEAD;
    const float* row = g_H2 + (size_t)n * F2 + h * OUT_FEAT;
    float sa = 0.f, sd = 0.f;
#pragma unroll
    for (int k = 0; k < 4; k++) {
        int c = lane + 32 * k;
        float v = row[c];
        sa += v * att_src[h * OUT_FEAT + c];
        sd += v * att_dst[h * OUT_FEAT + c];
    }
#pragma unroll
    for (int o = 16; o > 0; o >>= 1) {
        sa += __shfl_xor_sync(0xffffffffu, sa, o);
        sd += __shfl_xor_sync(0xffffffffu, sd, o);
    }
    if (lane == 0) {
        g_A2s[n * OUT_HEAD + h] = sa;
        g_A2d[n * OUT_HEAD + h] = sd;
    }
}

__device__ __forceinline__ float leaky(float x) { return x > 0.f ? x : NEG_SLOPE * x; }

// ---------------- Layer-1 softmax + aggregation + bias + elu ----------------
// block = one dst node, 256 threads. 64 heads x 64 channels.
__global__ void k_agg1(const float* __restrict__ b1) {
    int n = blockIdx.x;
    int t = threadIdx.x;
    int h = t & 63, slot = t >> 6;        // 4 slots
    int beg = g_offs[n], end = g_offs[n + 1];
    float adst = g_A1d[n * IN_HEAD + h];

    __shared__ float red[4][64];
    __shared__ float sm_m[64], sm_inv[64];
    __shared__ int   srcb[8];
    __shared__ float alpha[8][64];

    // pass 1: per-head max
    float mx = -1e30f;
    for (int j = beg + slot; j < end; j += 4) {
        int s = g_esrc[j];
        mx = fmaxf(mx, leaky(g_A1s[s * IN_HEAD + h] + adst));
    }
    red[slot][h] = mx;
    __syncthreads();
    if (slot == 0) {
        float m = fmaxf(fmaxf(red[0][h], red[1][h]), fmaxf(red[2][h], red[3][h]));
        sm_m[h] = m;
    }
    __syncthreads();
    float M = sm_m[h];

    // pass 2: per-head exp-sum
    float sum = 0.f;
    for (int j = beg + slot; j < end; j += 4) {
        int s = g_esrc[j];
        sum += expf(leaky(g_A1s[s * IN_HEAD + h] + adst) - M);
    }
    red[slot][h] = sum;
    __syncthreads();
    if (slot == 0) {
        float d = red[0][h] + red[1][h] + red[2][h] + red[3][h];
        sm_inv[h] = 1.0f / (d + GAT_EPS);
    }
    __syncthreads();

    // pass 3: weighted aggregation
    int c = t & 63, g = t >> 6;           // thread owns channel c, head group g
    float acc[16];
#pragma unroll
    for (int k = 0; k < 16; k++) acc[k] = 0.f;

    for (int jb = beg; jb < end; jb += 8) {
        int cnt = min(8, end - jb);
        if (t < cnt) srcb[t] = g_esrc[jb + t];
        __syncthreads();
        for (int j = slot; j < cnt; j += 4) {
            int s = srcb[j];
            float e = leaky(g_A1s[s * IN_HEAD + h] + adst);
            alpha[j][h] = expf(e - sm_m[h]) * sm_inv[h];
        }
        __syncthreads();
        for (int j = 0; j < cnt; j++) {
            const float* row = g_H1 + (size_t)srcb[j] * F1;
#pragma unroll
            for (int k = 0; k < 16; k++) {
                int hh = g * 16 + k;
                acc[k] += alpha[j][hh] * row[hh * HID + c];
            }
        }
        __syncthreads();
    }
#pragma unroll
    for (int k = 0; k < 16; k++) {
        int idx = (g * 16 + k) * HID + c;
        float v = acc[k] + b1[idx];
        g_H1a[(size_t)n * F1 + idx] = v > 0.f ? v : expm1f(v);  // elu
    }
}

// ---------------- Layer-2 softmax + aggregation + head-mean + bias ----------------
// block = one dst node, 128 threads. 5 heads x 128 channels.
__global__ void k_agg2(const float* __restrict__ b2) {
    int n = blockIdx.x;
    int t = threadIdx.x;
    int beg = g_offs[n], end = g_offs[n + 1];

    __shared__ float sm_m[OUT_HEAD], sm_inv[OUT_HEAD];
    __shared__ int   srcb[16];
    __shared__ float alpha[16][OUT_HEAD];

    if (t < OUT_HEAD) {
        float adst = g_A2d[n * OUT_HEAD + t];
        float mx = -1e30f;
        for (int j = beg; j < end; j++)
            mx = fmaxf(mx, leaky(g_A2s[g_esrc[j] * OUT_HEAD + t] + adst));
        float sum = 0.f;
        for (int j = beg; j < end; j++)
            sum += expf(leaky(g_A2s[g_esrc[j] * OUT_HEAD + t] + adst) - mx);
        sm_m[t] = mx;
        sm_inv[t] = 1.0f / (sum + GAT_EPS);
    }
    __syncthreads();

    float acc[OUT_HEAD] = {0.f, 0.f, 0.f, 0.f, 0.f};
    for (int jb = beg; jb < end; jb += 16) {
        int cnt = min(16, end - jb);
        if (t < cnt) srcb[t] = g_esrc[jb + t];
        __syncthreads();
        if (t < cnt * OUT_HEAD) {
            int j = t / OUT_HEAD, h = t % OUT_HEAD;
            int s = srcb[j];
            float e = leaky(g_A2s[s * OUT_HEAD + h] + g_A2d[n * OUT_HEAD + h]);
            alpha[j][h] = expf(e - sm_m[h]) * sm_inv[h];
        }
        __syncthreads();
        for (int j = 0; j < cnt; j++) {
            const float* row = g_H2 + (size_t)srcb[j] * F2;
#pragma unroll
            for (int h = 0; h < OUT_HEAD; h++)
                acc[h] += alpha[j][h] * row[h * OUT_FEAT + t];
        }
        __syncthreads();
    }
    float o = (acc[0] + acc[1] + acc[2] + acc[3] + acc[4]) * 0.2f + b2[t];
    g_H2o[(size_t)n * OUT_FEAT + t] = o;
}

// ---------------- Final node-mean + tanh ----------------
__global__ void k_part() {   // 32 blocks x 128 threads
    int b = blockIdx.x, c = threadIdx.x;
    float s = 0.f;
    for (int i = 0; i < N_NODES / 32; i++)
        s += g_H2o[(size_t)(b * (N_NODES / 32) + i) * OUT_FEAT + c];
    g_part[b * OUT_FEAT + c] = s;
}

__global__ void k_final(float* __restrict__ out) {
    int c = threadIdx.x;
    float s = 0.f;
#pragma unroll
    for (int b = 0; b < 32; b++) s += g_part[b * OUT_FEAT + c];
    out[c] = tanhf(s / (float)N_NODES);
}

// GEMM launchers: fetch device-global addresses via a pointer-publishing kernel
// is unnecessary — we use small __global__ wrappers that call into the tiled
// GEMM body with global-array addresses (valid in device code).
__global__ void sgemm1_wrap_dummy() {}

extern "C" void kernel_launch(void* const* d_in, const int* in_sizes, int n_in,
                              void* d_out, int out_size) {
    const float* x        = (const float*)d_in[0];
    const void*  ei       = d_in[1];
    const float* W1       = (const float*)d_in[2];
    const float* att_src1 = (const float*)d_in[3];
    const float* att_dst1 = (const float*)d_in[4];
    const float* b1       = (const float*)d_in[5];
    const float* W2       = (const float*)d_in[6];
    const float* att_src2 = (const float*)d_in[7];
    const float* att_dst2 = (const float*)d_in[8];
    const float* b2       = (const float*)d_in[9];
    float* out = (float*)d_out;

    // Resolve device-global buffer addresses once (pure query, capture-safe).
    static float* s_H1  = nullptr;
    static float* s_H1a = nullptr;
    static float* s_H2  = nullptr;
    if (!s_H1)  cudaGetSymbolAddress((void**)&s_H1,  g_H1);
    if (!s_H1a) cudaGetSymbolAddress((void**)&s_H1a, g_H1a);
    if (!s_H2)  cudaGetSymbolAddress((void**)&s_H2,  g_H2);

    k_detect<<<1, 32>>>((const int*)ei);
    k_zero_counts<<<(N_NODES + 256) / 256, 256>>>();
    k_count<<<(E2 + 255) / 256, 256>>>(ei);
    k_scan<<<1, 1024>>>();
    k_scatter<<<(E2 + 255) / 256, 256>>>(ei);

    // GEMM1: H1 = x @ W1   [4096,256]x[256,4096]
    {
        dim3 grid(F1 / 64, N_NODES / 64);
        sgemm64<<<grid, 256>>>(x, W1, s_H1, N_NODES, F1, IN_FEAT);
    }
    k_dots1<<<(N_NODES * IN_HEAD) / 8, 256>>>(att_src1, att_dst1);
    k_agg1<<<N_NODES, 256>>>(b1);

    // GEMM2: H2 = H1a @ W2   [4096,4096]x[4096,640]
    {
        dim3 grid(F2 / 64, N_NODES / 64);
        sgemm64<<<grid, 256>>>(s_H1a, W2, s_H2, N_NODES, F2, F1);
    }
    k_dots2<<<((N_NODES * OUT_HEAD + 7) / 8), 256>>>(att_src2, att_dst2);
    k_agg2<<<N_NODES, 128>>>(b2);

    k_part<<<32, 128>>>();
    k_final<<<1, 128>>>(out);
}

// round 4
// speedup vs baseline: 1.6868x; 1.6868x over previous
#include <cuda_runtime.h>
#include <cuda_bf16.h>
#include <stdint.h>
#include <math.h>

typedef __nv_bfloat16 bf16;

// ---------------- Problem constants ----------------
#define N_NODES 4096
#define N_EDGES 32768
#define E2      (N_EDGES + N_NODES)   // with self loops = 36864
#define IN_FEAT 256
#define HID     64
#define IN_HEAD 64
#define OUT_FEAT 128
#define OUT_HEAD 5
#define F1      (IN_HEAD * HID)       // 4096
#define F2      (OUT_HEAD * OUT_FEAT) // 640
#define NEG_SLOPE 0.2f
#define GAT_EPS 1e-16f

#define K1E (3 * IN_FEAT)             // 768  (split-expanded K for GEMM1)
#define K2E (3 * F1)                  // 12288 (split-expanded K for GEMM2)

// ---------------- Device scratch ----------------
__device__ int   g_is64;
__device__ int   g_counts[N_NODES + 1];
__device__ int   g_offs[N_NODES + 1];
__device__ int   g_cursor[N_NODES];
__device__ int   g_esrc[E2];
__device__ float g_H1 [(size_t)N_NODES * F1];     // x @ W1  (fp32, 64 MB)
__device__ float g_A1s[(size_t)N_NODES * IN_HEAD];
__device__ float g_A1d[(size_t)N_NODES * IN_HEAD];
__device__ float g_H2 [(size_t)N_NODES * F2];     // H1a @ W2 (fp32, 10 MB)
__device__ float g_A2s[(size_t)N_NODES * OUT_HEAD];
__device__ float g_A2d[(size_t)N_NODES * OUT_HEAD];
__device__ float g_H2o[(size_t)N_NODES * OUT_FEAT];
__device__ float g_part[32 * OUT_FEAT];

// split-bf16 expanded operands: A'' = [A_hi, A_hi, A_lo], B'' = [B_hi, B_lo, B_hi]
__device__ bf16  g_xe  [(size_t)N_NODES * K1E];   // 6 MB
__device__ bf16  g_W1e [(size_t)K1E * F1];        // 6 MB
__device__ bf16  g_H1ae[(size_t)N_NODES * K2E];   // 100 MB
__device__ bf16  g_W2e [(size_t)K2E * F2];        // 15.7 MB

// ---------------- Edge index helpers (int32 vs int64 detection) ----------------
__global__ void k_detect(const int* ei32) {
    int t = threadIdx.x;
    int v = ei32[2 * t + 1];
    unsigned any = __ballot_sync(0xffffffffu, v != 0);
    if (t == 0) g_is64 = (any == 0) ? 1 : 0;
}

__device__ __forceinline__ int load_ei(const void* ei, int idx) {
    if (g_is64) return (int)((const long long*)ei)[idx];
    return ((const int*)ei)[idx];
}

// ---------------- CSR build ----------------
__global__ void k_zero_counts() {
    int i = blockIdx.x * blockDim.x + threadIdx.x;
    if (i <= N_NODES) g_counts[i] = 0;
}

__global__ void k_count(const void* ei) {
    int i = blockIdx.x * blockDim.x + threadIdx.x;
    if (i >= E2) return;
    int dst = (i < N_EDGES) ? load_ei(ei, N_EDGES + i) : (i - N_EDGES);
    atomicAdd(&g_counts[dst], 1);
}

__global__ void k_scan() {   // 1 block, 1024 threads; scan 4096 counts
    __shared__ int buf[2][1024];
    int t = threadIdx.x;
    int c0 = g_counts[4 * t], c1 = g_counts[4 * t + 1];
    int c2 = g_counts[4 * t + 2], c3 = g_counts[4 * t + 3];
    int s = c0 + c1 + c2 + c3;
    buf[0][t] = s;
    __syncthreads();
    int pin = 0;
    for (int off = 1; off < 1024; off <<= 1) {
        int v = buf[pin][t];
        if (t >= off) v += buf[pin][t - off];
        buf[pin ^ 1][t] = v;
        pin ^= 1;
        __syncthreads();
    }
    int incl = buf[pin][t];
    int base = incl - s;
    g_offs[4 * t]     = base;
    g_offs[4 * t + 1] = base + c0;
    g_offs[4 * t + 2] = base + c0 + c1;
    g_offs[4 * t + 3] = base + c0 + c1 + c2;
    g_cursor[4 * t]     = base;
    g_cursor[4 * t + 1] = base + c0;
    g_cursor[4 * t + 2] = base + c0 + c1;
    g_cursor[4 * t + 3] = base + c0 + c1 + c2;
    if (t == 1023) g_offs[N_NODES] = incl;
}

__global__ void k_scatter(const void* ei) {
    int i = blockIdx.x * blockDim.x + threadIdx.x;
    if (i >= E2) return;
    int src, dst;
    if (i < N_EDGES) { src = load_ei(ei, i); dst = load_ei(ei, N_EDGES + i); }
    else             { src = i - N_EDGES;    dst = i - N_EDGES; }
    int pos = atomicAdd(&g_cursor[dst], 1);
    g_esrc[pos] = src;
}

// ---------------- split-bf16 expansion kernels ----------------
__device__ __forceinline__ void split2(float v, bf16& hi, bf16& lo) {
    hi = __float2bfloat16(v);
    lo = __float2bfloat16(v - __bfloat162float(hi));
}

__global__ void k_split_x(const float* __restrict__ x) {   // [4096,256] -> [4096,768]
    int i = blockIdx.x * blockDim.x + threadIdx.x;         // 1M threads
    int m = i >> 8, k = i & 255;
    bf16 hi, lo; split2(x[i], hi, lo);
    bf16* row = g_xe + (size_t)m * K1E;
    row[k] = hi; row[IN_FEAT + k] = hi; row[2 * IN_FEAT + k] = lo;
}

__global__ void k_split_W1(const float* __restrict__ W) {  // [256,4096] -> [768,4096]
    int i = blockIdx.x * blockDim.x + threadIdx.x;         // 1M threads
    int k = i >> 12, n = i & 4095;
    bf16 hi, lo; split2(W[i], hi, lo);
    g_W1e[(size_t)k * F1 + n]                    = hi;
    g_W1e[(size_t)(IN_FEAT + k) * F1 + n]        = lo;
    g_W1e[(size_t)(2 * IN_FEAT + k) * F1 + n]    = hi;
}

__global__ void k_split_W2(const float* __restrict__ W) {  // [4096,640] -> [12288,640]
    int i = blockIdx.x * blockDim.x + threadIdx.x;         // 2.62M threads
    if (i >= F1 * F2) return;
    int k = i / F2, n = i % F2;
    bf16 hi, lo; split2(W[i], hi, lo);
    g_W2e[(size_t)k * F2 + n]              = hi;
    g_W2e[(size_t)(F1 + k) * F2 + n]       = lo;
    g_W2e[(size_t)(2 * F1 + k) * F2 + n]   = hi;
}

// ---------------- bf16 tensor-core GEMM ----------------
// C[M,N] = A[M,K] * B[K,N], A/B bf16 row-major, C fp32.
// BM=128, BN=128, BK=32, 256 threads (8 warps, 2x4), warp tile 64x32.
#define BM 128
#define BN 128
#define BK 32
#define APITCH (BK + 8)
#define BPITCH (BN + 8)

__global__ __launch_bounds__(256, 2)
void hgemm(const bf16* __restrict__ A, const bf16* __restrict__ B,
           float* __restrict__ C, int M, int N, int K) {
    __shared__ bf16 sA[2][BM][APITCH];
    __shared__ bf16 sB[2][BK][BPITCH];
    int t = threadIdx.x, lane = t & 31, warp = t >> 5;
    int wm = (warp >> 2) * 64;   // 0 or 64
    int wn = (warp & 3) * 32;    // 0,32,64,96
    int bx = blockIdx.x, by = blockIdx.y;
    const bf16* Ab = A + (size_t)(by * BM) * K;
    const bf16* Bb = B + bx * BN;

    int a_row = t >> 2;          // 0..63, +64
    int a_col = (t & 3) * 8;
    int b_row = t >> 4;          // 0..15, +16
    int b_col = (t & 15) * 8;

    float acc[4][4][4];
#pragma unroll
    for (int i = 0; i < 4; i++)
#pragma unroll
        for (int j = 0; j < 4; j++)
#pragma unroll
            for (int r = 0; r < 4; r++) acc[i][j][r] = 0.f;

    auto issue = [&](int s, int k0) {
        uint32_t da0 = (uint32_t)__cvta_generic_to_shared(&sA[s][a_row][a_col]);
        uint32_t da1 = (uint32_t)__cvta_generic_to_shared(&sA[s][a_row + 64][a_col]);
        const bf16* ga0 = Ab + (size_t)a_row * K + k0 + a_col;
        const bf16* ga1 = Ab + (size_t)(a_row + 64) * K + k0 + a_col;
        asm volatile("cp.async.cg.shared.global [%0], [%1], 16;" :: "r"(da0), "l"(ga0));
        asm volatile("cp.async.cg.shared.global [%0], [%1], 16;" :: "r"(da1), "l"(ga1));
        uint32_t db0 = (uint32_t)__cvta_generic_to_shared(&sB[s][b_row][b_col]);
        uint32_t db1 = (uint32_t)__cvta_generic_to_shared(&sB[s][b_row + 16][b_col]);
        const bf16* gb0 = Bb + (size_t)(k0 + b_row) * N + b_col;
        const bf16* gb1 = Bb + (size_t)(k0 + b_row + 16) * N + b_col;
        asm volatile("cp.async.cg.shared.global [%0], [%1], 16;" :: "r"(db0), "l"(gb0));
        asm volatile("cp.async.cg.shared.global [%0], [%1], 16;" :: "r"(db1), "l"(gb1));
        asm volatile("cp.async.commit_group;");
    };

    int nsteps = K / BK;
    issue(0, 0);
    for (int s = 0; s < nsteps; s++) {
        if (s + 1 < nsteps) {
            issue((s + 1) & 1, (s + 1) * BK);
            asm volatile("cp.async.wait_group 1;");
        } else {
            asm volatile("cp.async.wait_group 0;");
        }
        __syncthreads();
        int buf = s & 1;
#pragma unroll
        for (int kk = 0; kk < 2; kk++) {
            int k = kk * 16;
            uint32_t ar[4][4], br[4][2];
#pragma unroll
            for (int mi = 0; mi < 4; mi++) {
                int row = wm + mi * 16 + (lane & 7) + ((lane >> 3) & 1) * 8;
                int col = k + (lane >> 4) * 8;
                uint32_t addr = (uint32_t)__cvta_generic_to_shared(&sA[buf][row][col]);
                asm volatile("ldmatrix.sync.aligned.m8n8.x4.shared.b16 {%0,%1,%2,%3}, [%4];"
                             : "=r"(ar[mi][0]), "=r"(ar[mi][1]), "=r"(ar[mi][2]), "=r"(ar[mi][3])
                             : "r"(addr));
            }
#pragma unroll
            for (int ni = 0; ni < 4; ni++) {
                int l = lane & 15;
                int rrow = k + (l & 7) + ((l >> 3) & 1) * 8;
                uint32_t addr = (uint32_t)__cvta_generic_to_shared(&sB[buf][rrow][wn + ni * 8]);
                asm volatile("ldmatrix.sync.aligned.m8n8.x2.trans.shared.b16 {%0,%1}, [%2];"
                             : "=r"(br[ni][0]), "=r"(br[ni][1]) : "r"(addr));
            }
#pragma unroll
            for (int mi = 0; mi < 4; mi++)
#pragma unroll
                for (int ni = 0; ni < 4; ni++) {
                    asm volatile(
                        "mma.sync.aligned.m16n8k16.row.col.f32.bf16.bf16.f32 "
                        "{%0,%1,%2,%3}, {%4,%5,%6,%7}, {%8,%9}, {%0,%1,%2,%3};"
                        : "+f"(acc[mi][ni][0]), "+f"(acc[mi][ni][1]),
                          "+f"(acc[mi][ni][2]), "+f"(acc[mi][ni][3])
                        : "r"(ar[mi][0]), "r"(ar[mi][1]), "r"(ar[mi][2]), "r"(ar[mi][3]),
                          "r"(br[ni][0]), "r"(br[ni][1]));
                }
        }
        __syncthreads();
    }
    float* Cb = C + (size_t)(by * BM + wm) * N + bx * BN + wn;
#pragma unroll
    for (int mi = 0; mi < 4; mi++)
#pragma unroll
        for (int ni = 0; ni < 4; ni++) {
            int r0 = mi * 16 + (lane >> 2);
            int c0 = ni * 8 + (lane & 3) * 2;
            *(float2*)(Cb + (size_t)r0 * N + c0)       = make_float2(acc[mi][ni][0], acc[mi][ni][1]);
            *(float2*)(Cb + (size_t)(r0 + 8) * N + c0) = make_float2(acc[mi][ni][2], acc[mi][ni][3]);
        }
}

// ---------------- Attention dot products ----------------
__global__ void k_dots1(const float* __restrict__ att_src, const float* __restrict__ att_dst) {
    int warp = (blockIdx.x * blockDim.x + threadIdx.x) >> 5;
    int lane = threadIdx.x & 31;
    int n = warp >> 6, h = warp & 63;
    const float* row = g_H1 + (size_t)n * F1 + h * HID;
    float v1 = row[lane], v2 = row[lane + 32];
    float sa = v1 * att_src[h * HID + lane] + v2 * att_src[h * HID + lane + 32];
    float sd = v1 * att_dst[h * HID + lane] + v2 * att_dst[h * HID + lane + 32];
#pragma unroll
    for (int o = 16; o > 0; o >>= 1) {
        sa += __shfl_xor_sync(0xffffffffu, sa, o);
        sd += __shfl_xor_sync(0xffffffffu, sd, o);
    }
    if (lane == 0) {
        g_A1s[n * IN_HEAD + h] = sa;
        g_A1d[n * IN_HEAD + h] = sd;
    }
}

__global__ void k_dots2(const float* __restrict__ att_src, const float* __restrict__ att_dst) {
    int warp = (blockIdx.x * blockDim.x + threadIdx.x) >> 5;
    int lane = threadIdx.x & 31;
    if (warp >= N_NODES * OUT_HEAD) return;
    int n = warp / OUT_HEAD, h = warp % OUT_HEAD;
    const float* row = g_H2 + (size_t)n * F2 + h * OUT_FEAT;
    float sa = 0.f, sd = 0.f;
#pragma unroll
    for (int k = 0; k < 4; k++) {
        int c = lane + 32 * k;
        float v = row[c];
        sa += v * att_src[h * OUT_FEAT + c];
        sd += v * att_dst[h * OUT_FEAT + c];
    }
#pragma unroll
    for (int o = 16; o > 0; o >>= 1) {
        sa += __shfl_xor_sync(0xffffffffu, sa, o);
        sd += __shfl_xor_sync(0xffffffffu, sd, o);
    }
    if (lane == 0) {
        g_A2s[n * OUT_HEAD + h] = sa;
        g_A2d[n * OUT_HEAD + h] = sd;
    }
}

__device__ __forceinline__ float leaky(float x) { return x > 0.f ? x : NEG_SLOPE * x; }

// ---------------- Layer-1 softmax + aggregation + bias + elu -> split-bf16 ----------------
__global__ void k_agg1(const float* __restrict__ b1) {
    int n = blockIdx.x;
    int t = threadIdx.x;
    int h = t & 63, slot = t >> 6;
    int beg = g_offs[n], end = g_offs[n + 1];
    float adst = g_A1d[n * IN_HEAD + h];

    __shared__ float red[4][64];
    __shared__ float sm_m[64], sm_inv[64];
    __shared__ int   srcb[8];
    __shared__ float alpha[8][64];

    float mx = -1e30f;
    for (int j = beg + slot; j < end; j += 4) {
        int s = g_esrc[j];
        mx = fmaxf(mx, leaky(g_A1s[s * IN_HEAD + h] + adst));
    }
    red[slot][h] = mx;
    __syncthreads();
    if (slot == 0) {
        sm_m[h] = fmaxf(fmaxf(red[0][h], red[1][h]), fmaxf(red[2][h], red[3][h]));
    }
    __syncthreads();
    float M = sm_m[h];

    float sum = 0.f;
    for (int j = beg + slot; j < end; j += 4) {
        int s = g_esrc[j];
        sum += expf(leaky(g_A1s[s * IN_HEAD + h] + adst) - M);
    }
    red[slot][h] = sum;
    __syncthreads();
    if (slot == 0) {
        float d = red[0][h] + red[1][h] + red[2][h] + red[3][h];
        sm_inv[h] = 1.0f / (d + GAT_EPS);
    }
    __syncthreads();

    int c = t & 63, g = t >> 6;
    float acc[16];
#pragma unroll
    for (int k = 0; k < 16; k++) acc[k] = 0.f;

    for (int jb = beg; jb < end; jb += 8) {
        int cnt = min(8, end - jb);
        if (t < cnt) srcb[t] = g_esrc[jb + t];
        __syncthreads();
        for (int j = slot; j < cnt; j += 4) {
            int s = srcb[j];
            float e = leaky(g_A1s[s * IN_HEAD + h] + adst);
            alpha[j][h] = expf(e - sm_m[h]) * sm_inv[h];
        }
        __syncthreads();
        for (int j = 0; j < cnt; j++) {
            const float* row = g_H1 + (size_t)srcb[j] * F1;
#pragma unroll
            for (int k = 0; k < 16; k++) {
                int hh = g * 16 + k;
                acc[k] += alpha[j][hh] * row[hh * HID + c];
            }
        }
        __syncthreads();
    }
    bf16* rowo = g_H1ae + (size_t)n * K2E;
#pragma unroll
    for (int k = 0; k < 16; k++) {
        int idx = (g * 16 + k) * HID + c;
        float v = acc[k] + b1[idx];
        v = v > 0.f ? v : expm1f(v);   // elu
        bf16 hi, lo; split2(v, hi, lo);
        rowo[idx] = hi; rowo[F1 + idx] = hi; rowo[2 * F1 + idx] = lo;
    }
}

// ---------------- Layer-2 softmax + aggregation + head-mean + bias ----------------
__global__ void k_agg2(const float* __restrict__ b2) {
    int n = blockIdx.x;
    int t = threadIdx.x;
    int beg = g_offs[n], end = g_offs[n + 1];

    __shared__ float sm_m[OUT_HEAD], sm_inv[OUT_HEAD];
    __shared__ int   srcb[16];
    __shared__ float alpha[16][OUT_HEAD];

    if (t < OUT_HEAD) {
        float adst = g_A2d[n * OUT_HEAD + t];
        float mx = -1e30f;
        for (int j = beg; j < end; j++)
            mx = fmaxf(mx, leaky(g_A2s[g_esrc[j] * OUT_HEAD + t] + adst));
        float sum = 0.f;
        for (int j = beg; j < end; j++)
            sum += expf(leaky(g_A2s[g_esrc[j] * OUT_HEAD + t] + adst) - mx);
        sm_m[t] = mx;
        sm_inv[t] = 1.0f / (sum + GAT_EPS);
    }
    __syncthreads();

    float acc[OUT_HEAD] = {0.f, 0.f, 0.f, 0.f, 0.f};
    for (int jb = beg; jb < end; jb += 16) {
        int cnt = min(16, end - jb);
        if (t < cnt) srcb[t] = g_esrc[jb + t];
        __syncthreads();
        if (t < cnt * OUT_HEAD) {
            int j = t / OUT_HEAD, h = t % OUT_HEAD;
            int s = srcb[j];
            float e = leaky(g_A2s[s * OUT_HEAD + h] + g_A2d[n * OUT_HEAD + h]);
            alpha[j][h] = expf(e - sm_m[h]) * sm_inv[h];
        }
        __syncthreads();
        for (int j = 0; j < cnt; j++) {
            const float* row = g_H2 + (size_t)srcb[j] * F2;
#pragma unroll
            for (int h = 0; h < OUT_HEAD; h++)
                acc[h] += alpha[j][h] * row[h * OUT_FEAT + t];
        }
        __syncthreads();
    }
    float o = (acc[0] + acc[1] + acc[2] + acc[3] + acc[4]) * 0.2f + b2[t];
    g_H2o[(size_t)n * OUT_FEAT + t] = o;
}

// ---------------- Final node-mean + tanh ----------------
__global__ void k_part() {
    int b = blockIdx.x, c = threadIdx.x;
    float s = 0.f;
    for (int i = 0; i < N_NODES / 32; i++)
        s += g_H2o[(size_t)(b * (N_NODES / 32) + i) * OUT_FEAT + c];
    g_part[b * OUT_FEAT + c] = s;
}

__global__ void k_final(float* __restrict__ out) {
    int c = threadIdx.x;
    float s = 0.f;
#pragma unroll
    for (int b = 0; b < 32; b++) s += g_part[b * OUT_FEAT + c];
    out[c] = tanhf(s / (float)N_NODES);
}

// ---------------- Launch ----------------
extern "C" void kernel_launch(void* const* d_in, const int* in_sizes, int n_in,
                              void* d_out, int out_size) {
    const float* x        = (const float*)d_in[0];
    const void*  ei       = d_in[1];
    const float* W1       = (const float*)d_in[2];
    const float* att_src1 = (const float*)d_in[3];
    const float* att_dst1 = (const float*)d_in[4];
    const float* b1       = (const float*)d_in[5];
    const float* W2       = (const float*)d_in[6];
    const float* att_src2 = (const float*)d_in[7];
    const float* att_dst2 = (const float*)d_in[8];
    const float* b2       = (const float*)d_in[9];
    float* out = (float*)d_out;

    static float* s_H1   = nullptr;
    static float* s_H2   = nullptr;
    static bf16*  s_xe   = nullptr;
    static bf16*  s_W1e  = nullptr;
    static bf16*  s_H1ae = nullptr;
    static bf16*  s_W2e  = nullptr;
    if (!s_H1)   cudaGetSymbolAddress((void**)&s_H1,   g_H1);
    if (!s_H2)   cudaGetSymbolAddress((void**)&s_H2,   g_H2);
    if (!s_xe)   cudaGetSymbolAddress((void**)&s_xe,   g_xe);
    if (!s_W1e)  cudaGetSymbolAddress((void**)&s_W1e,  g_W1e);
    if (!s_H1ae) cudaGetSymbolAddress((void**)&s_H1ae, g_H1ae);
    if (!s_W2e)  cudaGetSymbolAddress((void**)&s_W2e,  g_W2e);

    k_detect<<<1, 32>>>((const int*)ei);
    k_zero_counts<<<(N_NODES + 256) / 256, 256>>>();
    k_count<<<(E2 + 255) / 256, 256>>>(ei);
    k_scan<<<1, 1024>>>();
    k_scatter<<<(E2 + 255) / 256, 256>>>(ei);

    // split-expand inputs for tensor-core GEMMs
    k_split_x <<<(N_NODES * IN_FEAT) / 256, 256>>>(x);
    k_split_W1<<<(IN_FEAT * F1) / 256, 256>>>(W1);
    k_split_W2<<<(F1 * F2 + 255) / 256, 256>>>(W2);

    // GEMM1: H1 = x @ W1  via split-bf16 [4096,768]x[768,4096]
    hgemm<<<dim3(F1 / BN, N_NODES / BM), 256>>>(s_xe, s_W1e, s_H1, N_NODES, F1, K1E);

    k_dots1<<<(N_NODES * IN_HEAD) / 8, 256>>>(att_src1, att_dst1);
    k_agg1<<<N_NODES, 256>>>(b1);

    // GEMM2: H2 = H1a @ W2  via split-bf16 [4096,12288]x[12288,640]
    hgemm<<<dim3(F2 / BN, N_NODES / BM), 256>>>(s_H1ae, s_W2e, s_H2, N_NODES, F2, K2E);

    k_dots2<<<((N_NODES * OUT_HEAD + 7) / 8), 256>>>(att_src2, att_dst2);
    k_agg2<<<N_NODES, 128>>>(b2);

    k_part<<<32, 128>>>();
    k_final<<<1, 128>>>(out);
}

// round 6
// speedup vs baseline: 1.8549x; 1.0996x over previous
#include <cuda_runtime.h>
#include <cuda_bf16.h>
#include <stdint.h>
#include <math.h>

typedef __nv_bfloat16 bf16;

// ---------------- Problem constants ----------------
#define N_NODES 4096
#define N_EDGES 32768
#define E2      (N_EDGES + N_NODES)   // with self loops = 36864
#define IN_FEAT 256
#define HID     64
#define IN_HEAD 64
#define OUT_FEAT 128
#define OUT_HEAD 5
#define F1      (IN_HEAD * HID)       // 4096
#define F2      (OUT_HEAD * OUT_FEAT) // 640
#define NEG_SLOPE 0.2f
#define GAT_EPS 1e-16f

#define K1E (3 * IN_FEAT)             // 768  (split-expanded K for GEMM1)
#define K2E (3 * F1)                  // 12288 (split-expanded K for GEMM2)

// ---------------- Device scratch ----------------
__device__ int   g_is64;
__device__ int   g_counts[N_NODES + 1];
__device__ int   g_offs[N_NODES + 1];
__device__ int   g_cursor[N_NODES];
__device__ int   g_esrc[E2];
__device__ float g_H1 [(size_t)N_NODES * F1];     // x @ W1  (fp32, 64 MB)
__device__ float g_A1s[(size_t)N_NODES * IN_HEAD];
__device__ float g_A1d[(size_t)N_NODES * IN_HEAD];
__device__ float g_H2 [(size_t)N_NODES * F2];     // H1a @ W2 (fp32, 10 MB)
__device__ float g_P0 [(size_t)N_NODES * F2];     // split-K partial 0
__device__ float g_P1 [(size_t)N_NODES * F2];     // split-K partial 1
__device__ float g_A2s[(size_t)N_NODES * OUT_HEAD];
__device__ float g_A2d[(size_t)N_NODES * OUT_HEAD];
__device__ float g_H2o[(size_t)N_NODES * OUT_FEAT];
__device__ float g_part[32 * OUT_FEAT];

// split-bf16 expanded operands: A'' = [A_hi, A_hi, A_lo], B'' = [B_hi, B_lo, B_hi]
__device__ bf16  g_xe  [(size_t)N_NODES * K1E];   // 6 MB
__device__ bf16  g_W1e [(size_t)K1E * F1];        // 6 MB
__device__ bf16  g_H1ae[(size_t)N_NODES * K2E];   // 100 MB
__device__ bf16  g_W2e [(size_t)K2E * F2];        // 15.7 MB

// ---------------- Edge index helpers (int32 vs int64 detection) ----------------
__global__ void k_detect(const int* ei32) {
    int t = threadIdx.x;
    int v = ei32[2 * t + 1];
    unsigned any = __ballot_sync(0xffffffffu, v != 0);
    if (t == 0) g_is64 = (any == 0) ? 1 : 0;
}

__device__ __forceinline__ int load_ei(const void* ei, int idx) {
    if (g_is64) return (int)((const long long*)ei)[idx];
    return ((const int*)ei)[idx];
}

// ---------------- CSR build ----------------
__global__ void k_zero_counts() {
    int i = blockIdx.x * blockDim.x + threadIdx.x;
    if (i <= N_NODES) g_counts[i] = 0;
}

__global__ void k_count(const void* ei) {
    int i = blockIdx.x * blockDim.x + threadIdx.x;
    if (i >= E2) return;
    int dst = (i < N_EDGES) ? load_ei(ei, N_EDGES + i) : (i - N_EDGES);
    atomicAdd(&g_counts[dst], 1);
}

__global__ void k_scan() {   // 1 block, 1024 threads; scan 4096 counts
    __shared__ int buf[2][1024];
    int t = threadIdx.x;
    int c0 = g_counts[4 * t], c1 = g_counts[4 * t + 1];
    int c2 = g_counts[4 * t + 2], c3 = g_counts[4 * t + 3];
    int s = c0 + c1 + c2 + c3;
    buf[0][t] = s;
    __syncthreads();
    int pin = 0;
    for (int off = 1; off < 1024; off <<= 1) {
        int v = buf[pin][t];
        if (t >= off) v += buf[pin][t - off];
        buf[pin ^ 1][t] = v;
        pin ^= 1;
        __syncthreads();
    }
    int incl = buf[pin][t];
    int base = incl - s;
    g_offs[4 * t]     = base;
    g_offs[4 * t + 1] = base + c0;
    g_offs[4 * t + 2] = base + c0 + c1;
    g_offs[4 * t + 3] = base + c0 + c1 + c2;
    g_cursor[4 * t]     = base;
    g_cursor[4 * t + 1] = base + c0;
    g_cursor[4 * t + 2] = base + c0 + c1;
    g_cursor[4 * t + 3] = base + c0 + c1 + c2;
    if (t == 1023) g_offs[N_NODES] = incl;
}

__global__ void k_scatter(const void* ei) {
    int i = blockIdx.x * blockDim.x + threadIdx.x;
    if (i >= E2) return;
    int src, dst;
    if (i < N_EDGES) { src = load_ei(ei, i); dst = load_ei(ei, N_EDGES + i); }
    else             { src = i - N_EDGES;    dst = i - N_EDGES; }
    int pos = atomicAdd(&g_cursor[dst], 1);
    g_esrc[pos] = src;
}

// ---------------- split-bf16 expansion kernels ----------------
__device__ __forceinline__ void split2(float v, bf16& hi, bf16& lo) {
    hi = __float2bfloat16(v);
    lo = __float2bfloat16(v - __bfloat162float(hi));
}

__global__ void k_split_x(const float* __restrict__ x) {   // [4096,256] -> [4096,768]
    int i = blockIdx.x * blockDim.x + threadIdx.x;
    int m = i >> 8, k = i & 255;
    bf16 hi, lo; split2(x[i], hi, lo);
    bf16* row = g_xe + (size_t)m * K1E;
    row[k] = hi; row[IN_FEAT + k] = hi; row[2 * IN_FEAT + k] = lo;
}

__global__ void k_split_W1(const float* __restrict__ W) {  // [256,4096] -> [768,4096]
    int i = blockIdx.x * blockDim.x + threadIdx.x;
    int k = i >> 12, n = i & 4095;
    bf16 hi, lo; split2(W[i], hi, lo);
    g_W1e[(size_t)k * F1 + n]                    = hi;
    g_W1e[(size_t)(IN_FEAT + k) * F1 + n]        = lo;
    g_W1e[(size_t)(2 * IN_FEAT + k) * F1 + n]    = hi;
}

__global__ void k_split_W2(const float* __restrict__ W) {  // [4096,640] -> [12288,640]
    int i = blockIdx.x * blockDim.x + threadIdx.x;
    if (i >= F1 * F2) return;
    int k = i / F2, n = i % F2;
    bf16 hi, lo; split2(W[i], hi, lo);
    g_W2e[(size_t)k * F2 + n]              = hi;
    g_W2e[(size_t)(F1 + k) * F2 + n]       = lo;
    g_W2e[(size_t)(2 * F1 + k) * F2 + n]   = hi;
}

// ---------------- bf16 tensor-core GEMM (mma.sync, 3-stage cp.async) ----------------
// C[M,N] = A[M, kOff:kOff+kLen] * B[kOff:kOff+kLen, N].  A/B bf16 row-major, C fp32.
// BM=128, BN=128, BK=32, 3 stages, 256 threads (8 warps 2x4, warp tile 64x32).
#define BM 128
#define BN 128
#define BK 32
#define STG 3
#define APITCH (BK + 8)
#define BPITCH (BN + 8)
#define HG_SMEM (STG * (BM * APITCH + BK * BPITCH) * 2)

__global__ __launch_bounds__(256, 2)
void hgemm(const bf16* __restrict__ A, const bf16* __restrict__ B,
           float* __restrict__ C, int N, int K, int kOff, int kLen) {
    extern __shared__ bf16 smbuf[];
    bf16* sA = smbuf;                          // [STG][BM][APITCH]
    bf16* sB = smbuf + STG * BM * APITCH;      // [STG][BK][BPITCH]
    int t = threadIdx.x, lane = t & 31, warp = t >> 5;
    int wm = (warp >> 2) * 64;   // 0 or 64
    int wn = (warp & 3) * 32;    // 0,32,64,96
    int bx = blockIdx.x, by = blockIdx.y;
    const bf16* Ab = A + (size_t)(by * BM) * K + kOff;
    const bf16* Bb = B + (size_t)kOff * N + bx * BN;

    int a_row = t >> 2;          // 0..63 (+64)
    int a_col = (t & 3) * 8;
    int b_row = t >> 4;          // 0..15 (+16)
    int b_col = (t & 15) * 8;

    float acc[4][4][4];
#pragma unroll
    for (int i = 0; i < 4; i++)
#pragma unroll
        for (int j = 0; j < 4; j++)
#pragma unroll
            for (int r = 0; r < 4; r++) acc[i][j][r] = 0.f;

    auto issue = [&](int j) {
        int buf = j % STG;
        int k0 = j * BK;
        bf16* pa = sA + buf * BM * APITCH;
        bf16* pb = sB + buf * BK * BPITCH;
        uint32_t da0 = (uint32_t)__cvta_generic_to_shared(pa + a_row * APITCH + a_col);
        uint32_t da1 = (uint32_t)__cvta_generic_to_shared(pa + (a_row + 64) * APITCH + a_col);
        const bf16* ga0 = Ab + (size_t)a_row * K + k0 + a_col;
        const bf16* ga1 = Ab + (size_t)(a_row + 64) * K + k0 + a_col;
        asm volatile("cp.async.cg.shared.global [%0], [%1], 16;" :: "r"(da0), "l"(ga0));
        asm volatile("cp.async.cg.shared.global [%0], [%1], 16;" :: "r"(da1), "l"(ga1));
        uint32_t db0 = (uint32_t)__cvta_generic_to_shared(pb + b_row * BPITCH + b_col);
        uint32_t db1 = (uint32_t)__cvta_generic_to_shared(pb + (b_row + 16) * BPITCH + b_col);
        const bf16* gb0 = Bb + (size_t)(k0 + b_row) * N + b_col;
        const bf16* gb1 = Bb + (size_t)(k0 + b_row + 16) * N + b_col;
        asm volatile("cp.async.cg.shared.global [%0], [%1], 16;" :: "r"(db0), "l"(gb0));
        asm volatile("cp.async.cg.shared.global [%0], [%1], 16;" :: "r"(db1), "l"(gb1));
        asm volatile("cp.async.commit_group;");
    };

    int nc = kLen / BK;
    issue(0);
    if (nc > 1) issue(1);
    for (int s = 0; s < nc; s++) {
        if (s < nc - 1) { asm volatile("cp.async.wait_group 1;"); }
        else            { asm volatile("cp.async.wait_group 0;"); }
        __syncthreads();
        if (s + 2 < nc) issue(s + 2);
        int buf = s % STG;
        bf16* pa = sA + buf * BM * APITCH;
        bf16* pb = sB + buf * BK * BPITCH;
#pragma unroll
        for (int kk = 0; kk < 2; kk++) {
            int k = kk * 16;
            uint32_t ar[4][4], br[2][4];
#pragma unroll
            for (int mi = 0; mi < 4; mi++) {
                int row = wm + mi * 16 + (lane & 7) + ((lane >> 3) & 1) * 8;
                int col = k + (lane >> 4) * 8;
                uint32_t addr = (uint32_t)__cvta_generic_to_shared(pa + row * APITCH + col);
                asm volatile("ldmatrix.sync.aligned.m8n8.x4.shared.b16 {%0,%1,%2,%3}, [%4];"
                             : "=r"(ar[mi][0]), "=r"(ar[mi][1]), "=r"(ar[mi][2]), "=r"(ar[mi][3])
                             : "r"(addr));
            }
#pragma unroll
            for (int n2 = 0; n2 < 2; n2++) {
                int rrow = k + (lane & 7) + ((lane >> 3) & 1) * 8;
                int rcol = wn + n2 * 16 + (lane >> 4) * 8;
                uint32_t addr = (uint32_t)__cvta_generic_to_shared(pb + rrow * BPITCH + rcol);
                asm volatile("ldmatrix.sync.aligned.m8n8.x4.trans.shared.b16 {%0,%1,%2,%3}, [%4];"
                             : "=r"(br[n2][0]), "=r"(br[n2][1]), "=r"(br[n2][2]), "=r"(br[n2][3])
                             : "r"(addr));
            }
#pragma unroll
            for (int mi = 0; mi < 4; mi++)
#pragma unroll
                for (int ni = 0; ni < 4; ni++) {
                    uint32_t b0 = br[ni >> 1][(ni & 1) * 2];
                    uint32_t b1 = br[ni >> 1][(ni & 1) * 2 + 1];
                    asm volatile(
                        "mma.sync.aligned.m16n8k16.row.col.f32.bf16.bf16.f32 "
                        "{%0,%1,%2,%3}, {%4,%5,%6,%7}, {%8,%9}, {%0,%1,%2,%3};"
                        : "+f"(acc[mi][ni][0]), "+f"(acc[mi][ni][1]),
                          "+f"(acc[mi][ni][2]), "+f"(acc[mi][ni][3])
                        : "r"(ar[mi][0]), "r"(ar[mi][1]), "r"(ar[mi][2]), "r"(ar[mi][3]),
                          "r"(b0), "r"(b1));
                }
        }
        __syncthreads();
    }
    float* Cb = C + (size_t)(by * BM + wm) * N + bx * BN + wn;
#pragma unroll
    for (int mi = 0; mi < 4; mi++)
#pragma unroll
        for (int ni = 0; ni < 4; ni++) {
            int r0 = mi * 16 + (lane >> 2);
            int c0 = ni * 8 + (lane & 3) * 2;
            *(float2*)(Cb + (size_t)r0 * N + c0)       = make_float2(acc[mi][ni][0], acc[mi][ni][1]);
            *(float2*)(Cb + (size_t)(r0 + 8) * N + c0) = make_float2(acc[mi][ni][2], acc[mi][ni][3]);
        }
}

// split-K reduction: H2 = P0 + P1 (float4 vectorized)
__global__ void k_red() {
    int i = blockIdx.x * blockDim.x + threadIdx.x;    // over float4s
    if (i >= (N_NODES * F2) / 4) return;
    float4 a = ((const float4*)g_P0)[i];
    float4 b = ((const float4*)g_P1)[i];
    ((float4*)g_H2)[i] = make_float4(a.x + b.x, a.y + b.y, a.z + b.z, a.w + b.w);
}

// ---------------- Attention dot products ----------------
__global__ void k_dots1(const float* __restrict__ att_src, const float* __restrict__ att_dst) {
    int warp = (blockIdx.x * blockDim.x + threadIdx.x) >> 5;
    int lane = threadIdx.x & 31;
    int n = warp >> 6, h = warp & 63;
    const float* row = g_H1 + (size_t)n * F1 + h * HID;
    float v1 = row[lane], v2 = row[lane + 32];
    float sa = v1 * att_src[h * HID + lane] + v2 * att_src[h * HID + lane + 32];
    float sd = v1 * att_dst[h * HID + lane] + v2 * att_dst[h * HID + lane + 32];
#pragma unroll
    for (int o = 16; o > 0; o >>= 1) {
        sa += __shfl_xor_sync(0xffffffffu, sa, o);
        sd += __shfl_xor_sync(0xffffffffu, sd, o);
    }
    if (lane == 0) {
        g_A1s[n * IN_HEAD + h] = sa;
        g_A1d[n * IN_HEAD + h] = sd;
    }
}

__global__ void k_dots2(const float* __restrict__ att_src, const float* __restrict__ att_dst) {
    int warp = (blockIdx.x * blockDim.x + threadIdx.x) >> 5;
    int lane = threadIdx.x & 31;
    if (warp >= N_NODES * OUT_HEAD) return;
    int n = warp / OUT_HEAD, h = warp % OUT_HEAD;
    const float* row = g_H2 + (size_t)n * F2 + h * OUT_FEAT;
    float sa = 0.f, sd = 0.f;
#pragma unroll
    for (int k = 0; k < 4; k++) {
        int c = lane + 32 * k;
        float v = row[c];
        sa += v * att_src[h * OUT_FEAT + c];
        sd += v * att_dst[h * OUT_FEAT + c];
    }
#pragma unroll
    for (int o = 16; o > 0; o >>= 1) {
        sa += __shfl_xor_sync(0xffffffffu, sa, o);
        sd += __shfl_xor_sync(0xffffffffu, sd, o);
    }
    if (lane == 0) {
        g_A2s[n * OUT_HEAD + h] = sa;
        g_A2d[n * OUT_HEAD + h] = sd;
    }
}

__device__ __forceinline__ float leaky(float x) { return x > 0.f ? x : NEG_SLOPE * x; }

// ---------------- Layer-1 softmax + aggregation + bias + elu -> split-bf16 ----------------
__global__ void k_agg1(const float* __restrict__ b1) {
    int n = blockIdx.x;
    int t = threadIdx.x;
    int h = t & 63, slot = t >> 6;
    int beg = g_offs[n], end = g_offs[n + 1];
    float adst = g_A1d[n * IN_HEAD + h];

    __shared__ float red[4][64];
    __shared__ float sm_m[64], sm_inv[64];
    __shared__ int   srcb[32];
    __shared__ float alpha[32][64];

    float mx = -1e30f;
    for (int j = beg + slot; j < end; j += 4) {
        int s = g_esrc[j];
        mx = fmaxf(mx, leaky(g_A1s[s * IN_HEAD + h] + adst));
    }
    red[slot][h] = mx;
    __syncthreads();
    if (slot == 0) {
        sm_m[h] = fmaxf(fmaxf(red[0][h], red[1][h]), fmaxf(red[2][h], red[3][h]));
    }
    __syncthreads();
    float M = sm_m[h];

    float sum = 0.f;
    for (int j = beg + slot; j < end; j += 4) {
        int s = g_esrc[j];
        sum += expf(leaky(g_A1s[s * IN_HEAD + h] + adst) - M);
    }
    red[slot][h] = sum;
    __syncthreads();
    if (slot == 0) {
        float d = red[0][h] + red[1][h] + red[2][h] + red[3][h];
        sm_inv[h] = 1.0f / (d + GAT_EPS);
    }
    __syncthreads();
    float INV = sm_inv[h];

    int c = t & 63, g = t >> 6;
    float acc[16];
#pragma unroll
    for (int k = 0; k < 16; k++) acc[k] = 0.f;

    for (int jb = beg; jb < end; jb += 32) {
        int cnt = min(32, end - jb);
        if (t < cnt) srcb[t] = g_esrc[jb + t];
        __syncthreads();
        for (int j = slot; j < cnt; j += 4) {
            int s = srcb[j];
            float e = leaky(g_A1s[s * IN_HEAD + h] + adst);
            alpha[j][h] = expf(e - M) * INV;
        }
        __syncthreads();
        for (int j = 0; j < cnt; j++) {
            const float* row = g_H1 + (size_t)srcb[j] * F1;
            float a0 = alpha[j][g * 16];   // dummy read pattern avoided; per-k below
#pragma unroll
            for (int k = 0; k < 16; k++) {
                int hh = g * 16 + k;
                acc[k] += alpha[j][hh] * row[hh * HID + c];
            }
            (void)a0;
        }
        __syncthreads();
    }
    bf16* rowo = g_H1ae + (size_t)n * K2E;
#pragma unroll
    for (int k = 0; k < 16; k++) {
        int idx = (g * 16 + k) * HID + c;
        float v = acc[k] + b1[idx];
        v = v > 0.f ? v : expm1f(v);   // elu
        bf16 hi, lo; split2(v, hi, lo);
        rowo[idx] = hi; rowo[F1 + idx] = hi; rowo[2 * F1 + idx] = lo;
    }
}

// ---------------- Layer-2 softmax + aggregation + head-mean + bias ----------------
__global__ void k_agg2(const float* __restrict__ b2) {
    int n = blockIdx.x;
    int t = threadIdx.x;
    int beg = g_offs[n], end = g_offs[n + 1];

    __shared__ float sm_m[OUT_HEAD], sm_inv[OUT_HEAD];
    __shared__ int   srcb[16];
    __shared__ float alpha[16][OUT_HEAD];

    if (t < OUT_HEAD) {
        float adst = g_A2d[n * OUT_HEAD + t];
        float mx = -1e30f;
        for (int j = beg; j < end; j++)
            mx = fmaxf(mx, leaky(g_A2s[g_esrc[j] * OUT_HEAD + t] + adst));
        float sum = 0.f;
        for (int j = beg; j < end; j++)
            sum += expf(leaky(g_A2s[g_esrc[j] * OUT_HEAD + t] + adst) - mx);
        sm_m[t] = mx;
        sm_inv[t] = 1.0f / (sum + GAT_EPS);
    }
    __syncthreads();

    float acc[OUT_HEAD] = {0.f, 0.f, 0.f, 0.f, 0.f};
    for (int jb = beg; jb < end; jb += 16) {
        int cnt = min(16, end - jb);
        if (t < cnt) srcb[t] = g_esrc[jb + t];
        __syncthreads();
        if (t < cnt * OUT_HEAD) {
            int j = t / OUT_HEAD, hh = t % OUT_HEAD;
            int s = srcb[j];
            float e = leaky(g_A2s[s * OUT_HEAD + hh] + g_A2d[n * OUT_HEAD + hh]);
            alpha[j][hh] = expf(e - sm_m[hh]) * sm_inv[hh];
        }
        __syncthreads();
        for (int j = 0; j < cnt; j++) {
            const float* row = g_H2 + (size_t)srcb[j] * F2;
#pragma unroll
            for (int hh = 0; hh < OUT_HEAD; hh++)
                acc[hh] += alpha[j][hh] * row[hh * OUT_FEAT + t];
        }
        __syncthreads();
    }
    float o = (acc[0] + acc[1] + acc[2] + acc[3] + acc[4]) * 0.2f + b2[t];
    g_H2o[(size_t)n * OUT_FEAT + t] = o;
}

// ---------------- Final node-mean + tanh ----------------
__global__ void k_part() {
    int b = blockIdx.x, c = threadIdx.x;
    float s = 0.f;
    for (int i = 0; i < N_NODES / 32; i++)
        s += g_H2o[(size_t)(b * (N_NODES / 32) + i) * OUT_FEAT + c];
    g_part[b * OUT_FEAT + c] = s;
}

__global__ void k_final(float* __restrict__ out) {
    int c = threadIdx.x;
    float s = 0.f;
#pragma unroll
    for (int b = 0; b < 32; b++) s += g_part[b * OUT_FEAT + c];
    out[c] = tanhf(s / (float)N_NODES);
}

// ---------------- Launch ----------------
extern "C" void kernel_launch(void* const* d_in, const int* in_sizes, int n_in,
                              void* d_out, int out_size) {
    const float* x        = (const float*)d_in[0];
    const void*  ei       = d_in[1];
    const float* W1       = (const float*)d_in[2];
    const float* att_src1 = (const float*)d_in[3];
    const float* att_dst1 = (const float*)d_in[4];
    const float* b1       = (const float*)d_in[5];
    const float* W2       = (const float*)d_in[6];
    const float* att_src2 = (const float*)d_in[7];
    const float* att_dst2 = (const float*)d_in[8];
    const float* b2       = (const float*)d_in[9];
    float* out = (float*)d_out;

    static float* s_H1   = nullptr;
    static float* s_P0   = nullptr;
    static float* s_P1   = nullptr;
    static bf16*  s_xe   = nullptr;
    static bf16*  s_W1e  = nullptr;
    static bf16*  s_H1ae = nullptr;
    static bf16*  s_W2e  = nullptr;
    static bool   s_init = false;
    if (!s_init) {
        cudaGetSymbolAddress((void**)&s_H1,   g_H1);
        cudaGetSymbolAddress((void**)&s_P0,   g_P0);
        cudaGetSymbolAddress((void**)&s_P1,   g_P1);
        cudaGetSymbolAddress((void**)&s_xe,   g_xe);
        cudaGetSymbolAddress((void**)&s_W1e,  g_W1e);
        cudaGetSymbolAddress((void**)&s_H1ae, g_H1ae);
        cudaGetSymbolAddress((void**)&s_W2e,  g_W2e);
        cudaFuncSetAttribute(hgemm, cudaFuncAttributeMaxDynamicSharedMemorySize, HG_SMEM);
        s_init = true;
    }

    k_detect<<<1, 32>>>((const int*)ei);
    k_zero_counts<<<(N_NODES + 256) / 256, 256>>>();
    k_count<<<(E2 + 255) / 256, 256>>>(ei);
    k_scan<<<1, 1024>>>();
    k_scatter<<<(E2 + 255) / 256, 256>>>(ei);

    // split-expand inputs for tensor-core GEMMs
    k_split_x <<<(N_NODES * IN_FEAT) / 256, 256>>>(x);
    k_split_W1<<<(IN_FEAT * F1) / 256, 256>>>(W1);
    k_split_W2<<<(F1 * F2 + 255) / 256, 256>>>(W2);

    // GEMM1: H1 = x @ W1  via split-bf16 [4096,768]x[768,4096]
    hgemm<<<dim3(F1 / BN, N_NODES / BM), 256, HG_SMEM>>>(s_xe, s_W1e, s_H1, F1, K1E, 0, K1E);

    k_dots1<<<(N_NODES * IN_HEAD) / 8, 256>>>(att_src1, att_dst1);
    k_agg1<<<N_NODES, 256>>>(b1);

    // GEMM2: H2 = H1a @ W2  via split-bf16 [4096,12288]x[12288,640], split-K = 2
    hgemm<<<dim3(F2 / BN, N_NODES / BM), 256, HG_SMEM>>>(s_H1ae, s_W2e, s_P0, F2, K2E, 0,       K2E / 2);
    hgemm<<<dim3(F2 / BN, N_NODES / BM), 256, HG_SMEM>>>(s_H1ae, s_W2e, s_P1, F2, K2E, K2E / 2, K2E / 2);
    k_red<<<((N_NODES * F2 / 4) + 255) / 256, 256>>>();

    k_dots2<<<((N_NODES * OUT_HEAD + 7) / 8), 256>>>(att_src2, att_dst2);
    k_agg2<<<N_NODES, 128>>>(b2);

    k_part<<<32, 128>>>();
    k_final<<<1, 128>>>(out);
}

// round 7
// speedup vs baseline: 2.4717x; 1.3325x over previous
#include <cuda_runtime.h>
#include <cuda_bf16.h>
#include <stdint.h>
#include <math.h>

typedef __nv_bfloat16 bf16;

// ---------------- Problem constants ----------------
#define N_NODES 4096
#define N_EDGES 32768
#define E2      (N_EDGES + N_NODES)   // with self loops = 36864
#define IN_FEAT 256
#define HID     64
#define IN_HEAD 64
#define OUT_FEAT 128
#define OUT_HEAD 5
#define F1      (IN_HEAD * HID)       // 4096
#define F2      (OUT_HEAD * OUT_FEAT) // 640
#define NEG_SLOPE 0.2f
#define GAT_EPS 1e-16f

#define K1E (3 * IN_FEAT)             // 768  (3-term split K for GEMM1)
#define K2E (2 * F1)                  // 8192 (2-term split K for GEMM2)

// ---------------- Device scratch ----------------
__device__ int   g_is64;
__device__ int   g_counts[N_NODES + 1];
__device__ int   g_offs[N_NODES + 1];
__device__ int   g_cursor[N_NODES];
__device__ int   g_esrc[E2];
__device__ float g_H1 [(size_t)N_NODES * F1];     // x @ W1  (fp32, 64 MB)
__device__ float g_A1s[(size_t)N_NODES * IN_HEAD];
__device__ float g_A1d[(size_t)N_NODES * IN_HEAD];
__device__ float g_H2 [(size_t)N_NODES * F2];     // H1a @ W2 (fp32, 10 MB)
__device__ float g_P0 [(size_t)N_NODES * F2];     // split-K partial 0
__device__ float g_P1 [(size_t)N_NODES * F2];     // split-K partial 1
__device__ float g_A2s[(size_t)N_NODES * OUT_HEAD];
__device__ float g_A2d[(size_t)N_NODES * OUT_HEAD];
__device__ float g_H2o[(size_t)N_NODES * OUT_FEAT];
__device__ float g_part[32 * OUT_FEAT];

// split-bf16 expanded operands.
// GEMM1 (3-term): A''=[A_hi, A_hi, A_lo], B''=[B_hi, B_lo, B_hi]
// GEMM2 (2-term): A''=[A_hi, A_hi],       B''=[B_hi, B_lo]   (= A_hi @ B exactly)
__device__ bf16  g_xe  [(size_t)N_NODES * K1E];   // 6 MB
__device__ bf16  g_W1e [(size_t)K1E * F1];        // 6 MB
__device__ bf16  g_H1ae[(size_t)N_NODES * K2E];   // 67 MB
__device__ bf16  g_W2e [(size_t)K2E * F2];        // 10.5 MB

// ---------------- init: zero counts + int64/int32 detect ----------------
__global__ void k_init(const int* ei32) {
    int i = blockIdx.x * blockDim.x + threadIdx.x;
    if (i <= N_NODES) g_counts[i] = 0;
    if (blockIdx.x == 0 && threadIdx.x < 32) {
        int v = ei32[2 * threadIdx.x + 1];
        unsigned any = __ballot_sync(0xffffffffu, v != 0);
        if (threadIdx.x == 0) g_is64 = (any == 0) ? 1 : 0;
    }
}

__device__ __forceinline__ int load_ei(const void* ei, int idx) {
    if (g_is64) return (int)((const long long*)ei)[idx];
    return ((const int*)ei)[idx];
}

// ---------------- CSR build ----------------
__global__ void k_count(const void* ei) {
    int i = blockIdx.x * blockDim.x + threadIdx.x;
    if (i >= E2) return;
    int dst = (i < N_EDGES) ? load_ei(ei, N_EDGES + i) : (i - N_EDGES);
    atomicAdd(&g_counts[dst], 1);
}

__global__ void k_scan() {   // 1 block, 1024 threads; scan 4096 counts
    __shared__ int buf[2][1024];
    int t = threadIdx.x;
    int c0 = g_counts[4 * t], c1 = g_counts[4 * t + 1];
    int c2 = g_counts[4 * t + 2], c3 = g_counts[4 * t + 3];
    int s = c0 + c1 + c2 + c3;
    buf[0][t] = s;
    __syncthreads();
    int pin = 0;
    for (int off = 1; off < 1024; off <<= 1) {
        int v = buf[pin][t];
        if (t >= off) v += buf[pin][t - off];
        buf[pin ^ 1][t] = v;
        pin ^= 1;
        __syncthreads();
    }
    int incl = buf[pin][t];
    int base = incl - s;
    g_offs[4 * t]     = base;
    g_offs[4 * t + 1] = base + c0;
    g_offs[4 * t + 2] = base + c0 + c1;
    g_offs[4 * t + 3] = base + c0 + c1 + c2;
    g_cursor[4 * t]     = base;
    g_cursor[4 * t + 1] = base + c0;
    g_cursor[4 * t + 2] = base + c0 + c1;
    g_cursor[4 * t + 3] = base + c0 + c1 + c2;
    if (t == 1023) g_offs[N_NODES] = incl;
}

__global__ void k_scatter(const void* ei) {
    int i = blockIdx.x * blockDim.x + threadIdx.x;
    if (i >= E2) return;
    int src, dst;
    if (i < N_EDGES) { src = load_ei(ei, i); dst = load_ei(ei, N_EDGES + i); }
    else             { src = i - N_EDGES;    dst = i - N_EDGES; }
    int pos = atomicAdd(&g_cursor[dst], 1);
    g_esrc[pos] = src;
}

// ---------------- split-bf16 expansion kernels ----------------
__device__ __forceinline__ void split2(float v, bf16& hi, bf16& lo) {
    hi = __float2bfloat16(v);
    lo = __float2bfloat16(v - __bfloat162float(hi));
}

__global__ void k_split_x(const float* __restrict__ x) {   // [4096,256] -> [4096,768]
    int i = blockIdx.x * blockDim.x + threadIdx.x;
    int m = i >> 8, k = i & 255;
    bf16 hi, lo; split2(x[i], hi, lo);
    bf16* row = g_xe + (size_t)m * K1E;
    row[k] = hi; row[IN_FEAT + k] = hi; row[2 * IN_FEAT + k] = lo;
}

__global__ void k_split_W1(const float* __restrict__ W) {  // [256,4096] -> [768,4096]
    int i = blockIdx.x * blockDim.x + threadIdx.x;
    int k = i >> 12, n = i & 4095;
    bf16 hi, lo; split2(W[i], hi, lo);
    g_W1e[(size_t)k * F1 + n]                    = hi;
    g_W1e[(size_t)(IN_FEAT + k) * F1 + n]        = lo;
    g_W1e[(size_t)(2 * IN_FEAT + k) * F1 + n]    = hi;
}

__global__ void k_split_W2(const float* __restrict__ W) {  // [4096,640] -> [8192,640]
    int i = blockIdx.x * blockDim.x + threadIdx.x;
    if (i >= F1 * F2) return;
    int k = i / F2, n = i % F2;
    bf16 hi, lo; split2(W[i], hi, lo);
    g_W2e[(size_t)k * F2 + n]        = hi;
    g_W2e[(size_t)(F1 + k) * F2 + n] = lo;
}

// ---------------- bf16 tensor-core GEMM (mma.sync, 3-stage cp.async) ----------------
// C[M,N] = A[M, kOff:kOff+kLen] * B[kOff:kOff+kLen, N].  A/B bf16 row-major, C fp32.
// blockIdx.z selects split-K segment: kOff = z * kLen, C = (z ? C1 : C0).
// BM=128, BN=128, BK=32, 3 stages, 256 threads (8 warps 2x4, warp tile 64x32).
#define BM 128
#define BN 128
#define BK 32
#define STG 3
#define APITCH (BK + 8)
#define BPITCH (BN + 8)
#define HG_SMEM (STG * (BM * APITCH + BK * BPITCH) * 2)

__global__ __launch_bounds__(256, 2)
void hgemm(const bf16* __restrict__ A, const bf16* __restrict__ B,
           float* __restrict__ C0, float* __restrict__ C1,
           int N, int K, int kLen) {
    extern __shared__ bf16 smbuf[];
    bf16* sA = smbuf;                          // [STG][BM][APITCH]
    bf16* sB = smbuf + STG * BM * APITCH;      // [STG][BK][BPITCH]
    int t = threadIdx.x, lane = t & 31, warp = t >> 5;
    int wm = (warp >> 2) * 64;   // 0 or 64
    int wn = (warp & 3) * 32;    // 0,32,64,96
    int bx = blockIdx.x, by = blockIdx.y, bz = blockIdx.z;
    int kOff = bz * kLen;
    float* C = bz ? C1 : C0;
    const bf16* Ab = A + (size_t)(by * BM) * K + kOff;
    const bf16* Bb = B + (size_t)kOff * N + bx * BN;

    int a_row = t >> 2;          // 0..63 (+64)
    int a_col = (t & 3) * 8;
    int b_row = t >> 4;          // 0..15 (+16)
    int b_col = (t & 15) * 8;

    float acc[4][4][4];
#pragma unroll
    for (int i = 0; i < 4; i++)
#pragma unroll
        for (int j = 0; j < 4; j++)
#pragma unroll
            for (int r = 0; r < 4; r++) acc[i][j][r] = 0.f;

    auto issue = [&](int j) {
        int buf = j % STG;
        int k0 = j * BK;
        bf16* pa = sA + buf * BM * APITCH;
        bf16* pb = sB + buf * BK * BPITCH;
        uint32_t da0 = (uint32_t)__cvta_generic_to_shared(pa + a_row * APITCH + a_col);
        uint32_t da1 = (uint32_t)__cvta_generic_to_shared(pa + (a_row + 64) * APITCH + a_col);
        const bf16* ga0 = Ab + (size_t)a_row * K + k0 + a_col;
        const bf16* ga1 = Ab + (size_t)(a_row + 64) * K + k0 + a_col;
        asm volatile("cp.async.cg.shared.global [%0], [%1], 16;" :: "r"(da0), "l"(ga0));
        asm volatile("cp.async.cg.shared.global [%0], [%1], 16;" :: "r"(da1), "l"(ga1));
        uint32_t db0 = (uint32_t)__cvta_generic_to_shared(pb + b_row * BPITCH + b_col);
        uint32_t db1 = (uint32_t)__cvta_generic_to_shared(pb + (b_row + 16) * BPITCH + b_col);
        const bf16* gb0 = Bb + (size_t)(k0 + b_row) * N + b_col;
        const bf16* gb1 = Bb + (size_t)(k0 + b_row + 16) * N + b_col;
        asm volatile("cp.async.cg.shared.global [%0], [%1], 16;" :: "r"(db0), "l"(gb0));
        asm volatile("cp.async.cg.shared.global [%0], [%1], 16;" :: "r"(db1), "l"(gb1));
        asm volatile("cp.async.commit_group;");
    };

    int nc = kLen / BK;
    issue(0);
    if (nc > 1) issue(1);
    for (int s = 0; s < nc; s++) {
        if (s < nc - 1) { asm volatile("cp.async.wait_group 1;"); }
        else            { asm volatile("cp.async.wait_group 0;"); }
        __syncthreads();
        if (s + 2 < nc) issue(s + 2);
        int buf = s % STG;
        bf16* pa = sA + buf * BM * APITCH;
        bf16* pb = sB + buf * BK * BPITCH;
#pragma unroll
        for (int kk = 0; kk < 2; kk++) {
            int k = kk * 16;
            uint32_t ar[4][4], br[2][4];
#pragma unroll
            for (int mi = 0; mi < 4; mi++) {
                int row = wm + mi * 16 + (lane & 7) + ((lane >> 3) & 1) * 8;
                int col = k + (lane >> 4) * 8;
                uint32_t addr = (uint32_t)__cvta_generic_to_shared(pa + row * APITCH + col);
                asm volatile("ldmatrix.sync.aligned.m8n8.x4.shared.b16 {%0,%1,%2,%3}, [%4];"
                             : "=r"(ar[mi][0]), "=r"(ar[mi][1]), "=r"(ar[mi][2]), "=r"(ar[mi][3])
                             : "r"(addr));
            }
#pragma unroll
            for (int n2 = 0; n2 < 2; n2++) {
                int rrow = k + (lane & 7) + ((lane >> 3) & 1) * 8;
                int rcol = wn + n2 * 16 + (lane >> 4) * 8;
                uint32_t addr = (uint32_t)__cvta_generic_to_shared(pb + rrow * BPITCH + rcol);
                asm volatile("ldmatrix.sync.aligned.m8n8.x4.trans.shared.b16 {%0,%1,%2,%3}, [%4];"
                             : "=r"(br[n2][0]), "=r"(br[n2][1]), "=r"(br[n2][2]), "=r"(br[n2][3])
                             : "r"(addr));
            }
#pragma unroll
            for (int mi = 0; mi < 4; mi++)
#pragma unroll
                for (int ni = 0; ni < 4; ni++) {
                    uint32_t b0 = br[ni >> 1][(ni & 1) * 2];
                    uint32_t b1 = br[ni >> 1][(ni & 1) * 2 + 1];
                    asm volatile(
                        "mma.sync.aligned.m16n8k16.row.col.f32.bf16.bf16.f32 "
                        "{%0,%1,%2,%3}, {%4,%5,%6,%7}, {%8,%9}, {%0,%1,%2,%3};"
                        : "+f"(acc[mi][ni][0]), "+f"(acc[mi][ni][1]),
                          "+f"(acc[mi][ni][2]), "+f"(acc[mi][ni][3])
                        : "r"(ar[mi][0]), "r"(ar[mi][1]), "r"(ar[mi][2]), "r"(ar[mi][3]),
                          "r"(b0), "r"(b1));
                }
        }
        __syncthreads();
    }
    float* Cb = C + (size_t)(by * BM + wm) * N + bx * BN + wn;
#pragma unroll
    for (int mi = 0; mi < 4; mi++)
#pragma unroll
        for (int ni = 0; ni < 4; ni++) {
            int r0 = mi * 16 + (lane >> 2);
            int c0 = ni * 8 + (lane & 3) * 2;
            *(float2*)(Cb + (size_t)r0 * N + c0)       = make_float2(acc[mi][ni][0], acc[mi][ni][1]);
            *(float2*)(Cb + (size_t)(r0 + 8) * N + c0) = make_float2(acc[mi][ni][2], acc[mi][ni][3]);
        }
}

// split-K reduction: H2 = P0 + P1 (float4 vectorized)
__global__ void k_red() {
    int i = blockIdx.x * blockDim.x + threadIdx.x;    // over float4s
    if (i >= (N_NODES * F2) / 4) return;
    float4 a = ((const float4*)g_P0)[i];
    float4 b = ((const float4*)g_P1)[i];
    ((float4*)g_H2)[i] = make_float4(a.x + b.x, a.y + b.y, a.z + b.z, a.w + b.w);
}

// ---------------- Attention dot products ----------------
__global__ void k_dots1(const float* __restrict__ att_src, const float* __restrict__ att_dst) {
    int warp = (blockIdx.x * blockDim.x + threadIdx.x) >> 5;
    int lane = threadIdx.x & 31;
    int n = warp >> 6, h = warp & 63;
    const float* row = g_H1 + (size_t)n * F1 + h * HID;
    float v1 = row[lane], v2 = row[lane + 32];
    float sa = v1 * att_src[h * HID + lane] + v2 * att_src[h * HID + lane + 32];
    float sd = v1 * att_dst[h * HID + lane] + v2 * att_dst[h * HID + lane + 32];
#pragma unroll
    for (int o = 16; o > 0; o >>= 1) {
        sa += __shfl_xor_sync(0xffffffffu, sa, o);
        sd += __shfl_xor_sync(0xffffffffu, sd, o);
    }
    if (lane == 0) {
        g_A1s[n * IN_HEAD + h] = sa;
        g_A1d[n * IN_HEAD + h] = sd;
    }
}

__global__ void k_dots2(const float* __restrict__ att_src, const float* __restrict__ att_dst) {
    int warp = (blockIdx.x * blockDim.x + threadIdx.x) >> 5;
    int lane = threadIdx.x & 31;
    if (warp >= N_NODES * OUT_HEAD) return;
    int n = warp / OUT_HEAD, h = warp % OUT_HEAD;
    const float* row = g_H2 + (size_t)n * F2 + h * OUT_FEAT;
    float sa = 0.f, sd = 0.f;
#pragma unroll
    for (int k = 0; k < 4; k++) {
        int c = lane + 32 * k;
        float v = row[c];
        sa += v * att_src[h * OUT_FEAT + c];
        sd += v * att_dst[h * OUT_FEAT + c];
    }
#pragma unroll
    for (int o = 16; o > 0; o >>= 1) {
        sa += __shfl_xor_sync(0xffffffffu, sa, o);
        sd += __shfl_xor_sync(0xffffffffu, sd, o);
    }
    if (lane == 0) {
        g_A2s[n * OUT_HEAD + h] = sa;
        g_A2d[n * OUT_HEAD + h] = sd;
    }
}

__device__ __forceinline__ float leaky(float x) { return x > 0.f ? x : NEG_SLOPE * x; }

// ---------------- Layer-1 softmax + aggregation + bias + elu -> 2-term bf16 ----------------
__global__ void k_agg1(const float* __restrict__ b1) {
    int n = blockIdx.x;
    int t = threadIdx.x;
    int h = t & 63, slot = t >> 6;
    int beg = g_offs[n], end = g_offs[n + 1];
    float adst = g_A1d[n * IN_HEAD + h];

    __shared__ float red[4][64];
    __shared__ float sm_m[64], sm_inv[64];
    __shared__ int   srcb[32];
    __shared__ float alpha[32][64];

    float mx = -1e30f;
    for (int j = beg + slot; j < end; j += 4) {
        int s = g_esrc[j];
        mx = fmaxf(mx, leaky(g_A1s[s * IN_HEAD + h] + adst));
    }
    red[slot][h] = mx;
    __syncthreads();
    if (slot == 0) {
        sm_m[h] = fmaxf(fmaxf(red[0][h], red[1][h]), fmaxf(red[2][h], red[3][h]));
    }
    __syncthreads();
    float M = sm_m[h];

    float sum = 0.f;
    for (int j = beg + slot; j < end; j += 4) {
        int s = g_esrc[j];
        sum += expf(leaky(g_A1s[s * IN_HEAD + h] + adst) - M);
    }
    red[slot][h] = sum;
    __syncthreads();
    if (slot == 0) {
        float d = red[0][h] + red[1][h] + red[2][h] + red[3][h];
        sm_inv[h] = 1.0f / (d + GAT_EPS);
    }
    __syncthreads();
    float INV = sm_inv[h];

    int c = t & 63, g = t >> 6;
    float acc[16];
#pragma unroll
    for (int k = 0; k < 16; k++) acc[k] = 0.f;

    for (int jb = beg; jb < end; jb += 32) {
        int cnt = min(32, end - jb);
        if (t < cnt) srcb[t] = g_esrc[jb + t];
        __syncthreads();
        for (int j = slot; j < cnt; j += 4) {
            int s = srcb[j];
            float e = leaky(g_A1s[s * IN_HEAD + h] + adst);
            alpha[j][h] = expf(e - M) * INV;
        }
        __syncthreads();
        for (int j = 0; j < cnt; j++) {
            const float* row = g_H1 + (size_t)srcb[j] * F1;
#pragma unroll
            for (int k = 0; k < 16; k++) {
                int hh = g * 16 + k;
                acc[k] += alpha[j][hh] * row[hh * HID + c];
            }
        }
        __syncthreads();
    }
    bf16* rowo = g_H1ae + (size_t)n * K2E;
#pragma unroll
    for (int k = 0; k < 16; k++) {
        int idx = (g * 16 + k) * HID + c;
        float v = acc[k] + b1[idx];
        v = v > 0.f ? v : expm1f(v);   // elu
        bf16 hi = __float2bfloat16(v);
        rowo[idx] = hi; rowo[F1 + idx] = hi;   // 2-term: [A_hi | A_hi]
    }
}

// ---------------- Layer-2 softmax + aggregation + head-mean + bias ----------------
__global__ void k_agg2(const float* __restrict__ b2) {
    int n = blockIdx.x;
    int t = threadIdx.x;
    int beg = g_offs[n], end = g_offs[n + 1];

    __shared__ float sm_m[OUT_HEAD], sm_inv[OUT_HEAD];
    __shared__ int   srcb[16];
    __shared__ float alpha[16][OUT_HEAD];

    if (t < OUT_HEAD) {
        float adst = g_A2d[n * OUT_HEAD + t];
        float mx = -1e30f;
        for (int j = beg; j < end; j++)
            mx = fmaxf(mx, leaky(g_A2s[g_esrc[j] * OUT_HEAD + t] + adst));
        float sum = 0.f;
        for (int j = beg; j < end; j++)
            sum += expf(leaky(g_A2s[g_esrc[j] * OUT_HEAD + t] + adst) - mx);
        sm_m[t] = mx;
        sm_inv[t] = 1.0f / (sum + GAT_EPS);
    }
    __syncthreads();

    float acc[OUT_HEAD] = {0.f, 0.f, 0.f, 0.f, 0.f};
    for (int jb = beg; jb < end; jb += 16) {
        int cnt = min(16, end - jb);
        if (t < cnt) srcb[t] = g_esrc[jb + t];
        __syncthreads();
        if (t < cnt * OUT_HEAD) {
            int j = t / OUT_HEAD, hh = t % OUT_HEAD;
            int s = srcb[j];
            float e = leaky(g_A2s[s * OUT_HEAD + hh] + g_A2d[n * OUT_HEAD + hh]);
            alpha[j][hh] = expf(e - sm_m[hh]) * sm_inv[hh];
        }
        __syncthreads();
        for (int j = 0; j < cnt; j++) {
            const float* row = g_H2 + (size_t)srcb[j] * F2;
#pragma unroll
            for (int hh = 0; hh < OUT_HEAD; hh++)
                acc[hh] += alpha[j][hh] * row[hh * OUT_FEAT + t];
        }
        __syncthreads();
    }
    float o = (acc[0] + acc[1] + acc[2] + acc[3] + acc[4]) * 0.2f + b2[t];
    g_H2o[(size_t)n * OUT_FEAT + t] = o;
}

// ---------------- Final node-mean + tanh ----------------
__global__ void k_part() {
    int b = blockIdx.x, c = threadIdx.x;
    float s = 0.f;
    for (int i = 0; i < N_NODES / 32; i++)
        s += g_H2o[(size_t)(b * (N_NODES / 32) + i) * OUT_FEAT + c];
    g_part[b * OUT_FEAT + c] = s;
}

__global__ void k_final(float* __restrict__ out) {
    int c = threadIdx.x;
    float s = 0.f;
#pragma unroll
    for (int b = 0; b < 32; b++) s += g_part[b * OUT_FEAT + c];
    out[c] = tanhf(s / (float)N_NODES);
}

// ---------------- Launch ----------------
extern "C" void kernel_launch(void* const* d_in, const int* in_sizes, int n_in,
                              void* d_out, int out_size) {
    const float* x        = (const float*)d_in[0];
    const void*  ei       = d_in[1];
    const float* W1       = (const float*)d_in[2];
    const float* att_src1 = (const float*)d_in[3];
    const float* att_dst1 = (const float*)d_in[4];
    const float* b1       = (const float*)d_in[5];
    const float* W2       = (const float*)d_in[6];
    const float* att_src2 = (const float*)d_in[7];
    const float* att_dst2 = (const float*)d_in[8];
    const float* b2       = (const float*)d_in[9];
    float* out = (float*)d_out;

    static float* s_H1   = nullptr;
    static float* s_P0   = nullptr;
    static float* s_P1   = nullptr;
    static bf16*  s_xe   = nullptr;
    static bf16*  s_W1e  = nullptr;
    static bf16*  s_H1ae = nullptr;
    static bf16*  s_W2e  = nullptr;
    static bool   s_init = false;
    if (!s_init) {
        cudaGetSymbolAddress((void**)&s_H1,   g_H1);
        cudaGetSymbolAddress((void**)&s_P0,   g_P0);
        cudaGetSymbolAddress((void**)&s_P1,   g_P1);
        cudaGetSymbolAddress((void**)&s_xe,   g_xe);
        cudaGetSymbolAddress((void**)&s_W1e,  g_W1e);
        cudaGetSymbolAddress((void**)&s_H1ae, g_H1ae);
        cudaGetSymbolAddress((void**)&s_W2e,  g_W2e);
        cudaFuncSetAttribute(hgemm, cudaFuncAttributeMaxDynamicSharedMemorySize, HG_SMEM);
        s_init = true;
    }

    k_init<<<(N_NODES + 256) / 256, 256>>>((const int*)ei);
    k_count<<<(E2 + 255) / 256, 256>>>(ei);
    k_scan<<<1, 1024>>>();
    k_scatter<<<(E2 + 255) / 256, 256>>>(ei);

    // split-expand inputs for tensor-core GEMMs
    k_split_x <<<(N_NODES * IN_FEAT) / 256, 256>>>(x);
    k_split_W1<<<(IN_FEAT * F1) / 256, 256>>>(W1);
    k_split_W2<<<(F1 * F2 + 255) / 256, 256>>>(W2);

    // GEMM1: H1 = x @ W1  (3-term split)  [4096,768]x[768,4096]
    hgemm<<<dim3(F1 / BN, N_NODES / BM, 1), 256, HG_SMEM>>>(
        s_xe, s_W1e, s_H1, s_H1, F1, K1E, K1E);

    k_dots1<<<(N_NODES * IN_HEAD) / 8, 256>>>(att_src1, att_dst1);
    k_agg1<<<N_NODES, 256>>>(b1);

    // GEMM2: H2 = H1a_hi @ W2  (2-term split)  [4096,8192]x[8192,640], fused split-K=2
    hgemm<<<dim3(F2 / BN, N_NODES / BM, 2), 256, HG_SMEM>>>(
        s_H1ae, s_W2e, s_P0, s_P1, F2, K2E, K2E / 2);
    k_red<<<((N_NODES * F2 / 4) + 255) / 256, 256>>>();

    k_dots2<<<((N_NODES * OUT_HEAD + 7) / 8), 256>>>(att_src2, att_dst2);
    k_agg2<<<N_NODES, 128>>>(b2);

    k_part<<<32, 128>>>();
    k_final<<<1, 128>>>(out);
}

// round 8
// speedup vs baseline: 2.7815x; 1.1253x over previous
#include <cuda_runtime.h>
#include <cuda_bf16.h>
#include <stdint.h>
#include <math.h>

typedef __nv_bfloat16 bf16;

// ---------------- Problem constants ----------------
#define N_NODES 4096
#define N_EDGES 32768
#define E2      (N_EDGES + N_NODES)   // with self loops = 36864
#define IN_FEAT 256
#define HID     64
#define IN_HEAD 64
#define OUT_FEAT 128
#define OUT_HEAD 5
#define F1      (IN_HEAD * HID)       // 4096
#define F2      (OUT_HEAD * OUT_FEAT) // 640
#define NEG_SLOPE 0.2f
#define GAT_EPS 1e-16f

#define K1E (2 * IN_FEAT)             // 512  logical K for GEMM1 (2-term)
#define K2E (2 * F1)                  // 8192 logical K for GEMM2 (2-term)

// ---------------- Device scratch ----------------
__device__ int   g_is64;
__device__ int   g_counts[N_NODES + 1];
__device__ int   g_offs[N_NODES + 1];
__device__ int   g_cursor[N_NODES];
__device__ int   g_esrc[E2];
__device__ bf16  g_H1b[(size_t)N_NODES * F1];     // x @ W1 in bf16 (32 MB)
__device__ float g_A1s[(size_t)N_NODES * IN_HEAD];
__device__ float g_A1d[(size_t)N_NODES * IN_HEAD];
__device__ float g_H2 [(size_t)N_NODES * F2];     // H1a @ W2 (fp32, 10 MB)
__device__ float g_P0 [(size_t)N_NODES * F2];     // split-K partial 0
__device__ float g_P1 [(size_t)N_NODES * F2];     // split-K partial 1
__device__ float g_A2s[(size_t)N_NODES * OUT_HEAD];
__device__ float g_A2d[(size_t)N_NODES * OUT_HEAD];
__device__ float g_H2o[(size_t)N_NODES * OUT_FEAT];
__device__ float g_part[32 * OUT_FEAT];

// bf16 operands. A operands stored WITHOUT duplication (kernel applies k & aKmod):
//   GEMM1: A = x_hi [4096,256], B = [W1_hi ; W1_lo] [512,4096]  -> x_hi @ W1 exact
//   GEMM2: A = H1a_hi [4096,4096], B = [W2_hi ; W2_lo] [8192,640] -> H1a_hi @ W2 exact
__device__ bf16  g_xe  [(size_t)N_NODES * IN_FEAT]; // 2 MB
__device__ bf16  g_W1e [(size_t)K1E * F1];          // 4 MB
__device__ bf16  g_H1ae[(size_t)N_NODES * F1];      // 33 MB
__device__ bf16  g_W2e [(size_t)K2E * F2];          // 10.5 MB

// ---------------- init: zero counts + int64/int32 detect ----------------
__global__ void k_init(const int* ei32) {
    int i = blockIdx.x * blockDim.x + threadIdx.x;
    if (i <= N_NODES) g_counts[i] = 0;
    if (blockIdx.x == 0 && threadIdx.x < 32) {
        int v = ei32[2 * threadIdx.x + 1];
        unsigned any = __ballot_sync(0xffffffffu, v != 0);
        if (threadIdx.x == 0) g_is64 = (any == 0) ? 1 : 0;
    }
}

__device__ __forceinline__ int load_ei(const void* ei, int idx) {
    if (g_is64) return (int)((const long long*)ei)[idx];
    return ((const int*)ei)[idx];
}

// ---------------- CSR build ----------------
__global__ void k_count(const void* ei) {
    int i = blockIdx.x * blockDim.x + threadIdx.x;
    if (i >= E2) return;
    int dst = (i < N_EDGES) ? load_ei(ei, N_EDGES + i) : (i - N_EDGES);
    atomicAdd(&g_counts[dst], 1);
}

__global__ void k_scan() {   // 1 block, 1024 threads; scan 4096 counts
    __shared__ int buf[2][1024];
    int t = threadIdx.x;
    int c0 = g_counts[4 * t], c1 = g_counts[4 * t + 1];
    int c2 = g_counts[4 * t + 2], c3 = g_counts[4 * t + 3];
    int s = c0 + c1 + c2 + c3;
    buf[0][t] = s;
    __syncthreads();
    int pin = 0;
    for (int off = 1; off < 1024; off <<= 1) {
        int v = buf[pin][t];
        if (t >= off) v += buf[pin][t - off];
        buf[pin ^ 1][t] = v;
        pin ^= 1;
        __syncthreads();
    }
    int incl = buf[pin][t];
    int base = incl - s;
    g_offs[4 * t]     = base;
    g_offs[4 * t + 1] = base + c0;
    g_offs[4 * t + 2] = base + c0 + c1;
    g_offs[4 * t + 3] = base + c0 + c1 + c2;
    g_cursor[4 * t]     = base;
    g_cursor[4 * t + 1] = base + c0;
    g_cursor[4 * t + 2] = base + c0 + c1;
    g_cursor[4 * t + 3] = base + c0 + c1 + c2;
    if (t == 1023) g_offs[N_NODES] = incl;
}

__global__ void k_scatter(const void* ei) {
    int i = blockIdx.x * blockDim.x + threadIdx.x;
    if (i >= E2) return;
    int src, dst;
    if (i < N_EDGES) { src = load_ei(ei, i); dst = load_ei(ei, N_EDGES + i); }
    else             { src = i - N_EDGES;    dst = i - N_EDGES; }
    int pos = atomicAdd(&g_cursor[dst], 1);
    g_esrc[pos] = src;
}

// ---------------- split-bf16 expansion kernels ----------------
__device__ __forceinline__ void split2(float v, bf16& hi, bf16& lo) {
    hi = __float2bfloat16(v);
    lo = __float2bfloat16(v - __bfloat162float(hi));
}

__global__ void k_split_x(const float* __restrict__ x) {   // x_hi [4096,256]
    int i = blockIdx.x * blockDim.x + threadIdx.x;
    g_xe[i] = __float2bfloat16(x[i]);
}

__global__ void k_split_W1(const float* __restrict__ W) {  // [256,4096] -> [512,4096]
    int i = blockIdx.x * blockDim.x + threadIdx.x;
    int k = i >> 12, n = i & 4095;
    bf16 hi, lo; split2(W[i], hi, lo);
    g_W1e[(size_t)k * F1 + n]              = hi;
    g_W1e[(size_t)(IN_FEAT + k) * F1 + n]  = lo;
}

__global__ void k_split_W2(const float* __restrict__ W) {  // [4096,640] -> [8192,640]
    int i = blockIdx.x * blockDim.x + threadIdx.x;
    if (i >= F1 * F2) return;
    int k = i / F2, n = i % F2;
    bf16 hi, lo; split2(W[i], hi, lo);
    g_W2e[(size_t)k * F2 + n]        = hi;
    g_W2e[(size_t)(F1 + k) * F2 + n] = lo;
}

// ---------------- bf16 tensor-core GEMM (mma.sync, 3-stage cp.async) ----------------
// C[M,N] = A[M, *] * B[kOff:kOff+kLen, N].  A col index = (kLog & aKmod), physical
// row stride aStride. OUT=0: C fp32; OUT=1: C bf16.
// BM=128, BN=128, BK=32, 3 stages, 256 threads (8 warps 2x4, warp tile 64x32).
#define BM 128
#define BN 128
#define BK 32
#define STG 3
#define APITCH (BK + 8)
#define BPITCH (BN + 8)
#define HG_SMEM (STG * (BM * APITCH + BK * BPITCH) * 2)

template <int OUT>
__global__ __launch_bounds__(256, 2)
void hgemm(const bf16* __restrict__ A, const bf16* __restrict__ B,
           void* __restrict__ C0, void* __restrict__ C1,
           int N, int aStride, int aKmod, int kLen) {
    extern __shared__ bf16 smbuf[];
    bf16* sA = smbuf;                          // [STG][BM][APITCH]
    bf16* sB = smbuf + STG * BM * APITCH;      // [STG][BK][BPITCH]
    int t = threadIdx.x, lane = t & 31, warp = t >> 5;
    int wm = (warp >> 2) * 64;   // 0 or 64
    int wn = (warp & 3) * 32;    // 0,32,64,96
    int bx = blockIdx.x, by = blockIdx.y, bz = blockIdx.z;
    int kOff = bz * kLen;
    void* C = bz ? C1 : C0;
    const bf16* Ab = A + (size_t)(by * BM) * aStride;
    const bf16* Bb = B + (size_t)kOff * N + bx * BN;

    int a_row = t >> 2;          // 0..63 (+64)
    int a_col = (t & 3) * 8;
    int b_row = t >> 4;          // 0..15 (+16)
    int b_col = (t & 15) * 8;

    float acc[4][4][4];
#pragma unroll
    for (int i = 0; i < 4; i++)
#pragma unroll
        for (int j = 0; j < 4; j++)
#pragma unroll
            for (int r = 0; r < 4; r++) acc[i][j][r] = 0.f;

    auto issue = [&](int j) {
        int buf = j % STG;
        int k0 = j * BK;
        int akc = (kOff + k0 + a_col) & aKmod;
        bf16* pa = sA + buf * BM * APITCH;
        bf16* pb = sB + buf * BK * BPITCH;
        uint32_t da0 = (uint32_t)__cvta_generic_to_shared(pa + a_row * APITCH + a_col);
        uint32_t da1 = (uint32_t)__cvta_generic_to_shared(pa + (a_row + 64) * APITCH + a_col);
        const bf16* ga0 = Ab + (size_t)a_row * aStride + akc;
        const bf16* ga1 = Ab + (size_t)(a_row + 64) * aStride + akc;
        asm volatile("cp.async.cg.shared.global [%0], [%1], 16;" :: "r"(da0), "l"(ga0));
        asm volatile("cp.async.cg.shared.global [%0], [%1], 16;" :: "r"(da1), "l"(ga1));
        uint32_t db0 = (uint32_t)__cvta_generic_to_shared(pb + b_row * BPITCH + b_col);
        uint32_t db1 = (uint32_t)__cvta_generic_to_shared(pb + (b_row + 16) * BPITCH + b_col);
        const bf16* gb0 = Bb + (size_t)(k0 + b_row) * N + b_col;
        const bf16* gb1 = Bb + (size_t)(k0 + b_row + 16) * N + b_col;
        asm volatile("cp.async.cg.shared.global [%0], [%1], 16;" :: "r"(db0), "l"(gb0));
        asm volatile("cp.async.cg.shared.global [%0], [%1], 16;" :: "r"(db1), "l"(gb1));
        asm volatile("cp.async.commit_group;");
    };

    int nc = kLen / BK;
    issue(0);
    if (nc > 1) issue(1);
    for (int s = 0; s < nc; s++) {
        if (s < nc - 1) { asm volatile("cp.async.wait_group 1;"); }
        else            { asm volatile("cp.async.wait_group 0;"); }
        __syncthreads();
        if (s + 2 < nc) issue(s + 2);
        int buf = s % STG;
        bf16* pa = sA + buf * BM * APITCH;
        bf16* pb = sB + buf * BK * BPITCH;
#pragma unroll
        for (int kk = 0; kk < 2; kk++) {
            int k = kk * 16;
            uint32_t ar[4][4], br[2][4];
#pragma unroll
            for (int mi = 0; mi < 4; mi++) {
                int row = wm + mi * 16 + (lane & 7) + ((lane >> 3) & 1) * 8;
                int col = k + (lane >> 4) * 8;
                uint32_t addr = (uint32_t)__cvta_generic_to_shared(pa + row * APITCH + col);
                asm volatile("ldmatrix.sync.aligned.m8n8.x4.shared.b16 {%0,%1,%2,%3}, [%4];"
                             : "=r"(ar[mi][0]), "=r"(ar[mi][1]), "=r"(ar[mi][2]), "=r"(ar[mi][3])
                             : "r"(addr));
            }
#pragma unroll
            for (int n2 = 0; n2 < 2; n2++) {
                int rrow = k + (lane & 7) + ((lane >> 3) & 1) * 8;
                int rcol = wn + n2 * 16 + (lane >> 4) * 8;
                uint32_t addr = (uint32_t)__cvta_generic_to_shared(pb + rrow * BPITCH + rcol);
                asm volatile("ldmatrix.sync.aligned.m8n8.x4.trans.shared.b16 {%0,%1,%2,%3}, [%4];"
                             : "=r"(br[n2][0]), "=r"(br[n2][1]), "=r"(br[n2][2]), "=r"(br[n2][3])
                             : "r"(addr));
            }
#pragma unroll
            for (int mi = 0; mi < 4; mi++)
#pragma unroll
                for (int ni = 0; ni < 4; ni++) {
                    uint32_t b0 = br[ni >> 1][(ni & 1) * 2];
                    uint32_t b1 = br[ni >> 1][(ni & 1) * 2 + 1];
                    asm volatile(
                        "mma.sync.aligned.m16n8k16.row.col.f32.bf16.bf16.f32 "
                        "{%0,%1,%2,%3}, {%4,%5,%6,%7}, {%8,%9}, {%0,%1,%2,%3};"
                        : "+f"(acc[mi][ni][0]), "+f"(acc[mi][ni][1]),
                          "+f"(acc[mi][ni][2]), "+f"(acc[mi][ni][3])
                        : "r"(ar[mi][0]), "r"(ar[mi][1]), "r"(ar[mi][2]), "r"(ar[mi][3]),
                          "r"(b0), "r"(b1));
                }
        }
        __syncthreads();
    }
    if (OUT == 0) {
        float* Cb = (float*)C + (size_t)(by * BM + wm) * N + bx * BN + wn;
#pragma unroll
        for (int mi = 0; mi < 4; mi++)
#pragma unroll
            for (int ni = 0; ni < 4; ni++) {
                int r0 = mi * 16 + (lane >> 2);
                int c0 = ni * 8 + (lane & 3) * 2;
                *(float2*)(Cb + (size_t)r0 * N + c0)       = make_float2(acc[mi][ni][0], acc[mi][ni][1]);
                *(float2*)(Cb + (size_t)(r0 + 8) * N + c0) = make_float2(acc[mi][ni][2], acc[mi][ni][3]);
            }
    } else {
        bf16* Cb = (bf16*)C + (size_t)(by * BM + wm) * N + bx * BN + wn;
#pragma unroll
        for (int mi = 0; mi < 4; mi++)
#pragma unroll
            for (int ni = 0; ni < 4; ni++) {
                int r0 = mi * 16 + (lane >> 2);
                int c0 = ni * 8 + (lane & 3) * 2;
                __nv_bfloat162 v0 = __floats2bfloat162_rn(acc[mi][ni][0], acc[mi][ni][1]);
                __nv_bfloat162 v1 = __floats2bfloat162_rn(acc[mi][ni][2], acc[mi][ni][3]);
                *(__nv_bfloat162*)(Cb + (size_t)r0 * N + c0)       = v0;
                *(__nv_bfloat162*)(Cb + (size_t)(r0 + 8) * N + c0) = v1;
            }
    }
}

// split-K reduction: H2 = P0 + P1 (float4 vectorized)
__global__ void k_red() {
    int i = blockIdx.x * blockDim.x + threadIdx.x;    // over float4s
    if (i >= (N_NODES * F2) / 4) return;
    float4 a = ((const float4*)g_P0)[i];
    float4 b = ((const float4*)g_P1)[i];
    ((float4*)g_H2)[i] = make_float4(a.x + b.x, a.y + b.y, a.z + b.z, a.w + b.w);
}

// ---------------- Attention dot products ----------------
__global__ void k_dots1(const float* __restrict__ att_src, const float* __restrict__ att_dst) {
    int warp = (blockIdx.x * blockDim.x + threadIdx.x) >> 5;
    int lane = threadIdx.x & 31;
    int n = warp >> 6, h = warp & 63;
    const bf16* row = g_H1b + (size_t)n * F1 + h * HID;
    float v1 = __bfloat162float(row[lane]), v2 = __bfloat162float(row[lane + 32]);
    float sa = v1 * att_src[h * HID + lane] + v2 * att_src[h * HID + lane + 32];
    float sd = v1 * att_dst[h * HID + lane] + v2 * att_dst[h * HID + lane + 32];
#pragma unroll
    for (int o = 16; o > 0; o >>= 1) {
        sa += __shfl_xor_sync(0xffffffffu, sa, o);
        sd += __shfl_xor_sync(0xffffffffu, sd, o);
    }
    if (lane == 0) {
        g_A1s[n * IN_HEAD + h] = sa;
        g_A1d[n * IN_HEAD + h] = sd;
    }
}

__global__ void k_dots2(const float* __restrict__ att_src, const float* __restrict__ att_dst) {
    int warp = (blockIdx.x * blockDim.x + threadIdx.x) >> 5;
    int lane = threadIdx.x & 31;
    if (warp >= N_NODES * OUT_HEAD) return;
    int n = warp / OUT_HEAD, h = warp % OUT_HEAD;
    const float* row = g_H2 + (size_t)n * F2 + h * OUT_FEAT;
    float sa = 0.f, sd = 0.f;
#pragma unroll
    for (int k = 0; k < 4; k++) {
        int c = lane + 32 * k;
        float v = row[c];
        sa += v * att_src[h * OUT_FEAT + c];
        sd += v * att_dst[h * OUT_FEAT + c];
    }
#pragma unroll
    for (int o = 16; o > 0; o >>= 1) {
        sa += __shfl_xor_sync(0xffffffffu, sa, o);
        sd += __shfl_xor_sync(0xffffffffu, sd, o);
    }
    if (lane == 0) {
        g_A2s[n * OUT_HEAD + h] = sa;
        g_A2d[n * OUT_HEAD + h] = sd;
    }
}

__device__ __forceinline__ float leaky(float x) { return x > 0.f ? x : NEG_SLOPE * x; }

// ---------------- Layer-1 softmax + aggregation + bias + elu -> bf16 hi ----------------
__global__ void k_agg1(const float* __restrict__ b1) {
    int n = blockIdx.x;
    int t = threadIdx.x;
    int h = t & 63, slot = t >> 6;
    int beg = g_offs[n], end = g_offs[n + 1];
    float adst = g_A1d[n * IN_HEAD + h];

    __shared__ float red[4][64];
    __shared__ float sm_m[64], sm_inv[64];
    __shared__ int   srcb[32];
    __shared__ float alpha[32][64];

    float mx = -1e30f;
    for (int j = beg + slot; j < end; j += 4) {
        int s = g_esrc[j];
        mx = fmaxf(mx, leaky(g_A1s[s * IN_HEAD + h] + adst));
    }
    red[slot][h] = mx;
    __syncthreads();
    if (slot == 0) {
        sm_m[h] = fmaxf(fmaxf(red[0][h], red[1][h]), fmaxf(red[2][h], red[3][h]));
    }
    __syncthreads();
    float M = sm_m[h];

    float sum = 0.f;
    for (int j = beg + slot; j < end; j += 4) {
        int s = g_esrc[j];
        sum += expf(leaky(g_A1s[s * IN_HEAD + h] + adst) - M);
    }
    red[slot][h] = sum;
    __syncthreads();
    if (slot == 0) {
        float d = red[0][h] + red[1][h] + red[2][h] + red[3][h];
        sm_inv[h] = 1.0f / (d + GAT_EPS);
    }
    __syncthreads();
    float INV = sm_inv[h];

    int c = t & 63, g = t >> 6;
    float acc[16];
#pragma unroll
    for (int k = 0; k < 16; k++) acc[k] = 0.f;

    for (int jb = beg; jb < end; jb += 32) {
        int cnt = min(32, end - jb);
        if (t < cnt) srcb[t] = g_esrc[jb + t];
        __syncthreads();
        for (int j = slot; j < cnt; j += 4) {
            int s = srcb[j];
            float e = leaky(g_A1s[s * IN_HEAD + h] + adst);
            alpha[j][h] = expf(e - M) * INV;
        }
        __syncthreads();
        for (int j = 0; j < cnt; j++) {
            const bf16* row = g_H1b + (size_t)srcb[j] * F1;
#pragma unroll
            for (int k = 0; k < 16; k++) {
                int hh = g * 16 + k;
                acc[k] += alpha[j][hh] * __bfloat162float(row[hh * HID + c]);
            }
        }
        __syncthreads();
    }
    bf16* rowo = g_H1ae + (size_t)n * F1;
#pragma unroll
    for (int k = 0; k < 16; k++) {
        int idx = (g * 16 + k) * HID + c;
        float v = acc[k] + b1[idx];
        v = v > 0.f ? v : expm1f(v);   // elu
        rowo[idx] = __float2bfloat16(v);
    }
}

// ---------------- Layer-2 softmax + aggregation + head-mean + bias ----------------
__global__ void k_agg2(const float* __restrict__ b2) {
    int n = blockIdx.x;
    int t = threadIdx.x;
    int beg = g_offs[n], end = g_offs[n + 1];

    __shared__ float sm_m[OUT_HEAD], sm_inv[OUT_HEAD];
    __shared__ int   srcb[16];
    __shared__ float alpha[16][OUT_HEAD];

    if (t < OUT_HEAD) {
        float adst = g_A2d[n * OUT_HEAD + t];
        float mx = -1e30f;
        for (int j = beg; j < end; j++)
            mx = fmaxf(mx, leaky(g_A2s[g_esrc[j] * OUT_HEAD + t] + adst));
        float sum = 0.f;
        for (int j = beg; j < end; j++)
            sum += expf(leaky(g_A2s[g_esrc[j] * OUT_HEAD + t] + adst) - mx);
        sm_m[t] = mx;
        sm_inv[t] = 1.0f / (sum + GAT_EPS);
    }
    __syncthreads();

    float acc[OUT_HEAD] = {0.f, 0.f, 0.f, 0.f, 0.f};
    for (int jb = beg; jb < end; jb += 16) {
        int cnt = min(16, end - jb);
        if (t < cnt) srcb[t] = g_esrc[jb + t];
        __syncthreads();
        if (t < cnt * OUT_HEAD) {
            int j = t / OUT_HEAD, hh = t % OUT_HEAD;
            int s = srcb[j];
            float e = leaky(g_A2s[s * OUT_HEAD + hh] + g_A2d[n * OUT_HEAD + hh]);
            alpha[j][hh] = expf(e - sm_m[hh]) * sm_inv[hh];
        }
        __syncthreads();
        for (int j = 0; j < cnt; j++) {
            const float* row = g_H2 + (size_t)srcb[j] * F2;
#pragma unroll
            for (int hh = 0; hh < OUT_HEAD; hh++)
                acc[hh] += alpha[j][hh] * row[hh * OUT_FEAT + t];
        }
        __syncthreads();
    }
    float o = (acc[0] + acc[1] + acc[2] + acc[3] + acc[4]) * 0.2f + b2[t];
    g_H2o[(size_t)n * OUT_FEAT + t] = o;
}

// ---------------- Final node-mean + tanh ----------------
__global__ void k_part() {
    int b = blockIdx.x, c = threadIdx.x;
    float s = 0.f;
    for (int i = 0; i < N_NODES / 32; i++)
        s += g_H2o[(size_t)(b * (N_NODES / 32) + i) * OUT_FEAT + c];
    g_part[b * OUT_FEAT + c] = s;
}

__global__ void k_final(float* __restrict__ out) {
    int c = threadIdx.x;
    float s = 0.f;
#pragma unroll
    for (int b = 0; b < 32; b++) s += g_part[b * OUT_FEAT + c];
    out[c] = tanhf(s / (float)N_NODES);
}

// ---------------- Launch ----------------
extern "C" void kernel_launch(void* const* d_in, const int* in_sizes, int n_in,
                              void* d_out, int out_size) {
    const float* x        = (const float*)d_in[0];
    const void*  ei       = d_in[1];
    const float* W1       = (const float*)d_in[2];
    const float* att_src1 = (const float*)d_in[3];
    const float* att_dst1 = (const float*)d_in[4];
    const float* b1       = (const float*)d_in[5];
    const float* W2       = (const float*)d_in[6];
    const float* att_src2 = (const float*)d_in[7];
    const float* att_dst2 = (const float*)d_in[8];
    const float* b2       = (const float*)d_in[9];
    float* out = (float*)d_out;

    static bf16*  s_H1b  = nullptr;
    static float* s_P0   = nullptr;
    static float* s_P1   = nullptr;
    static bf16*  s_xe   = nullptr;
    static bf16*  s_W1e  = nullptr;
    static bf16*  s_H1ae = nullptr;
    static bf16*  s_W2e  = nullptr;
    static bool   s_init = false;
    if (!s_init) {
        cudaGetSymbolAddress((void**)&s_H1b,  g_H1b);
        cudaGetSymbolAddress((void**)&s_P0,   g_P0);
        cudaGetSymbolAddress((void**)&s_P1,   g_P1);
        cudaGetSymbolAddress((void**)&s_xe,   g_xe);
        cudaGetSymbolAddress((void**)&s_W1e,  g_W1e);
        cudaGetSymbolAddress((void**)&s_H1ae, g_H1ae);
        cudaGetSymbolAddress((void**)&s_W2e,  g_W2e);
        cudaFuncSetAttribute(hgemm<0>, cudaFuncAttributeMaxDynamicSharedMemorySize, HG_SMEM);
        cudaFuncSetAttribute(hgemm<1>, cudaFuncAttributeMaxDynamicSharedMemorySize, HG_SMEM);
        s_init = true;
    }

    k_init<<<(N_NODES + 256) / 256, 256>>>((const int*)ei);
    k_count<<<(E2 + 255) / 256, 256>>>(ei);
    k_scan<<<1, 1024>>>();
    k_scatter<<<(E2 + 255) / 256, 256>>>(ei);

    // bf16 operand prep
    k_split_x <<<(N_NODES * IN_FEAT) / 256, 256>>>(x);
    k_split_W1<<<(IN_FEAT * F1) / 256, 256>>>(W1);
    k_split_W2<<<(F1 * F2 + 255) / 256, 256>>>(W2);

    // GEMM1: H1b = x_hi @ [W1_hi;W1_lo]  (= x_hi @ W1), bf16 out, A col = k & 255
    hgemm<1><<<dim3(F1 / BN, N_NODES / BM, 1), 256, HG_SMEM>>>(
        s_xe, s_W1e, s_H1b, s_H1b, F1, IN_FEAT, IN_FEAT - 1, K1E);

    k_dots1<<<(N_NODES * IN_HEAD) / 8, 256>>>(att_src1, att_dst1);
    k_agg1<<<N_NODES, 256>>>(b1);

    // GEMM2: H2 = H1a_hi @ [W2_hi;W2_lo], fused split-K=2, A col = k & 4095
    hgemm<0><<<dim3(F2 / BN, N_NODES / BM, 2), 256, HG_SMEM>>>(
        s_H1ae, s_W2e, s_P0, s_P1, F2, F1, F1 - 1, K2E / 2);
    k_red<<<((N_NODES * F2 / 4) + 255) / 256, 256>>>();

    k_dots2<<<((N_NODES * OUT_HEAD + 7) / 8), 256>>>(att_src2, att_dst2);
    k_agg2<<<N_NODES, 128>>>(b2);

    k_part<<<32, 128>>>();
    k_final<<<1, 128>>>(out);
}

// round 9
// speedup vs baseline: 2.9096x; 1.0461x over previous
#include <cuda_runtime.h>
#include <cuda_bf16.h>
#include <stdint.h>
#include <math.h>

typedef __nv_bfloat16 bf16;

// ---------------- Problem constants ----------------
#define N_NODES 4096
#define N_EDGES 32768
#define E2      (N_EDGES + N_NODES)   // with self loops = 36864
#define IN_FEAT 256
#define HID     64
#define IN_HEAD 64
#define OUT_FEAT 128
#define OUT_HEAD 5
#define F1      (IN_HEAD * HID)       // 4096
#define F2      (OUT_HEAD * OUT_FEAT) // 640
#define NEG_SLOPE 0.2f
#define GAT_EPS 1e-16f

#define K1E (2 * IN_FEAT)             // 512  logical K for GEMM1 (2-term)
#define K2E (2 * F1)                  // 8192 logical K for GEMM2 (2-term)

// ---------------- Device scratch ----------------
__device__ int   g_is64;
__device__ int   g_counts[N_NODES + 1];
__device__ int   g_offs[N_NODES + 1];
__device__ int   g_cursor[N_NODES];
__device__ int   g_esrc[E2];
__device__ bf16  g_H1b[(size_t)N_NODES * F1];     // x @ W1 in bf16 (32 MB)
__device__ float g_A1s[(size_t)N_NODES * IN_HEAD];
__device__ float g_A1d[(size_t)N_NODES * IN_HEAD];
__device__ float g_H2 [(size_t)N_NODES * F2];     // H1a @ W2 (fp32, 10 MB)
__device__ float g_P0 [(size_t)N_NODES * F2];     // split-K partial 0
__device__ float g_P1 [(size_t)N_NODES * F2];     // split-K partial 1
__device__ float g_A2s[(size_t)N_NODES * OUT_HEAD];
__device__ float g_A2d[(size_t)N_NODES * OUT_HEAD];
__device__ float g_H2o[(size_t)N_NODES * OUT_FEAT];
__device__ float g_part[32 * OUT_FEAT];

// bf16 operands. A operands stored WITHOUT duplication (kernel applies k & aKmod):
//   GEMM1: A = x_hi [4096,256], B = [W1_hi ; W1_lo] [512,4096]  -> x_hi @ W1 exact
//   GEMM2: A = H1a_hi [4096,4096], B = [W2_hi ; W2_lo] [8192,640] -> H1a_hi @ W2 exact
__device__ bf16  g_xe  [(size_t)N_NODES * IN_FEAT]; // 2 MB
__device__ bf16  g_W1e [(size_t)K1E * F1];          // 4 MB
__device__ bf16  g_H1ae[(size_t)N_NODES * F1];      // 33 MB
__device__ bf16  g_W2e [(size_t)K2E * F2];          // 10.5 MB

// ---------------- init: zero counts + int64/int32 detect ----------------
__global__ void k_init(const int* ei32) {
    int i = blockIdx.x * blockDim.x + threadIdx.x;
    if (i <= N_NODES) g_counts[i] = 0;
    if (blockIdx.x == 0 && threadIdx.x < 32) {
        int v = ei32[2 * threadIdx.x + 1];
        unsigned any = __ballot_sync(0xffffffffu, v != 0);
        if (threadIdx.x == 0) g_is64 = (any == 0) ? 1 : 0;
    }
}

__device__ __forceinline__ int load_ei(const void* ei, int idx) {
    if (g_is64) return (int)((const long long*)ei)[idx];
    return ((const int*)ei)[idx];
}

// ---------------- CSR build ----------------
__global__ void k_count(const void* ei) {
    int i = blockIdx.x * blockDim.x + threadIdx.x;
    if (i >= E2) return;
    int dst = (i < N_EDGES) ? load_ei(ei, N_EDGES + i) : (i - N_EDGES);
    atomicAdd(&g_counts[dst], 1);
}

__global__ void k_scan() {   // 1 block, 1024 threads; scan 4096 counts
    __shared__ int buf[2][1024];
    int t = threadIdx.x;
    int c0 = g_counts[4 * t], c1 = g_counts[4 * t + 1];
    int c2 = g_counts[4 * t + 2], c3 = g_counts[4 * t + 3];
    int s = c0 + c1 + c2 + c3;
    buf[0][t] = s;
    __syncthreads();
    int pin = 0;
    for (int off = 1; off < 1024; off <<= 1) {
        int v = buf[pin][t];
        if (t >= off) v += buf[pin][t - off];
        buf[pin ^ 1][t] = v;
        pin ^= 1;
        __syncthreads();
    }
    int incl = buf[pin][t];
    int base = incl - s;
    g_offs[4 * t]     = base;
    g_offs[4 * t + 1] = base + c0;
    g_offs[4 * t + 2] = base + c0 + c1;
    g_offs[4 * t + 3] = base + c0 + c1 + c2;
    g_cursor[4 * t]     = base;
    g_cursor[4 * t + 1] = base + c0;
    g_cursor[4 * t + 2] = base + c0 + c1;
    g_cursor[4 * t + 3] = base + c0 + c1 + c2;
    if (t == 1023) g_offs[N_NODES] = incl;
}

__global__ void k_scatter(const void* ei) {
    int i = blockIdx.x * blockDim.x + threadIdx.x;
    if (i >= E2) return;
    int src, dst;
    if (i < N_EDGES) { src = load_ei(ei, i); dst = load_ei(ei, N_EDGES + i); }
    else             { src = i - N_EDGES;    dst = i - N_EDGES; }
    int pos = atomicAdd(&g_cursor[dst], 1);
    g_esrc[pos] = src;
}

// ---------------- split-bf16 expansion kernels ----------------
__device__ __forceinline__ void split2(float v, bf16& hi, bf16& lo) {
    hi = __float2bfloat16(v);
    lo = __float2bfloat16(v - __bfloat162float(hi));
}

__global__ void k_split_x(const float* __restrict__ x) {   // x_hi [4096,256]
    int i = blockIdx.x * blockDim.x + threadIdx.x;
    g_xe[i] = __float2bfloat16(x[i]);
}

__global__ void k_split_W1(const float* __restrict__ W) {  // [256,4096] -> [512,4096]
    int i = blockIdx.x * blockDim.x + threadIdx.x;
    int k = i >> 12, n = i & 4095;
    bf16 hi, lo; split2(W[i], hi, lo);
    g_W1e[(size_t)k * F1 + n]              = hi;
    g_W1e[(size_t)(IN_FEAT + k) * F1 + n]  = lo;
}

__global__ void k_split_W2(const float* __restrict__ W) {  // [4096,640] -> [8192,640]
    int i = blockIdx.x * blockDim.x + threadIdx.x;
    if (i >= F1 * F2) return;
    int k = i / F2, n = i % F2;
    bf16 hi, lo; split2(W[i], hi, lo);
    g_W2e[(size_t)k * F2 + n]        = hi;
    g_W2e[(size_t)(F1 + k) * F2 + n] = lo;
}

// ---------------- bf16 tensor-core GEMM (mma.sync, 3-stage cp.async) ----------------
// C[M,N] = A[M, *] * B[kOff:kOff+kLen, N].  A col index = (kLog & aKmod), physical
// row stride aStride. OUT=0: C fp32; OUT=1: C bf16.
// BM=128, BN=128, BK=32, 3 stages, 256 threads (8 warps 2x4, warp tile 64x32).
#define BM 128
#define BN 128
#define BK 32
#define STG 3
#define APITCH (BK + 8)
#define BPITCH (BN + 8)
#define HG_SMEM (STG * (BM * APITCH + BK * BPITCH) * 2)

template <int OUT>
__global__ __launch_bounds__(256, 2)
void hgemm(const bf16* __restrict__ A, const bf16* __restrict__ B,
           void* __restrict__ C0, void* __restrict__ C1,
           int N, int aStride, int aKmod, int kLen) {
    extern __shared__ bf16 smbuf[];
    bf16* sA = smbuf;                          // [STG][BM][APITCH]
    bf16* sB = smbuf + STG * BM * APITCH;      // [STG][BK][BPITCH]
    int t = threadIdx.x, lane = t & 31, warp = t >> 5;
    int wm = (warp >> 2) * 64;   // 0 or 64
    int wn = (warp & 3) * 32;    // 0,32,64,96
    int bx = blockIdx.x, by = blockIdx.y, bz = blockIdx.z;
    int kOff = bz * kLen;
    void* C = bz ? C1 : C0;
    const bf16* Ab = A + (size_t)(by * BM) * aStride;
    const bf16* Bb = B + (size_t)kOff * N + bx * BN;

    int a_row = t >> 2;          // 0..63 (+64)
    int a_col = (t & 3) * 8;
    int b_row = t >> 4;          // 0..15 (+16)
    int b_col = (t & 15) * 8;

    float acc[4][4][4];
#pragma unroll
    for (int i = 0; i < 4; i++)
#pragma unroll
        for (int j = 0; j < 4; j++)
#pragma unroll
            for (int r = 0; r < 4; r++) acc[i][j][r] = 0.f;

    auto issue = [&](int j) {
        int buf = j % STG;
        int k0 = j * BK;
        int akc = (kOff + k0 + a_col) & aKmod;
        bf16* pa = sA + buf * BM * APITCH;
        bf16* pb = sB + buf * BK * BPITCH;
        uint32_t da0 = (uint32_t)__cvta_generic_to_shared(pa + a_row * APITCH + a_col);
        uint32_t da1 = (uint32_t)__cvta_generic_to_shared(pa + (a_row + 64) * APITCH + a_col);
        const bf16* ga0 = Ab + (size_t)a_row * aStride + akc;
        const bf16* ga1 = Ab + (size_t)(a_row + 64) * aStride + akc;
        asm volatile("cp.async.cg.shared.global [%0], [%1], 16;" :: "r"(da0), "l"(ga0));
        asm volatile("cp.async.cg.shared.global [%0], [%1], 16;" :: "r"(da1), "l"(ga1));
        uint32_t db0 = (uint32_t)__cvta_generic_to_shared(pb + b_row * BPITCH + b_col);
        uint32_t db1 = (uint32_t)__cvta_generic_to_shared(pb + (b_row + 16) * BPITCH + b_col);
        const bf16* gb0 = Bb + (size_t)(k0 + b_row) * N + b_col;
        const bf16* gb1 = Bb + (size_t)(k0 + b_row + 16) * N + b_col;
        asm volatile("cp.async.cg.shared.global [%0], [%1], 16;" :: "r"(db0), "l"(gb0));
        asm volatile("cp.async.cg.shared.global [%0], [%1], 16;" :: "r"(db1), "l"(gb1));
        asm volatile("cp.async.commit_group;");
    };

    int nc = kLen / BK;
    issue(0);
    if (nc > 1) issue(1);
    for (int s = 0; s < nc; s++) {
        if (s < nc - 1) { asm volatile("cp.async.wait_group 1;"); }
        else            { asm volatile("cp.async.wait_group 0;"); }
        __syncthreads();
        if (s + 2 < nc) issue(s + 2);
        int buf = s % STG;
        bf16* pa = sA + buf * BM * APITCH;
        bf16* pb = sB + buf * BK * BPITCH;
#pragma unroll
        for (int kk = 0; kk < 2; kk++) {
            int k = kk * 16;
            uint32_t ar[4][4], br[2][4];
#pragma unroll
            for (int mi = 0; mi < 4; mi++) {
                int row = wm + mi * 16 + (lane & 7) + ((lane >> 3) & 1) * 8;
                int col = k + (lane >> 4) * 8;
                uint32_t addr = (uint32_t)__cvta_generic_to_shared(pa + row * APITCH + col);
                asm volatile("ldmatrix.sync.aligned.m8n8.x4.shared.b16 {%0,%1,%2,%3}, [%4];"
                             : "=r"(ar[mi][0]), "=r"(ar[mi][1]), "=r"(ar[mi][2]), "=r"(ar[mi][3])
                             : "r"(addr));
            }
#pragma unroll
            for (int n2 = 0; n2 < 2; n2++) {
                int rrow = k + (lane & 7) + ((lane >> 3) & 1) * 8;
                int rcol = wn + n2 * 16 + (lane >> 4) * 8;
                uint32_t addr = (uint32_t)__cvta_generic_to_shared(pb + rrow * BPITCH + rcol);
                asm volatile("ldmatrix.sync.aligned.m8n8.x4.trans.shared.b16 {%0,%1,%2,%3}, [%4];"
                             : "=r"(br[n2][0]), "=r"(br[n2][1]), "=r"(br[n2][2]), "=r"(br[n2][3])
                             : "r"(addr));
            }
#pragma unroll
            for (int mi = 0; mi < 4; mi++)
#pragma unroll
                for (int ni = 0; ni < 4; ni++) {
                    uint32_t b0 = br[ni >> 1][(ni & 1) * 2];
                    uint32_t b1 = br[ni >> 1][(ni & 1) * 2 + 1];
                    asm volatile(
                        "mma.sync.aligned.m16n8k16.row.col.f32.bf16.bf16.f32 "
                        "{%0,%1,%2,%3}, {%4,%5,%6,%7}, {%8,%9}, {%0,%1,%2,%3};"
                        : "+f"(acc[mi][ni][0]), "+f"(acc[mi][ni][1]),
                          "+f"(acc[mi][ni][2]), "+f"(acc[mi][ni][3])
                        : "r"(ar[mi][0]), "r"(ar[mi][1]), "r"(ar[mi][2]), "r"(ar[mi][3]),
                          "r"(b0), "r"(b1));
                }
        }
        __syncthreads();
    }
    if (OUT == 0) {
        float* Cb = (float*)C + (size_t)(by * BM + wm) * N + bx * BN + wn;
#pragma unroll
        for (int mi = 0; mi < 4; mi++)
#pragma unroll
            for (int ni = 0; ni < 4; ni++) {
                int r0 = mi * 16 + (lane >> 2);
                int c0 = ni * 8 + (lane & 3) * 2;
                *(float2*)(Cb + (size_t)r0 * N + c0)       = make_float2(acc[mi][ni][0], acc[mi][ni][1]);
                *(float2*)(Cb + (size_t)(r0 + 8) * N + c0) = make_float2(acc[mi][ni][2], acc[mi][ni][3]);
            }
    } else {
        bf16* Cb = (bf16*)C + (size_t)(by * BM + wm) * N + bx * BN + wn;
#pragma unroll
        for (int mi = 0; mi < 4; mi++)
#pragma unroll
            for (int ni = 0; ni < 4; ni++) {
                int r0 = mi * 16 + (lane >> 2);
                int c0 = ni * 8 + (lane & 3) * 2;
                __nv_bfloat162 v0 = __floats2bfloat162_rn(acc[mi][ni][0], acc[mi][ni][1]);
                __nv_bfloat162 v1 = __floats2bfloat162_rn(acc[mi][ni][2], acc[mi][ni][3]);
                *(__nv_bfloat162*)(Cb + (size_t)r0 * N + c0)       = v0;
                *(__nv_bfloat162*)(Cb + (size_t)(r0 + 8) * N + c0) = v1;
            }
    }
}

// ---------------- fused split-K reduce + layer-2 attention dots ----------------
// block = one node n; 160 threads = 5 warps; warp h handles head h (128 channels).
__global__ void k_red_dots2(const float* __restrict__ att_src, const float* __restrict__ att_dst) {
    int n = blockIdx.x;
    int t = threadIdx.x, lane = t & 31, h = t >> 5;
    const float4* p0 = (const float4*)g_P0 + (size_t)n * (F2 / 4);
    const float4* p1 = (const float4*)g_P1 + (size_t)n * (F2 / 4);
    float4* h2 = (float4*)g_H2 + (size_t)n * (F2 / 4);

    float4 a = p0[t], b = p1[t];
    float4 v = make_float4(a.x + b.x, a.y + b.y, a.z + b.z, a.w + b.w);
    h2[t] = v;

    int c0 = lane * 4;     // channel within head
    const float* as = att_src + h * OUT_FEAT + c0;
    const float* ad = att_dst + h * OUT_FEAT + c0;
    float sa = v.x * as[0] + v.y * as[1] + v.z * as[2] + v.w * as[3];
    float sd = v.x * ad[0] + v.y * ad[1] + v.z * ad[2] + v.w * ad[3];
#pragma unroll
    for (int o = 16; o > 0; o >>= 1) {
        sa += __shfl_xor_sync(0xffffffffu, sa, o);
        sd += __shfl_xor_sync(0xffffffffu, sd, o);
    }
    if (lane == 0) {
        g_A2s[n * OUT_HEAD + h] = sa;
        g_A2d[n * OUT_HEAD + h] = sd;
    }
}

// ---------------- Layer-1 attention dots ----------------
__global__ void k_dots1(const float* __restrict__ att_src, const float* __restrict__ att_dst) {
    int warp = (blockIdx.x * blockDim.x + threadIdx.x) >> 5;
    int lane = threadIdx.x & 31;
    int n = warp >> 6, h = warp & 63;
    const bf16* row = g_H1b + (size_t)n * F1 + h * HID;
    float v1 = __bfloat162float(row[lane]), v2 = __bfloat162float(row[lane + 32]);
    float sa = v1 * att_src[h * HID + lane] + v2 * att_src[h * HID + lane + 32];
    float sd = v1 * att_dst[h * HID + lane] + v2 * att_dst[h * HID + lane + 32];
#pragma unroll
    for (int o = 16; o > 0; o >>= 1) {
        sa += __shfl_xor_sync(0xffffffffu, sa, o);
        sd += __shfl_xor_sync(0xffffffffu, sd, o);
    }
    if (lane == 0) {
        g_A1s[n * IN_HEAD + h] = sa;
        g_A1d[n * IN_HEAD + h] = sd;
    }
}

__device__ __forceinline__ float leaky(float x) { return x > 0.f ? x : NEG_SLOPE * x; }

// ---------------- Layer-1 softmax + aggregation + bias + elu -> bf16 hi ----------------
__global__ void k_agg1(const float* __restrict__ b1) {
    int n = blockIdx.x;
    int t = threadIdx.x;
    int h = t & 63, slot = t >> 6;
    int beg = g_offs[n], end = g_offs[n + 1];
    float adst = g_A1d[n * IN_HEAD + h];

    __shared__ float red[4][64];
    __shared__ float sm_m[64], sm_inv[64];
    __shared__ int   srcb[32];
    __shared__ float alpha[32][64];

    float mx = -1e30f;
    for (int j = beg + slot; j < end; j += 4) {
        int s = g_esrc[j];
        mx = fmaxf(mx, leaky(g_A1s[s * IN_HEAD + h] + adst));
    }
    red[slot][h] = mx;
    __syncthreads();
    if (slot == 0) {
        sm_m[h] = fmaxf(fmaxf(red[0][h], red[1][h]), fmaxf(red[2][h], red[3][h]));
    }
    __syncthreads();
    float M = sm_m[h];

    float sum = 0.f;
    for (int j = beg + slot; j < end; j += 4) {
        int s = g_esrc[j];
        sum += expf(leaky(g_A1s[s * IN_HEAD + h] + adst) - M);
    }
    red[slot][h] = sum;
    __syncthreads();
    if (slot == 0) {
        float d = red[0][h] + red[1][h] + red[2][h] + red[3][h];
        sm_inv[h] = 1.0f / (d + GAT_EPS);
    }
    __syncthreads();
    float INV = sm_inv[h];

    int c = t & 63, g = t >> 6;
    float acc[16];
#pragma unroll
    for (int k = 0; k < 16; k++) acc[k] = 0.f;

    for (int jb = beg; jb < end; jb += 32) {
        int cnt = min(32, end - jb);
        if (t < cnt) srcb[t] = g_esrc[jb + t];
        __syncthreads();
        for (int j = slot; j < cnt; j += 4) {
            int s = srcb[j];
            float e = leaky(g_A1s[s * IN_HEAD + h] + adst);
            alpha[j][h] = expf(e - M) * INV;
        }
        __syncthreads();
        for (int j = 0; j < cnt; j++) {
            const bf16* row = g_H1b + (size_t)srcb[j] * F1;
#pragma unroll
            for (int k = 0; k < 16; k++) {
                int hh = g * 16 + k;
                acc[k] += alpha[j][hh] * __bfloat162float(row[hh * HID + c]);
            }
        }
        __syncthreads();
    }
    bf16* rowo = g_H1ae + (size_t)n * F1;
#pragma unroll
    for (int k = 0; k < 16; k++) {
        int idx = (g * 16 + k) * HID + c;
        float v = acc[k] + b1[idx];
        v = v > 0.f ? v : expm1f(v);   // elu
        rowo[idx] = __float2bfloat16(v);
    }
}

// ---------------- Layer-2 softmax + aggregation + head-mean + bias ----------------
__global__ void k_agg2(const float* __restrict__ b2) {
    int n = blockIdx.x;
    int t = threadIdx.x;
    int beg = g_offs[n], end = g_offs[n + 1];

    __shared__ float sm_m[OUT_HEAD], sm_inv[OUT_HEAD];
    __shared__ int   srcb[16];
    __shared__ float alpha[16][OUT_HEAD];

    if (t < OUT_HEAD) {
        float adst = g_A2d[n * OUT_HEAD + t];
        float mx = -1e30f;
        for (int j = beg; j < end; j++)
            mx = fmaxf(mx, leaky(g_A2s[g_esrc[j] * OUT_HEAD + t] + adst));
        float sum = 0.f;
        for (int j = beg; j < end; j++)
            sum += expf(leaky(g_A2s[g_esrc[j] * OUT_HEAD + t] + adst) - mx);
        sm_m[t] = mx;
        sm_inv[t] = 1.0f / (sum + GAT_EPS);
    }
    __syncthreads();

    float acc[OUT_HEAD] = {0.f, 0.f, 0.f, 0.f, 0.f};
    for (int jb = beg; jb < end; jb += 16) {
        int cnt = min(16, end - jb);
        if (t < cnt) srcb[t] = g_esrc[jb + t];
        __syncthreads();
        if (t < cnt * OUT_HEAD) {
            int j = t / OUT_HEAD, hh = t % OUT_HEAD;
            int s = srcb[j];
            float e = leaky(g_A2s[s * OUT_HEAD + hh] + g_A2d[n * OUT_HEAD + hh]);
            alpha[j][hh] = expf(e - sm_m[hh]) * sm_inv[hh];
        }
        __syncthreads();
        for (int j = 0; j < cnt; j++) {
            const float* row = g_H2 + (size_t)srcb[j] * F2;
#pragma unroll
            for (int hh = 0; hh < OUT_HEAD; hh++)
                acc[hh] += alpha[j][hh] * row[hh * OUT_FEAT + t];
        }
        __syncthreads();
    }
    float o = (acc[0] + acc[1] + acc[2] + acc[3] + acc[4]) * 0.2f + b2[t];
    g_H2o[(size_t)n * OUT_FEAT + t] = o;
}

// ---------------- Final node-mean + tanh ----------------
__global__ void k_part() {
    int b = blockIdx.x, c = threadIdx.x;
    float s = 0.f;
    for (int i = 0; i < N_NODES / 32; i++)
        s += g_H2o[(size_t)(b * (N_NODES / 32) + i) * OUT_FEAT + c];
    g_part[b * OUT_FEAT + c] = s;
}

__global__ void k_final(float* __restrict__ out) {
    int c = threadIdx.x;
    float s = 0.f;
#pragma unroll
    for (int b = 0; b < 32; b++) s += g_part[b * OUT_FEAT + c];
    out[c] = tanhf(s / (float)N_NODES);
}

// ---------------- Launch ----------------
extern "C" void kernel_launch(void* const* d_in, const int* in_sizes, int n_in,
                              void* d_out, int out_size) {
    const float* x        = (const float*)d_in[0];
    const void*  ei       = d_in[1];
    const float* W1       = (const float*)d_in[2];
    const float* att_src1 = (const float*)d_in[3];
    const float* att_dst1 = (const float*)d_in[4];
    const float* b1       = (const float*)d_in[5];
    const float* W2       = (const float*)d_in[6];
    const float* att_src2 = (const float*)d_in[7];
    const float* att_dst2 = (const float*)d_in[8];
    const float* b2       = (const float*)d_in[9];
    float* out = (float*)d_out;

    static bf16*  s_H1b  = nullptr;
    static float* s_P0   = nullptr;
    static float* s_P1   = nullptr;
    static bf16*  s_xe   = nullptr;
    static bf16*  s_W1e  = nullptr;
    static bf16*  s_H1ae = nullptr;
    static bf16*  s_W2e  = nullptr;
    static cudaStream_t s2 = nullptr;
    static cudaEvent_t  evFork = nullptr, evJoin = nullptr;
    static bool   s_init = false;
    if (!s_init) {
        cudaGetSymbolAddress((void**)&s_H1b,  g_H1b);
        cudaGetSymbolAddress((void**)&s_P0,   g_P0);
        cudaGetSymbolAddress((void**)&s_P1,   g_P1);
        cudaGetSymbolAddress((void**)&s_xe,   g_xe);
        cudaGetSymbolAddress((void**)&s_W1e,  g_W1e);
        cudaGetSymbolAddress((void**)&s_H1ae, g_H1ae);
        cudaGetSymbolAddress((void**)&s_W2e,  g_W2e);
        cudaFuncSetAttribute(hgemm<0>, cudaFuncAttributeMaxDynamicSharedMemorySize, HG_SMEM);
        cudaFuncSetAttribute(hgemm<1>, cudaFuncAttributeMaxDynamicSharedMemorySize, HG_SMEM);
        cudaStreamCreateWithFlags(&s2, cudaStreamNonBlocking);
        cudaEventCreateWithFlags(&evFork, cudaEventDisableTiming);
        cudaEventCreateWithFlags(&evJoin, cudaEventDisableTiming);
        s_init = true;
    }

    // ---- fork: CSR chain + W2 split on s2, concurrent with GEMM1 path ----
    cudaEventRecord(evFork, 0);
    cudaStreamWaitEvent(s2, evFork, 0);

    k_init    <<<(N_NODES + 256) / 256, 256, 0, s2>>>((const int*)ei);
    k_count   <<<(E2 + 255) / 256, 256, 0, s2>>>(ei);
    k_scan    <<<1, 1024, 0, s2>>>();
    k_scatter <<<(E2 + 255) / 256, 256, 0, s2>>>(ei);
    k_split_W2<<<(F1 * F2 + 255) / 256, 256, 0, s2>>>(W2);
    cudaEventRecord(evJoin, s2);

    // ---- main stream: GEMM1 path ----
    k_split_x <<<(N_NODES * IN_FEAT) / 256, 256>>>(x);
    k_split_W1<<<(IN_FEAT * F1) / 256, 256>>>(W1);

    // GEMM1: H1b = x_hi @ [W1_hi;W1_lo]  (= x_hi @ W1), bf16 out, A col = k & 255
    hgemm<1><<<dim3(F1 / BN, N_NODES / BM, 1), 256, HG_SMEM>>>(
        s_xe, s_W1e, s_H1b, s_H1b, F1, IN_FEAT, IN_FEAT - 1, K1E);

    k_dots1<<<(N_NODES * IN_HEAD) / 8, 256>>>(att_src1, att_dst1);

    // ---- join: agg1 needs CSR; GEMM2 needs W2e ----
    cudaStreamWaitEvent(0, evJoin, 0);

    k_agg1<<<N_NODES, 256>>>(b1);

    // GEMM2: H2 = H1a_hi @ [W2_hi;W2_lo], fused split-K=2, A col = k & 4095
    hgemm<0><<<dim3(F2 / BN, N_NODES / BM, 2), 256, HG_SMEM>>>(
        s_H1ae, s_W2e, s_P0, s_P1, F2, F1, F1 - 1, K2E / 2);

    // fused: H2 = P0 + P1 and layer-2 attention dots
    k_red_dots2<<<N_NODES, 160>>>(att_src2, att_dst2);

    k_agg2<<<N_NODES, 128>>>(b2);

    k_part<<<32, 128>>>();
    k_final<<<1, 128>>>(out);
}

// round 10
// speedup vs baseline: 4.1477x; 1.4255x over previous
#include <cuda_runtime.h>
#include <cuda_fp16.h>
#include <stdint.h>
#include <math.h>

typedef __half f16;

// ---------------- Problem constants ----------------
#define N_NODES 4096
#define N_EDGES 32768
#define E2      (N_EDGES + N_NODES)   // with self loops = 36864
#define IN_FEAT 256
#define HID     64
#define IN_HEAD 64
#define OUT_FEAT 128
#define OUT_HEAD 5
#define F1      (IN_HEAD * HID)       // 4096
#define F2      (OUT_HEAD * OUT_FEAT) // 640
#define NEG_SLOPE 0.2f
#define GAT_EPS 1e-16f

// ---------------- Device scratch ----------------
__device__ int   g_is64;
__device__ int   g_counts[N_NODES + 1];
__device__ int   g_offs[N_NODES + 1];
__device__ int   g_cursor[N_NODES];
__device__ int   g_esrc[E2];
__device__ f16   g_H1h[(size_t)N_NODES * F1];     // x @ W1 in fp16 (32 MB)
__device__ float g_A1s[(size_t)N_NODES * IN_HEAD];
__device__ float g_A1d[(size_t)N_NODES * IN_HEAD];
__device__ float g_H2 [(size_t)N_NODES * F2];     // H1a @ W2 (fp32, 10 MB)
__device__ float g_P0 [(size_t)N_NODES * F2];     // split-K partial 0
__device__ float g_P1 [(size_t)N_NODES * F2];     // split-K partial 1
__device__ float g_A2s[(size_t)N_NODES * OUT_HEAD];
__device__ float g_A2d[(size_t)N_NODES * OUT_HEAD];
__device__ float g_H2o[(size_t)N_NODES * OUT_FEAT];
__device__ float g_part[32 * OUT_FEAT];

// fp16 operands (single-term; fp16 ulp 2^-11 is 4x tighter than bf16)
__device__ f16   g_xh  [(size_t)N_NODES * IN_FEAT]; // 2 MB
__device__ f16   g_W1h [(size_t)IN_FEAT * F1];      // 2 MB
__device__ f16   g_H1ae[(size_t)N_NODES * F1];      // 32 MB (elu(agg1+b1) fp16)
__device__ f16   g_W2h [(size_t)F1 * F2];           // 5.2 MB

// ---------------- init: zero counts + int64/int32 detect ----------------
__global__ void k_init(const int* ei32) {
    int i = blockIdx.x * blockDim.x + threadIdx.x;
    if (i <= N_NODES) g_counts[i] = 0;
    if (blockIdx.x == 0 && threadIdx.x < 32) {
        int v = ei32[2 * threadIdx.x + 1];
        unsigned any = __ballot_sync(0xffffffffu, v != 0);
        if (threadIdx.x == 0) g_is64 = (any == 0) ? 1 : 0;
    }
}

__device__ __forceinline__ int load_ei(const void* ei, int idx) {
    if (g_is64) return (int)((const long long*)ei)[idx];
    return ((const int*)ei)[idx];
}

// ---------------- CSR build ----------------
__global__ void k_count(const void* ei) {
    int i = blockIdx.x * blockDim.x + threadIdx.x;
    if (i >= E2) return;
    int dst = (i < N_EDGES) ? load_ei(ei, N_EDGES + i) : (i - N_EDGES);
    atomicAdd(&g_counts[dst], 1);
}

__global__ void k_scan() {   // 1 block, 1024 threads; scan 4096 counts
    __shared__ int buf[2][1024];
    int t = threadIdx.x;
    int c0 = g_counts[4 * t], c1 = g_counts[4 * t + 1];
    int c2 = g_counts[4 * t + 2], c3 = g_counts[4 * t + 3];
    int s = c0 + c1 + c2 + c3;
    buf[0][t] = s;
    __syncthreads();
    int pin = 0;
    for (int off = 1; off < 1024; off <<= 1) {
        int v = buf[pin][t];
        if (t >= off) v += buf[pin][t - off];
        buf[pin ^ 1][t] = v;
        pin ^= 1;
        __syncthreads();
    }
    int incl = buf[pin][t];
    int base = incl - s;
    g_offs[4 * t]     = base;
    g_offs[4 * t + 1] = base + c0;
    g_offs[4 * t + 2] = base + c0 + c1;
    g_offs[4 * t + 3] = base + c0 + c1 + c2;
    g_cursor[4 * t]     = base;
    g_cursor[4 * t + 1] = base + c0;
    g_cursor[4 * t + 2] = base + c0 + c1;
    g_cursor[4 * t + 3] = base + c0 + c1 + c2;
    if (t == 1023) g_offs[N_NODES] = incl;
}

__global__ void k_scatter(const void* ei) {
    int i = blockIdx.x * blockDim.x + threadIdx.x;
    if (i >= E2) return;
    int src, dst;
    if (i < N_EDGES) { src = load_ei(ei, i); dst = load_ei(ei, N_EDGES + i); }
    else             { src = i - N_EDGES;    dst = i - N_EDGES; }
    int pos = atomicAdd(&g_cursor[dst], 1);
    g_esrc[pos] = src;
}

// ---------------- fp16 convert kernels (vectorized) ----------------
__global__ void k_cvt_x(const float* __restrict__ x) {     // 1M elems, float4 -> half2x2
    int i = blockIdx.x * blockDim.x + threadIdx.x;         // over float4
    float4 v = ((const float4*)x)[i];
    __half2* o = (__half2*)g_xh;
    o[2 * i]     = __floats2half2_rn(v.x, v.y);
    o[2 * i + 1] = __floats2half2_rn(v.z, v.w);
}

__global__ void k_cvt_W1(const float* __restrict__ W) {    // 1M elems
    int i = blockIdx.x * blockDim.x + threadIdx.x;
    float4 v = ((const float4*)W)[i];
    __half2* o = (__half2*)g_W1h;
    o[2 * i]     = __floats2half2_rn(v.x, v.y);
    o[2 * i + 1] = __floats2half2_rn(v.z, v.w);
}

__global__ void k_cvt_W2(const float* __restrict__ W) {    // 2.62M elems
    int i = blockIdx.x * blockDim.x + threadIdx.x;
    if (i >= (F1 * F2) / 4) return;
    float4 v = ((const float4*)W)[i];
    __half2* o = (__half2*)g_W2h;
    o[2 * i]     = __floats2half2_rn(v.x, v.y);
    o[2 * i + 1] = __floats2half2_rn(v.z, v.w);
}

// ---------------- fp16 tensor-core GEMM (mma.sync, 3-stage cp.async) ----------------
// C[M,N] = A[M, kOff:kOff+kLen] * B[kOff:kOff+kLen, N].  A/B fp16 row-major.
// blockIdx.z selects split-K segment (kOff = z*kLen, C = z ? C1 : C0).
// OUT=0: C fp32; OUT=1: C fp16.
// BM=128, BN=128, BK=32, 3 stages, 256 threads (8 warps 2x4, warp tile 64x32).
#define BM 128
#define BN 128
#define BK 32
#define STG 3
#define APITCH (BK + 8)
#define BPITCH (BN + 8)
#define HG_SMEM (STG * (BM * APITCH + BK * BPITCH) * 2)

template <int OUT>
__global__ __launch_bounds__(256, 2)
void hgemm(const f16* __restrict__ A, const f16* __restrict__ B,
           void* __restrict__ C0, void* __restrict__ C1,
           int N, int aStride, int kLen) {
    extern __shared__ f16 smbuf[];
    f16* sA = smbuf;                          // [STG][BM][APITCH]
    f16* sB = smbuf + STG * BM * APITCH;      // [STG][BK][BPITCH]
    int t = threadIdx.x, lane = t & 31, warp = t >> 5;
    int wm = (warp >> 2) * 64;   // 0 or 64
    int wn = (warp & 3) * 32;    // 0,32,64,96
    int bx = blockIdx.x, by = blockIdx.y, bz = blockIdx.z;
    int kOff = bz * kLen;
    void* C = bz ? C1 : C0;
    const f16* Ab = A + (size_t)(by * BM) * aStride + kOff;
    const f16* Bb = B + (size_t)kOff * N + bx * BN;

    int a_row = t >> 2;          // 0..63 (+64)
    int a_col = (t & 3) * 8;
    int b_row = t >> 4;          // 0..15 (+16)
    int b_col = (t & 15) * 8;

    float acc[4][4][4];
#pragma unroll
    for (int i = 0; i < 4; i++)
#pragma unroll
        for (int j = 0; j < 4; j++)
#pragma unroll
            for (int r = 0; r < 4; r++) acc[i][j][r] = 0.f;

    auto issue = [&](int j) {
        int buf = j % STG;
        int k0 = j * BK;
        f16* pa = sA + buf * BM * APITCH;
        f16* pb = sB + buf * BK * BPITCH;
        uint32_t da0 = (uint32_t)__cvta_generic_to_shared(pa + a_row * APITCH + a_col);
        uint32_t da1 = (uint32_t)__cvta_generic_to_shared(pa + (a_row + 64) * APITCH + a_col);
        const f16* ga0 = Ab + (size_t)a_row * aStride + k0 + a_col;
        const f16* ga1 = Ab + (size_t)(a_row + 64) * aStride + k0 + a_col;
        asm volatile("cp.async.cg.shared.global [%0], [%1], 16;" :: "r"(da0), "l"(ga0));
        asm volatile("cp.async.cg.shared.global [%0], [%1], 16;" :: "r"(da1), "l"(ga1));
        uint32_t db0 = (uint32_t)__cvta_generic_to_shared(pb + b_row * BPITCH + b_col);
        uint32_t db1 = (uint32_t)__cvta_generic_to_shared(pb + (b_row + 16) * BPITCH + b_col);
        const f16* gb0 = Bb + (size_t)(k0 + b_row) * N + b_col;
        const f16* gb1 = Bb + (size_t)(k0 + b_row + 16) * N + b_col;
        asm volatile("cp.async.cg.shared.global [%0], [%1], 16;" :: "r"(db0), "l"(gb0));
        asm volatile("cp.async.cg.shared.global [%0], [%1], 16;" :: "r"(db1), "l"(gb1));
        asm volatile("cp.async.commit_group;");
    };

    int nc = kLen / BK;
    issue(0);
    if (nc > 1) issue(1);
    for (int s = 0; s < nc; s++) {
        if (s < nc - 1) { asm volatile("cp.async.wait_group 1;"); }
        else            { asm volatile("cp.async.wait_group 0;"); }
        __syncthreads();
        if (s + 2 < nc) issue(s + 2);
        int buf = s % STG;
        f16* pa = sA + buf * BM * APITCH;
        f16* pb = sB + buf * BK * BPITCH;
#pragma unroll
        for (int kk = 0; kk < 2; kk++) {
            int k = kk * 16;
            uint32_t ar[4][4], br[2][4];
#pragma unroll
            for (int mi = 0; mi < 4; mi++) {
                int row = wm + mi * 16 + (lane & 7) + ((lane >> 3) & 1) * 8;
                int col = k + (lane >> 4) * 8;
                uint32_t addr = (uint32_t)__cvta_generic_to_shared(pa + row * APITCH + col);
                asm volatile("ldmatrix.sync.aligned.m8n8.x4.shared.b16 {%0,%1,%2,%3}, [%4];"
                             : "=r"(ar[mi][0]), "=r"(ar[mi][1]), "=r"(ar[mi][2]), "=r"(ar[mi][3])
                             : "r"(addr));
            }
#pragma unroll
            for (int n2 = 0; n2 < 2; n2++) {
                int rrow = k + (lane & 7) + ((lane >> 3) & 1) * 8;
                int rcol = wn + n2 * 16 + (lane >> 4) * 8;
                uint32_t addr = (uint32_t)__cvta_generic_to_shared(pb + rrow * BPITCH + rcol);
                asm volatile("ldmatrix.sync.aligned.m8n8.x4.trans.shared.b16 {%0,%1,%2,%3}, [%4];"
                             : "=r"(br[n2][0]), "=r"(br[n2][1]), "=r"(br[n2][2]), "=r"(br[n2][3])
                             : "r"(addr));
            }
#pragma unroll
            for (int mi = 0; mi < 4; mi++)
#pragma unroll
                for (int ni = 0; ni < 4; ni++) {
                    uint32_t b0 = br[ni >> 1][(ni & 1) * 2];
                    uint32_t b1 = br[ni >> 1][(ni & 1) * 2 + 1];
                    asm volatile(
                        "mma.sync.aligned.m16n8k16.row.col.f32.f16.f16.f32 "
                        "{%0,%1,%2,%3}, {%4,%5,%6,%7}, {%8,%9}, {%0,%1,%2,%3};"
                        : "+f"(acc[mi][ni][0]), "+f"(acc[mi][ni][1]),
                          "+f"(acc[mi][ni][2]), "+f"(acc[mi][ni][3])
                        : "r"(ar[mi][0]), "r"(ar[mi][1]), "r"(ar[mi][2]), "r"(ar[mi][3]),
                          "r"(b0), "r"(b1));
                }
        }
        __syncthreads();
    }
    if (OUT == 0) {
        float* Cb = (float*)C + (size_t)(by * BM + wm) * N + bx * BN + wn;
#pragma unroll
        for (int mi = 0; mi < 4; mi++)
#pragma unroll
            for (int ni = 0; ni < 4; ni++) {
                int r0 = mi * 16 + (lane >> 2);
                int c0 = ni * 8 + (lane & 3) * 2;
                *(float2*)(Cb + (size_t)r0 * N + c0)       = make_float2(acc[mi][ni][0], acc[mi][ni][1]);
                *(float2*)(Cb + (size_t)(r0 + 8) * N + c0) = make_float2(acc[mi][ni][2], acc[mi][ni][3]);
            }
    } else {
        f16* Cb = (f16*)C + (size_t)(by * BM + wm) * N + bx * BN + wn;
#pragma unroll
        for (int mi = 0; mi < 4; mi++)
#pragma unroll
            for (int ni = 0; ni < 4; ni++) {
                int r0 = mi * 16 + (lane >> 2);
                int c0 = ni * 8 + (lane & 3) * 2;
                *(__half2*)(Cb + (size_t)r0 * N + c0)       = __floats2half2_rn(acc[mi][ni][0], acc[mi][ni][1]);
                *(__half2*)(Cb + (size_t)(r0 + 8) * N + c0) = __floats2half2_rn(acc[mi][ni][2], acc[mi][ni][3]);
            }
    }
}

// ---------------- fused split-K reduce + layer-2 attention dots ----------------
// block = one node n; 160 threads = 5 warps; warp h handles head h (128 channels).
__global__ void k_red_dots2(const float* __restrict__ att_src, const float* __restrict__ att_dst) {
    int n = blockIdx.x;
    int t = threadIdx.x, lane = t & 31, h = t >> 5;
    const float4* p0 = (const float4*)g_P0 + (size_t)n * (F2 / 4);
    const float4* p1 = (const float4*)g_P1 + (size_t)n * (F2 / 4);
    float4* h2 = (float4*)g_H2 + (size_t)n * (F2 / 4);

    float4 a = p0[t], b = p1[t];
    float4 v = make_float4(a.x + b.x, a.y + b.y, a.z + b.z, a.w + b.w);
    h2[t] = v;

    int c0 = lane * 4;     // channel within head
    const float* as = att_src + h * OUT_FEAT + c0;
    const float* ad = att_dst + h * OUT_FEAT + c0;
    float sa = v.x * as[0] + v.y * as[1] + v.z * as[2] + v.w * as[3];
    float sd = v.x * ad[0] + v.y * ad[1] + v.z * ad[2] + v.w * ad[3];
#pragma unroll
    for (int o = 16; o > 0; o >>= 1) {
        sa += __shfl_xor_sync(0xffffffffu, sa, o);
        sd += __shfl_xor_sync(0xffffffffu, sd, o);
    }
    if (lane == 0) {
        g_A2s[n * OUT_HEAD + h] = sa;
        g_A2d[n * OUT_HEAD + h] = sd;
    }
}

// ---------------- Layer-1 attention dots ----------------
__global__ void k_dots1(const float* __restrict__ att_src, const float* __restrict__ att_dst) {
    int warp = (blockIdx.x * blockDim.x + threadIdx.x) >> 5;
    int lane = threadIdx.x & 31;
    int n = warp >> 6, h = warp & 63;
    const f16* row = g_H1h + (size_t)n * F1 + h * HID;
    float v1 = __half2float(row[lane]), v2 = __half2float(row[lane + 32]);
    float sa = v1 * att_src[h * HID + lane] + v2 * att_src[h * HID + lane + 32];
    float sd = v1 * att_dst[h * HID + lane] + v2 * att_dst[h * HID + lane + 32];
#pragma unroll
    for (int o = 16; o > 0; o >>= 1) {
        sa += __shfl_xor_sync(0xffffffffu, sa, o);
        sd += __shfl_xor_sync(0xffffffffu, sd, o);
    }
    if (lane == 0) {
        g_A1s[n * IN_HEAD + h] = sa;
        g_A1d[n * IN_HEAD + h] = sd;
    }
}

__device__ __forceinline__ float leaky(float x) { return x > 0.f ? x : NEG_SLOPE * x; }

// ---------------- Layer-1 softmax + aggregation + bias + elu -> fp16 ----------------
__global__ void k_agg1(const float* __restrict__ b1) {
    int n = blockIdx.x;
    int t = threadIdx.x;
    int h = t & 63, slot = t >> 6;
    int beg = g_offs[n], end = g_offs[n + 1];
    float adst = g_A1d[n * IN_HEAD + h];

    __shared__ float red[4][64];
    __shared__ float sm_m[64], sm_inv[64];
    __shared__ int   srcb[32];
    __shared__ float alpha[32][64];

    float mx = -1e30f;
    for (int j = beg + slot; j < end; j += 4) {
        int s = g_esrc[j];
        mx = fmaxf(mx, leaky(g_A1s[s * IN_HEAD + h] + adst));
    }
    red[slot][h] = mx;
    __syncthreads();
    if (slot == 0) {
        sm_m[h] = fmaxf(fmaxf(red[0][h], red[1][h]), fmaxf(red[2][h], red[3][h]));
    }
    __syncthreads();
    float M = sm_m[h];

    float sum = 0.f;
    for (int j = beg + slot; j < end; j += 4) {
        int s = g_esrc[j];
        sum += expf(leaky(g_A1s[s * IN_HEAD + h] + adst) - M);
    }
    red[slot][h] = sum;
    __syncthreads();
    if (slot == 0) {
        float d = red[0][h] + red[1][h] + red[2][h] + red[3][h];
        sm_inv[h] = 1.0f / (d + GAT_EPS);
    }
    __syncthreads();
    float INV = sm_inv[h];

    int c = t & 63, g = t >> 6;
    float acc[16];
#pragma unroll
    for (int k = 0; k < 16; k++) acc[k] = 0.f;

    for (int jb = beg; jb < end; jb += 32) {
        int cnt = min(32, end - jb);
        if (t < cnt) srcb[t] = g_esrc[jb + t];
        __syncthreads();
        for (int j = slot; j < cnt; j += 4) {
            int s = srcb[j];
            float e = leaky(g_A1s[s * IN_HEAD + h] + adst);
            alpha[j][h] = expf(e - M) * INV;
        }
        __syncthreads();
        for (int j = 0; j < cnt; j++) {
            const f16* row = g_H1h + (size_t)srcb[j] * F1;
#pragma unroll
            for (int k = 0; k < 16; k++) {
                int hh = g * 16 + k;
                acc[k] += alpha[j][hh] * __half2float(row[hh * HID + c]);
            }
        }
        __syncthreads();
    }
    f16* rowo = g_H1ae + (size_t)n * F1;
#pragma unroll
    for (int k = 0; k < 16; k++) {
        int idx = (g * 16 + k) * HID + c;
        float v = acc[k] + b1[idx];
        v = v > 0.f ? v : expm1f(v);   // elu
        rowo[idx] = __float2half(v);
    }
}

// ---------------- Layer-2 softmax + aggregation + head-mean + bias ----------------
__global__ void k_agg2(const float* __restrict__ b2) {
    int n = blockIdx.x;
    int t = threadIdx.x;
    int beg = g_offs[n], end = g_offs[n + 1];

    __shared__ float sm_m[OUT_HEAD], sm_inv[OUT_HEAD];
    __shared__ int   srcb[16];
    __shared__ float alpha[16][OUT_HEAD];

    if (t < OUT_HEAD) {
        float adst = g_A2d[n * OUT_HEAD + t];
        float mx = -1e30f;
        for (int j = beg; j < end; j++)
            mx = fmaxf(mx, leaky(g_A2s[g_esrc[j] * OUT_HEAD + t] + adst));
        float sum = 0.f;
        for (int j = beg; j < end; j++)
            sum += expf(leaky(g_A2s[g_esrc[j] * OUT_HEAD + t] + adst) - mx);
        sm_m[t] = mx;
        sm_inv[t] = 1.0f / (sum + GAT_EPS);
    }
    __syncthreads();

    float acc[OUT_HEAD] = {0.f, 0.f, 0.f, 0.f, 0.f};
    for (int jb = beg; jb < end; jb += 16) {
        int cnt = min(16, end - jb);
        if (t < cnt) srcb[t] = g_esrc[jb + t];
        __syncthreads();
        if (t < cnt * OUT_HEAD) {
            int j = t / OUT_HEAD, hh = t % OUT_HEAD;
            int s = srcb[j];
            float e = leaky(g_A2s[s * OUT_HEAD + hh] + g_A2d[n * OUT_HEAD + hh]);
            alpha[j][hh] = expf(e - sm_m[hh]) * sm_inv[hh];
        }
        __syncthreads();
        for (int j = 0; j < cnt; j++) {
            const float* row = g_H2 + (size_t)srcb[j] * F2;
#pragma unroll
            for (int hh = 0; hh < OUT_HEAD; hh++)
                acc[hh] += alpha[j][hh] * row[hh * OUT_FEAT + t];
        }
        __syncthreads();
    }
    float o = (acc[0] + acc[1] + acc[2] + acc[3] + acc[4]) * 0.2f + b2[t];
    g_H2o[(size_t)n * OUT_FEAT + t] = o;
}

// ---------------- Final node-mean + tanh ----------------
__global__ void k_part() {
    int b = blockIdx.x, c = threadIdx.x;
    float s = 0.f;
    for (int i = 0; i < N_NODES / 32; i++)
        s += g_H2o[(size_t)(b * (N_NODES / 32) + i) * OUT_FEAT + c];
    g_part[b * OUT_FEAT + c] = s;
}

__global__ void k_final(float* __restrict__ out) {
    int c = threadIdx.x;
    float s = 0.f;
#pragma unroll
    for (int b = 0; b < 32; b++) s += g_part[b * OUT_FEAT + c];
    out[c] = tanhf(s / (float)N_NODES);
}

// ---------------- Launch ----------------
extern "C" void kernel_launch(void* const* d_in, const int* in_sizes, int n_in,
                              void* d_out, int out_size) {
    const float* x        = (const float*)d_in[0];
    const void*  ei       = d_in[1];
    const float* W1       = (const float*)d_in[2];
    const float* att_src1 = (const float*)d_in[3];
    const float* att_dst1 = (const float*)d_in[4];
    const float* b1       = (const float*)d_in[5];
    const float* W2       = (const float*)d_in[6];
    const float* att_src2 = (const float*)d_in[7];
    const float* att_dst2 = (const float*)d_in[8];
    const float* b2       = (const float*)d_in[9];
    float* out = (float*)d_out;

    static f16*   s_H1h  = nullptr;
    static float* s_P0   = nullptr;
    static float* s_P1   = nullptr;
    static f16*   s_xh   = nullptr;
    static f16*   s_W1h  = nullptr;
    static f16*   s_H1ae = nullptr;
    static f16*   s_W2h  = nullptr;
    static cudaStream_t s2 = nullptr;
    static cudaEvent_t  evFork = nullptr, evJoin = nullptr;
    static bool   s_init = false;
    if (!s_init) {
        cudaGetSymbolAddress((void**)&s_H1h,  g_H1h);
        cudaGetSymbolAddress((void**)&s_P0,   g_P0);
        cudaGetSymbolAddress((void**)&s_P1,   g_P1);
        cudaGetSymbolAddress((void**)&s_xh,   g_xh);
        cudaGetSymbolAddress((void**)&s_W1h,  g_W1h);
        cudaGetSymbolAddress((void**)&s_H1ae, g_H1ae);
        cudaGetSymbolAddress((void**)&s_W2h,  g_W2h);
        cudaFuncSetAttribute(hgemm<0>, cudaFuncAttributeMaxDynamicSharedMemorySize, HG_SMEM);
        cudaFuncSetAttribute(hgemm<1>, cudaFuncAttributeMaxDynamicSharedMemorySize, HG_SMEM);
        cudaStreamCreateWithFlags(&s2, cudaStreamNonBlocking);
        cudaEventCreateWithFlags(&evFork, cudaEventDisableTiming);
        cudaEventCreateWithFlags(&evJoin, cudaEventDisableTiming);
        s_init = true;
    }

    // ---- fork: CSR chain + W2 convert on s2, concurrent with GEMM1 path ----
    cudaEventRecord(evFork, 0);
    cudaStreamWaitEvent(s2, evFork, 0);

    k_init   <<<(N_NODES + 256) / 256, 256, 0, s2>>>((const int*)ei);
    k_count  <<<(E2 + 255) / 256, 256, 0, s2>>>(ei);
    k_scan   <<<1, 1024, 0, s2>>>();
    k_scatter<<<(E2 + 255) / 256, 256, 0, s2>>>(ei);
    k_cvt_W2 <<<((F1 * F2 / 4) + 255) / 256, 256, 0, s2>>>(W2);
    cudaEventRecord(evJoin, s2);

    // ---- main stream: GEMM1 path ----
    k_cvt_x <<<(N_NODES * IN_FEAT / 4) / 256, 256>>>(x);
    k_cvt_W1<<<(IN_FEAT * F1 / 4) / 256, 256>>>(W1);

    // GEMM1: H1h = x_f16 @ W1_f16, K=256, fp16 out
    hgemm<1><<<dim3(F1 / BN, N_NODES / BM, 1), 256, HG_SMEM>>>(
        s_xh, s_W1h, s_H1h, s_H1h, F1, IN_FEAT, IN_FEAT);

    k_dots1<<<(N_NODES * IN_HEAD) / 8, 256>>>(att_src1, att_dst1);

    // ---- join: agg1 needs CSR; GEMM2 needs W2h ----
    cudaStreamWaitEvent(0, evJoin, 0);

    k_agg1<<<N_NODES, 256>>>(b1);

    // GEMM2: H2 = H1a_f16 @ W2_f16, K=4096, fused split-K=2 (kLen=2048)
    hgemm<0><<<dim3(F2 / BN, N_NODES / BM, 2), 256, HG_SMEM>>>(
        s_H1ae, s_W2h, s_P0, s_P1, F2, F1, F1 / 2);

    // fused: H2 = P0 + P1 and layer-2 attention dots
    k_red_dots2<<<N_NODES, 160>>>(att_src2, att_dst2);

    k_agg2<<<N_NODES, 128>>>(b2);

    k_part<<<32, 128>>>();
    k_final<<<1, 128>>>(out);
}

// round 11
// speedup vs baseline: 4.6264x; 1.1154x over previous
#include <cuda_runtime.h>
#include <cuda_fp16.h>
#include <stdint.h>
#include <math.h>

typedef __half f16;

// ---------------- Problem constants ----------------
#define N_NODES 4096
#define N_EDGES 32768
#define E2      (N_EDGES + N_NODES)   // with self loops = 36864
#define IN_FEAT 256
#define HID     64
#define IN_HEAD 64
#define OUT_FEAT 128
#define OUT_HEAD 5
#define F1      (IN_HEAD * HID)       // 4096
#define F2      (OUT_HEAD * OUT_FEAT) // 640
#define NEG_SLOPE 0.2f
#define GAT_EPS 1e-16f
#define KSPLIT  4

// ---------------- Device scratch ----------------
__device__ int   g_is64;
__device__ int   g_counts[N_NODES + 1];
__device__ int   g_offs[N_NODES + 1];
__device__ int   g_cursor[N_NODES];
__device__ int   g_esrc[E2];
__device__ f16   g_H1h[(size_t)N_NODES * F1];     // x @ W1 in fp16 (32 MB)
__device__ float g_A1s[(size_t)N_NODES * IN_HEAD];
__device__ float g_A1d[(size_t)N_NODES * IN_HEAD];
__device__ float g_Pk [(size_t)KSPLIT * N_NODES * F2];  // split-K partials (40 MB)
__device__ f16   g_H2h[(size_t)N_NODES * F2];     // H1a @ W2 in fp16 (5 MB)
__device__ float g_A2s[(size_t)N_NODES * OUT_HEAD];
__device__ float g_A2d[(size_t)N_NODES * OUT_HEAD];
__device__ float g_H2o[(size_t)N_NODES * OUT_FEAT];
__device__ float g_part[32 * OUT_FEAT];

// fp16 operands
__device__ f16   g_xh  [(size_t)N_NODES * IN_FEAT]; // 2 MB
__device__ f16   g_W1h [(size_t)IN_FEAT * F1];      // 2 MB
__device__ f16   g_H1ae[(size_t)N_NODES * F1];      // 32 MB (elu(agg1+b1) fp16)
__device__ f16   g_W2h [(size_t)F1 * F2];           // 5.2 MB

// ---------------- init: zero counts + int64/int32 detect ----------------
__global__ void k_init(const int* ei32) {
    int i = blockIdx.x * blockDim.x + threadIdx.x;
    if (i <= N_NODES) g_counts[i] = 0;
    if (blockIdx.x == 0 && threadIdx.x < 32) {
        int v = ei32[2 * threadIdx.x + 1];
        unsigned any = __ballot_sync(0xffffffffu, v != 0);
        if (threadIdx.x == 0) g_is64 = (any == 0) ? 1 : 0;
    }
}

__device__ __forceinline__ int load_ei(const void* ei, int idx) {
    if (g_is64) return (int)((const long long*)ei)[idx];
    return ((const int*)ei)[idx];
}

// ---------------- CSR build ----------------
__global__ void k_count(const void* ei) {
    int i = blockIdx.x * blockDim.x + threadIdx.x;
    if (i >= E2) return;
    int dst = (i < N_EDGES) ? load_ei(ei, N_EDGES + i) : (i - N_EDGES);
    atomicAdd(&g_counts[dst], 1);
}

__global__ void k_scan() {   // 1 block, 1024 threads; scan 4096 counts
    __shared__ int buf[2][1024];
    int t = threadIdx.x;
    int c0 = g_counts[4 * t], c1 = g_counts[4 * t + 1];
    int c2 = g_counts[4 * t + 2], c3 = g_counts[4 * t + 3];
    int s = c0 + c1 + c2 + c3;
    buf[0][t] = s;
    __syncthreads();
    int pin = 0;
    for (int off = 1; off < 1024; off <<= 1) {
        int v = buf[pin][t];
        if (t >= off) v += buf[pin][t - off];
        buf[pin ^ 1][t] = v;
        pin ^= 1;
        __syncthreads();
    }
    int incl = buf[pin][t];
    int base = incl - s;
    g_offs[4 * t]     = base;
    g_offs[4 * t + 1] = base + c0;
    g_offs[4 * t + 2] = base + c0 + c1;
    g_offs[4 * t + 3] = base + c0 + c1 + c2;
    g_cursor[4 * t]     = base;
    g_cursor[4 * t + 1] = base + c0;
    g_cursor[4 * t + 2] = base + c0 + c1;
    g_cursor[4 * t + 3] = base + c0 + c1 + c2;
    if (t == 1023) g_offs[N_NODES] = incl;
}

__global__ void k_scatter(const void* ei) {
    int i = blockIdx.x * blockDim.x + threadIdx.x;
    if (i >= E2) return;
    int src, dst;
    if (i < N_EDGES) { src = load_ei(ei, i); dst = load_ei(ei, N_EDGES + i); }
    else             { src = i - N_EDGES;    dst = i - N_EDGES; }
    int pos = atomicAdd(&g_cursor[dst], 1);
    g_esrc[pos] = src;
}

// ---------------- fp16 convert kernels (vectorized) ----------------
__global__ void k_cvt_x(const float* __restrict__ x) {
    int i = blockIdx.x * blockDim.x + threadIdx.x;
    float4 v = ((const float4*)x)[i];
    __half2* o = (__half2*)g_xh;
    o[2 * i]     = __floats2half2_rn(v.x, v.y);
    o[2 * i + 1] = __floats2half2_rn(v.z, v.w);
}

__global__ void k_cvt_W1(const float* __restrict__ W) {
    int i = blockIdx.x * blockDim.x + threadIdx.x;
    float4 v = ((const float4*)W)[i];
    __half2* o = (__half2*)g_W1h;
    o[2 * i]     = __floats2half2_rn(v.x, v.y);
    o[2 * i + 1] = __floats2half2_rn(v.z, v.w);
}

__global__ void k_cvt_W2(const float* __restrict__ W) {
    int i = blockIdx.x * blockDim.x + threadIdx.x;
    if (i >= (F1 * F2) / 4) return;
    float4 v = ((const float4*)W)[i];
    __half2* o = (__half2*)g_W2h;
    o[2 * i]     = __floats2half2_rn(v.x, v.y);
    o[2 * i + 1] = __floats2half2_rn(v.z, v.w);
}

// ---------------- fp16 tensor-core GEMM (mma.sync, 3-stage cp.async) ----------------
// C[M,N] = A[M, kOff:kOff+kLen] * B[kOff:kOff+kLen, N].  A/B fp16 row-major.
// blockIdx.z selects split-K segment: kOff = z*kLen, C = Cbase + z*cStride.
// OUT=0: C fp32; OUT=1: C fp16.
#define BM 128
#define BN 128
#define BK 32
#define STG 3
#define APITCH (BK + 8)
#define BPITCH (BN + 8)
#define HG_SMEM (STG * (BM * APITCH + BK * BPITCH) * 2)

template <int OUT>
__global__ __launch_bounds__(256, 2)
void hgemm(const f16* __restrict__ A, const f16* __restrict__ B,
           void* __restrict__ Cbase, size_t cStride,
           int N, int aStride, int kLen) {
    extern __shared__ f16 smbuf[];
    f16* sA = smbuf;                          // [STG][BM][APITCH]
    f16* sB = smbuf + STG * BM * APITCH;      // [STG][BK][BPITCH]
    int t = threadIdx.x, lane = t & 31, warp = t >> 5;
    int wm = (warp >> 2) * 64;   // 0 or 64
    int wn = (warp & 3) * 32;    // 0,32,64,96
    int bx = blockIdx.x, by = blockIdx.y, bz = blockIdx.z;
    int kOff = bz * kLen;
    const f16* Ab = A + (size_t)(by * BM) * aStride + kOff;
    const f16* Bb = B + (size_t)kOff * N + bx * BN;

    int a_row = t >> 2;          // 0..63 (+64)
    int a_col = (t & 3) * 8;
    int b_row = t >> 4;          // 0..15 (+16)
    int b_col = (t & 15) * 8;

    float acc[4][4][4];
#pragma unroll
    for (int i = 0; i < 4; i++)
#pragma unroll
        for (int j = 0; j < 4; j++)
#pragma unroll
            for (int r = 0; r < 4; r++) acc[i][j][r] = 0.f;

    auto issue = [&](int j) {
        int buf = j % STG;
        int k0 = j * BK;
        f16* pa = sA + buf * BM * APITCH;
        f16* pb = sB + buf * BK * BPITCH;
        uint32_t da0 = (uint32_t)__cvta_generic_to_shared(pa + a_row * APITCH + a_col);
        uint32_t da1 = (uint32_t)__cvta_generic_to_shared(pa + (a_row + 64) * APITCH + a_col);
        const f16* ga0 = Ab + (size_t)a_row * aStride + k0 + a_col;
        const f16* ga1 = Ab + (size_t)(a_row + 64) * aStride + k0 + a_col;
        asm volatile("cp.async.cg.shared.global [%0], [%1], 16;" :: "r"(da0), "l"(ga0));
        asm volatile("cp.async.cg.shared.global [%0], [%1], 16;" :: "r"(da1), "l"(ga1));
        uint32_t db0 = (uint32_t)__cvta_generic_to_shared(pb + b_row * BPITCH + b_col);
        uint32_t db1 = (uint32_t)__cvta_generic_to_shared(pb + (b_row + 16) * BPITCH + b_col);
        const f16* gb0 = Bb + (size_t)(k0 + b_row) * N + b_col;
        const f16* gb1 = Bb + (size_t)(k0 + b_row + 16) * N + b_col;
        asm volatile("cp.async.cg.shared.global [%0], [%1], 16;" :: "r"(db0), "l"(gb0));
        asm volatile("cp.async.cg.shared.global [%0], [%1], 16;" :: "r"(db1), "l"(gb1));
        asm volatile("cp.async.commit_group;");
    };

    int nc = kLen / BK;
    issue(0);
    if (nc > 1) issue(1);
    for (int s = 0; s < nc; s++) {
        if (s < nc - 1) { asm volatile("cp.async.wait_group 1;"); }
        else            { asm volatile("cp.async.wait_group 0;"); }
        __syncthreads();
        if (s + 2 < nc) issue(s + 2);
        int buf = s % STG;
        f16* pa = sA + buf * BM * APITCH;
        f16* pb = sB + buf * BK * BPITCH;
#pragma unroll
        for (int kk = 0; kk < 2; kk++) {
            int k = kk * 16;
            uint32_t ar[4][4], br[2][4];
#pragma unroll
            for (int mi = 0; mi < 4; mi++) {
                int row = wm + mi * 16 + (lane & 7) + ((lane >> 3) & 1) * 8;
                int col = k + (lane >> 4) * 8;
                uint32_t addr = (uint32_t)__cvta_generic_to_shared(pa + row * APITCH + col);
                asm volatile("ldmatrix.sync.aligned.m8n8.x4.shared.b16 {%0,%1,%2,%3}, [%4];"
                             : "=r"(ar[mi][0]), "=r"(ar[mi][1]), "=r"(ar[mi][2]), "=r"(ar[mi][3])
                             : "r"(addr));
            }
#pragma unroll
            for (int n2 = 0; n2 < 2; n2++) {
                int rrow = k + (lane & 7) + ((lane >> 3) & 1) * 8;
                int rcol = wn + n2 * 16 + (lane >> 4) * 8;
                uint32_t addr = (uint32_t)__cvta_generic_to_shared(pb + rrow * BPITCH + rcol);
                asm volatile("ldmatrix.sync.aligned.m8n8.x4.trans.shared.b16 {%0,%1,%2,%3}, [%4];"
                             : "=r"(br[n2][0]), "=r"(br[n2][1]), "=r"(br[n2][2]), "=r"(br[n2][3])
                             : "r"(addr));
            }
#pragma unroll
            for (int mi = 0; mi < 4; mi++)
#pragma unroll
                for (int ni = 0; ni < 4; ni++) {
                    uint32_t b0 = br[ni >> 1][(ni & 1) * 2];
                    uint32_t b1 = br[ni >> 1][(ni & 1) * 2 + 1];
                    asm volatile(
                        "mma.sync.aligned.m16n8k16.row.col.f32.f16.f16.f32 "
                        "{%0,%1,%2,%3}, {%4,%5,%6,%7}, {%8,%9}, {%0,%1,%2,%3};"
                        : "+f"(acc[mi][ni][0]), "+f"(acc[mi][ni][1]),
                          "+f"(acc[mi][ni][2]), "+f"(acc[mi][ni][3])
                        : "r"(ar[mi][0]), "r"(ar[mi][1]), "r"(ar[mi][2]), "r"(ar[mi][3]),
                          "r"(b0), "r"(b1));
                }
        }
        __syncthreads();
    }
    if (OUT == 0) {
        float* Cb = (float*)Cbase + bz * cStride + (size_t)(by * BM + wm) * N + bx * BN + wn;
#pragma unroll
        for (int mi = 0; mi < 4; mi++)
#pragma unroll
            for (int ni = 0; ni < 4; ni++) {
                int r0 = mi * 16 + (lane >> 2);
                int c0 = ni * 8 + (lane & 3) * 2;
                *(float2*)(Cb + (size_t)r0 * N + c0)       = make_float2(acc[mi][ni][0], acc[mi][ni][1]);
                *(float2*)(Cb + (size_t)(r0 + 8) * N + c0) = make_float2(acc[mi][ni][2], acc[mi][ni][3]);
            }
    } else {
        f16* Cb = (f16*)Cbase + bz * cStride + (size_t)(by * BM + wm) * N + bx * BN + wn;
#pragma unroll
        for (int mi = 0; mi < 4; mi++)
#pragma unroll
            for (int ni = 0; ni < 4; ni++) {
                int r0 = mi * 16 + (lane >> 2);
                int c0 = ni * 8 + (lane & 3) * 2;
                *(__half2*)(Cb + (size_t)r0 * N + c0)       = __floats2half2_rn(acc[mi][ni][0], acc[mi][ni][1]);
                *(__half2*)(Cb + (size_t)(r0 + 8) * N + c0) = __floats2half2_rn(acc[mi][ni][2], acc[mi][ni][3]);
            }
    }
}

// ---------------- fused split-K reduce (4-way) + fp16 H2 store + layer-2 dots ----------------
// block = one node n; 160 threads; warp h handles head h (128 channels).
__global__ void k_red_dots2(const float* __restrict__ att_src, const float* __restrict__ att_dst) {
    int n = blockIdx.x;
    int t = threadIdx.x, lane = t & 31, h = t >> 5;
    const size_t stride4 = (size_t)N_NODES * F2 / 4;
    const float4* p = (const float4*)g_Pk + (size_t)n * (F2 / 4);

    float4 v = p[t];
#pragma unroll
    for (int z = 1; z < KSPLIT; z++) {
        float4 a = p[z * stride4 + t];
        v.x += a.x; v.y += a.y; v.z += a.z; v.w += a.w;
    }
    __half2* h2 = (__half2*)g_H2h + (size_t)n * (F2 / 2);
    h2[2 * t]     = __floats2half2_rn(v.x, v.y);
    h2[2 * t + 1] = __floats2half2_rn(v.z, v.w);

    int c0 = lane * 4;
    const float* as = att_src + h * OUT_FEAT + c0;
    const float* ad = att_dst + h * OUT_FEAT + c0;
    float sa = v.x * as[0] + v.y * as[1] + v.z * as[2] + v.w * as[3];
    float sd = v.x * ad[0] + v.y * ad[1] + v.z * ad[2] + v.w * ad[3];
#pragma unroll
    for (int o = 16; o > 0; o >>= 1) {
        sa += __shfl_xor_sync(0xffffffffu, sa, o);
        sd += __shfl_xor_sync(0xffffffffu, sd, o);
    }
    if (lane == 0) {
        g_A2s[n * OUT_HEAD + h] = sa;
        g_A2d[n * OUT_HEAD + h] = sd;
    }
}

// ---------------- Layer-1 attention dots ----------------
__global__ void k_dots1(const float* __restrict__ att_src, const float* __restrict__ att_dst) {
    int warp = (blockIdx.x * blockDim.x + threadIdx.x) >> 5;
    int lane = threadIdx.x & 31;
    int n = warp >> 6, h = warp & 63;
    const f16* row = g_H1h + (size_t)n * F1 + h * HID;
    float v1 = __half2float(row[lane]), v2 = __half2float(row[lane + 32]);
    float sa = v1 * att_src[h * HID + lane] + v2 * att_src[h * HID + lane + 32];
    float sd = v1 * att_dst[h * HID + lane] + v2 * att_dst[h * HID + lane + 32];
#pragma unroll
    for (int o = 16; o > 0; o >>= 1) {
        sa += __shfl_xor_sync(0xffffffffu, sa, o);
        sd += __shfl_xor_sync(0xffffffffu, sd, o);
    }
    if (lane == 0) {
        g_A1s[n * IN_HEAD + h] = sa;
        g_A1d[n * IN_HEAD + h] = sd;
    }
}

__device__ __forceinline__ float leaky(float x) { return x > 0.f ? x : NEG_SLOPE * x; }

// ---------------- Layer-1 softmax + aggregation + bias + elu -> fp16 ----------------
// 256 threads: softmax phases use h = t&63, slot = t>>6.
// Aggregation: thread owns half2 channel pair c2 = t&31 across 8 heads g = t>>5.
__global__ void k_agg1(const float* __restrict__ b1) {
    int n = blockIdx.x;
    int t = threadIdx.x;
    int h = t & 63, slot = t >> 6;
    int beg = g_offs[n], end = g_offs[n + 1];
    float adst = g_A1d[n * IN_HEAD + h];

    __shared__ float red[4][64];
    __shared__ float sm_m[64], sm_inv[64];
    __shared__ int   srcb[32];
    __shared__ float alpha[32][64];

    float mx = -1e30f;
    for (int j = beg + slot; j < end; j += 4) {
        int s = g_esrc[j];
        mx = fmaxf(mx, leaky(g_A1s[s * IN_HEAD + h] + adst));
    }
    red[slot][h] = mx;
    __syncthreads();
    if (slot == 0) {
        sm_m[h] = fmaxf(fmaxf(red[0][h], red[1][h]), fmaxf(red[2][h], red[3][h]));
    }
    __syncthreads();
    float M = sm_m[h];

    float sum = 0.f;
    for (int j = beg + slot; j < end; j += 4) {
        int s = g_esrc[j];
        sum += expf(leaky(g_A1s[s * IN_HEAD + h] + adst) - M);
    }
    red[slot][h] = sum;
    __syncthreads();
    if (slot == 0) {
        float d = red[0][h] + red[1][h] + red[2][h] + red[3][h];
        sm_inv[h] = 1.0f / (d + GAT_EPS);
    }
    __syncthreads();
    float INV = sm_inv[h];

    int c2 = t & 31, g = t >> 5;   // half2 pair, head group of 8
    float2 acc[8];
#pragma unroll
    for (int k = 0; k < 8; k++) acc[k] = make_float2(0.f, 0.f);

    for (int jb = beg; jb < end; jb += 32) {
        int cnt = min(32, end - jb);
        if (t < cnt) srcb[t] = g_esrc[jb + t];
        __syncthreads();
        for (int j = slot; j < cnt; j += 4) {
            int s = srcb[j];
            float e = leaky(g_A1s[s * IN_HEAD + h] + adst);
            alpha[j][h] = expf(e - M) * INV;
        }
        __syncthreads();
        for (int j = 0; j < cnt; j++) {
            const __half2* row = (const __half2*)(g_H1h + (size_t)srcb[j] * F1);
#pragma unroll
            for (int k = 0; k < 8; k++) {
                int hh = g * 8 + k;
                float2 f = __half22float2(row[hh * 32 + c2]);
                float a = alpha[j][hh];
                acc[k].x += a * f.x;
                acc[k].y += a * f.y;
            }
        }
        __syncthreads();
    }
    __half2* rowo = (__half2*)(g_H1ae + (size_t)n * F1);
#pragma unroll
    for (int k = 0; k < 8; k++) {
        int hh = g * 8 + k;
        float vx = acc[k].x + b1[hh * HID + 2 * c2];
        float vy = acc[k].y + b1[hh * HID + 2 * c2 + 1];
        vx = vx > 0.f ? vx : expm1f(vx);
        vy = vy > 0.f ? vy : expm1f(vy);
        rowo[hh * 32 + c2] = __floats2half2_rn(vx, vy);
    }
}

// ---------------- Layer-2 softmax + aggregation + head-mean + bias ----------------
__global__ void k_agg2(const float* __restrict__ b2) {
    int n = blockIdx.x;
    int t = threadIdx.x;
    int beg = g_offs[n], end = g_offs[n + 1];

    __shared__ float sm_m[OUT_HEAD], sm_inv[OUT_HEAD];
    __shared__ int   srcb[16];
    __shared__ float alpha[16][OUT_HEAD];

    if (t < OUT_HEAD) {
        float adst = g_A2d[n * OUT_HEAD + t];
        float mx = -1e30f;
        for (int j = beg; j < end; j++)
            mx = fmaxf(mx, leaky(g_A2s[g_esrc[j] * OUT_HEAD + t] + adst));
        float sum = 0.f;
        for (int j = beg; j < end; j++)
            sum += expf(leaky(g_A2s[g_esrc[j] * OUT_HEAD + t] + adst) - mx);
        sm_m[t] = mx;
        sm_inv[t] = 1.0f / (sum + GAT_EPS);
    }
    __syncthreads();

    float acc[OUT_HEAD] = {0.f, 0.f, 0.f, 0.f, 0.f};
    for (int jb = beg; jb < end; jb += 16) {
        int cnt = min(16, end - jb);
        if (t < cnt) srcb[t] = g_esrc[jb + t];
        __syncthreads();
        if (t < cnt * OUT_HEAD) {
            int j = t / OUT_HEAD, hh = t % OUT_HEAD;
            int s = srcb[j];
            float e = leaky(g_A2s[s * OUT_HEAD + hh] + g_A2d[n * OUT_HEAD + hh]);
            alpha[j][hh] = expf(e - sm_m[hh]) * sm_inv[hh];
        }
        __syncthreads();
        for (int j = 0; j < cnt; j++) {
            const f16* row = g_H2h + (size_t)srcb[j] * F2;
#pragma unroll
            for (int hh = 0; hh < OUT_HEAD; hh++)
                acc[hh] += alpha[j][hh] * __half2float(row[hh * OUT_FEAT + t]);
        }
        __syncthreads();
    }
    float o = (acc[0] + acc[1] + acc[2] + acc[3] + acc[4]) * 0.2f + b2[t];
    g_H2o[(size_t)n * OUT_FEAT + t] = o;
}

// ---------------- Final node-mean + tanh ----------------
__global__ void k_part() {
    int b = blockIdx.x, c = threadIdx.x;
    float s = 0.f;
    for (int i = 0; i < N_NODES / 32; i++)
        s += g_H2o[(size_t)(b * (N_NODES / 32) + i) * OUT_FEAT + c];
    g_part[b * OUT_FEAT + c] = s;
}

__global__ void k_final(float* __restrict__ out) {
    int c = threadIdx.x;
    float s = 0.f;
#pragma unroll
    for (int b = 0; b < 32; b++) s += g_part[b * OUT_FEAT + c];
    out[c] = tanhf(s / (float)N_NODES);
}

// ---------------- Launch ----------------
extern "C" void kernel_launch(void* const* d_in, const int* in_sizes, int n_in,
                              void* d_out, int out_size) {
    const float* x        = (const float*)d_in[0];
    const void*  ei       = d_in[1];
    const float* W1       = (const float*)d_in[2];
    const float* att_src1 = (const float*)d_in[3];
    const float* att_dst1 = (const float*)d_in[4];
    const float* b1       = (const float*)d_in[5];
    const float* W2       = (const float*)d_in[6];
    const float* att_src2 = (const float*)d_in[7];
    const float* att_dst2 = (const float*)d_in[8];
    const float* b2       = (const float*)d_in[9];
    float* out = (float*)d_out;

    static f16*   s_H1h  = nullptr;
    static float* s_Pk   = nullptr;
    static f16*   s_xh   = nullptr;
    static f16*   s_W1h  = nullptr;
    static f16*   s_H1ae = nullptr;
    static f16*   s_W2h  = nullptr;
    static cudaStream_t s2 = nullptr;
    static cudaEvent_t  evFork = nullptr, evJoin = nullptr;
    static bool   s_init = false;
    if (!s_init) {
        cudaGetSymbolAddress((void**)&s_H1h,  g_H1h);
        cudaGetSymbolAddress((void**)&s_Pk,   g_Pk);
        cudaGetSymbolAddress((void**)&s_xh,   g_xh);
        cudaGetSymbolAddress((void**)&s_W1h,  g_W1h);
        cudaGetSymbolAddress((void**)&s_H1ae, g_H1ae);
        cudaGetSymbolAddress((void**)&s_W2h,  g_W2h);
        cudaFuncSetAttribute(hgemm<0>, cudaFuncAttributeMaxDynamicSharedMemorySize, HG_SMEM);
        cudaFuncSetAttribute(hgemm<1>, cudaFuncAttributeMaxDynamicSharedMemorySize, HG_SMEM);
        cudaStreamCreateWithFlags(&s2, cudaStreamNonBlocking);
        cudaEventCreateWithFlags(&evFork, cudaEventDisableTiming);
        cudaEventCreateWithFlags(&evJoin, cudaEventDisableTiming);
        s_init = true;
    }

    // ---- fork: CSR chain + W2 convert on s2, concurrent with GEMM1 path ----
    cudaEventRecord(evFork, 0);
    cudaStreamWaitEvent(s2, evFork, 0);

    k_init   <<<(N_NODES + 256) / 256, 256, 0, s2>>>((const int*)ei);
    k_count  <<<(E2 + 255) / 256, 256, 0, s2>>>(ei);
    k_scan   <<<1, 1024, 0, s2>>>();
    k_scatter<<<(E2 + 255) / 256, 256, 0, s2>>>(ei);
    k_cvt_W2 <<<((F1 * F2 / 4) + 255) / 256, 256, 0, s2>>>(W2);
    cudaEventRecord(evJoin, s2);

    // ---- main stream: GEMM1 path ----
    k_cvt_x <<<(N_NODES * IN_FEAT / 4) / 256, 256>>>(x);
    k_cvt_W1<<<(IN_FEAT * F1 / 4) / 256, 256>>>(W1);

    // GEMM1: H1h = x_f16 @ W1_f16, K=256, fp16 out
    hgemm<1><<<dim3(F1 / BN, N_NODES / BM, 1), 256, HG_SMEM>>>(
        s_xh, s_W1h, s_H1h, 0, F1, IN_FEAT, IN_FEAT);

    k_dots1<<<(N_NODES * IN_HEAD) / 8, 256>>>(att_src1, att_dst1);

    // ---- join: agg1 needs CSR; GEMM2 needs W2h ----
    cudaStreamWaitEvent(0, evJoin, 0);

    k_agg1<<<N_NODES, 256>>>(b1);

    // GEMM2: split-K=4, kLen=1024 (640 CTAs -> better wave fill)
    hgemm<0><<<dim3(F2 / BN, N_NODES / BM, KSPLIT), 256, HG_SMEM>>>(
        s_H1ae, s_W2h, s_Pk, (size_t)N_NODES * F2, F2, F1, F1 / KSPLIT);

    // fused: H2h = sum(Pk) (fp16) + layer-2 attention dots
    k_red_dots2<<<N_NODES, 160>>>(att_src2, att_dst2);

    k_agg2<<<N_NODES, 128>>>(b2);

    k_part<<<32, 128>>>();
    k_final<<<1, 128>>>(out);
}

// round 12
// speedup vs baseline: 4.8879x; 1.0565x over previous
#include <cuda_runtime.h>
#include <cuda_fp16.h>
#include <stdint.h>
#include <math.h>

typedef __half f16;

// ---------------- Problem constants ----------------
#define N_NODES 4096
#define N_EDGES 32768
#define E2      (N_EDGES + N_NODES)   // with self loops = 36864
#define IN_FEAT 256
#define HID     64
#define IN_HEAD 64
#define OUT_FEAT 128
#define OUT_HEAD 5
#define F1      (IN_HEAD * HID)       // 4096
#define F2      (OUT_HEAD * OUT_FEAT) // 640
#define NEG_SLOPE 0.2f
#define GAT_EPS 1e-16f
#define KSPLIT  4

// ---------------- Device scratch ----------------
__device__ int   g_is64;
__device__ int   g_counts[N_NODES + 1];
__device__ int   g_offs[N_NODES + 1];
__device__ int   g_cursor[N_NODES];
__device__ int   g_esrc[E2];
__device__ f16   g_H1h[(size_t)N_NODES * F1];     // x @ W1 in fp16 (32 MB)
__device__ float g_A1s[(size_t)N_NODES * IN_HEAD];
__device__ float g_A1d[(size_t)N_NODES * IN_HEAD];
__device__ float g_Pk [(size_t)KSPLIT * N_NODES * F2];  // split-K partials (40 MB)
__device__ f16   g_H2h[(size_t)N_NODES * F2];     // H1a @ W2 in fp16 (5 MB)
__device__ float g_A2s[(size_t)N_NODES * OUT_HEAD];
__device__ float g_A2d[(size_t)N_NODES * OUT_HEAD];
__device__ float g_H2o[(size_t)N_NODES * OUT_FEAT];
__device__ float g_part[32 * OUT_FEAT];

// fp16 operands
__device__ f16   g_xh  [(size_t)N_NODES * IN_FEAT]; // 2 MB
__device__ f16   g_W1h [(size_t)IN_FEAT * F1];      // 2 MB
__device__ f16   g_H1ae[(size_t)N_NODES * F1];      // 32 MB (elu(agg1+b1) fp16)
__device__ f16   g_W2h [(size_t)F1 * F2];           // 5.2 MB

// ---------------- init: zero counts + int64/int32 detect ----------------
__global__ void k_init(const int* ei32) {
    int i = blockIdx.x * blockDim.x + threadIdx.x;
    if (i <= N_NODES) g_counts[i] = 0;
    if (blockIdx.x == 0 && threadIdx.x < 32) {
        int v = ei32[2 * threadIdx.x + 1];
        unsigned any = __ballot_sync(0xffffffffu, v != 0);
        if (threadIdx.x == 0) g_is64 = (any == 0) ? 1 : 0;
    }
}

__device__ __forceinline__ int load_ei(const void* ei, int idx) {
    if (g_is64) return (int)((const long long*)ei)[idx];
    return ((const int*)ei)[idx];
}

// ---------------- CSR build ----------------
__global__ void k_count(const void* ei) {
    int i = blockIdx.x * blockDim.x + threadIdx.x;
    if (i >= E2) return;
    int dst = (i < N_EDGES) ? load_ei(ei, N_EDGES + i) : (i - N_EDGES);
    atomicAdd(&g_counts[dst], 1);
}

__global__ void k_scan() {   // 1 block, 1024 threads; scan 4096 counts
    __shared__ int buf[2][1024];
    int t = threadIdx.x;
    int c0 = g_counts[4 * t], c1 = g_counts[4 * t + 1];
    int c2 = g_counts[4 * t + 2], c3 = g_counts[4 * t + 3];
    int s = c0 + c1 + c2 + c3;
    buf[0][t] = s;
    __syncthreads();
    int pin = 0;
    for (int off = 1; off < 1024; off <<= 1) {
        int v = buf[pin][t];
        if (t >= off) v += buf[pin][t - off];
        buf[pin ^ 1][t] = v;
        pin ^= 1;
        __syncthreads();
    }
    int incl = buf[pin][t];
    int base = incl - s;
    g_offs[4 * t]     = base;
    g_offs[4 * t + 1] = base + c0;
    g_offs[4 * t + 2] = base + c0 + c1;
    g_offs[4 * t + 3] = base + c0 + c1 + c2;
    g_cursor[4 * t]     = base;
    g_cursor[4 * t + 1] = base + c0;
    g_cursor[4 * t + 2] = base + c0 + c1;
    g_cursor[4 * t + 3] = base + c0 + c1 + c2;
    if (t == 1023) g_offs[N_NODES] = incl;
}

__global__ void k_scatter(const void* ei) {
    int i = blockIdx.x * blockDim.x + threadIdx.x;
    if (i >= E2) return;
    int src, dst;
    if (i < N_EDGES) { src = load_ei(ei, i); dst = load_ei(ei, N_EDGES + i); }
    else             { src = i - N_EDGES;    dst = i - N_EDGES; }
    int pos = atomicAdd(&g_cursor[dst], 1);
    g_esrc[pos] = src;
}

// ---------------- fp16 convert kernels (vectorized) ----------------
// Also zero-inits A1s/A1d (one float each per thread; sizes match exactly).
__global__ void k_cvt_x(const float* __restrict__ x) {
    int i = blockIdx.x * blockDim.x + threadIdx.x;   // 262144 threads
    float4 v = ((const float4*)x)[i];
    __half2* o = (__half2*)g_xh;
    o[2 * i]     = __floats2half2_rn(v.x, v.y);
    o[2 * i + 1] = __floats2half2_rn(v.z, v.w);
    g_A1s[i] = 0.f;                                  // N_NODES*IN_HEAD == 262144
    g_A1d[i] = 0.f;
}

__global__ void k_cvt_W1(const float* __restrict__ W) {
    int i = blockIdx.x * blockDim.x + threadIdx.x;
    float4 v = ((const float4*)W)[i];
    __half2* o = (__half2*)g_W1h;
    o[2 * i]     = __floats2half2_rn(v.x, v.y);
    o[2 * i + 1] = __floats2half2_rn(v.z, v.w);
}

__global__ void k_cvt_W2(const float* __restrict__ W) {
    int i = blockIdx.x * blockDim.x + threadIdx.x;
    if (i >= (F1 * F2) / 4) return;
    float4 v = ((const float4*)W)[i];
    __half2* o = (__half2*)g_W2h;
    o[2 * i]     = __floats2half2_rn(v.x, v.y);
    o[2 * i + 1] = __floats2half2_rn(v.z, v.w);
}

// ---------------- fp16 tensor-core GEMM (mma.sync, 3-stage cp.async) ----------------
// C[M,N] = A[M, kOff:kOff+kLen] * B[kOff:kOff+kLen, N].  A/B fp16 row-major.
// blockIdx.z selects split-K segment: kOff = z*kLen, C = Cbase + z*cStride.
// OUT=0: C fp32.  OUT=1: C fp16 + fused layer-1 attention dots (att_src/att_dst
//   [IN_HEAD, HID]; each warp's 32-col slice lies inside one head; partial dots
//   from fp32 accumulators are lane-group reduced and atomicAdd'ed to A1s/A1d).
#define BM 128
#define BN 128
#define BK 32
#define STG 3
#define APITCH (BK + 8)
#define BPITCH (BN + 8)
#define HG_SMEM (STG * (BM * APITCH + BK * BPITCH) * 2)

template <int OUT>
__global__ __launch_bounds__(256, 2)
void hgemm(const f16* __restrict__ A, const f16* __restrict__ B,
           void* __restrict__ Cbase, size_t cStride,
           int N, int aStride, int kLen,
           const float* __restrict__ att_src, const float* __restrict__ att_dst) {
    extern __shared__ f16 smbuf[];
    f16* sA = smbuf;                          // [STG][BM][APITCH]
    f16* sB = smbuf + STG * BM * APITCH;      // [STG][BK][BPITCH]
    int t = threadIdx.x, lane = t & 31, warp = t >> 5;
    int wm = (warp >> 2) * 64;   // 0 or 64
    int wn = (warp & 3) * 32;    // 0,32,64,96
    int bx = blockIdx.x, by = blockIdx.y, bz = blockIdx.z;
    int kOff = bz * kLen;
    const f16* Ab = A + (size_t)(by * BM) * aStride + kOff;
    const f16* Bb = B + (size_t)kOff * N + bx * BN;

    int a_row = t >> 2;          // 0..63 (+64)
    int a_col = (t & 3) * 8;
    int b_row = t >> 4;          // 0..15 (+16)
    int b_col = (t & 15) * 8;

    float acc[4][4][4];
#pragma unroll
    for (int i = 0; i < 4; i++)
#pragma unroll
        for (int j = 0; j < 4; j++)
#pragma unroll
            for (int r = 0; r < 4; r++) acc[i][j][r] = 0.f;

    auto issue = [&](int j) {
        int buf = j % STG;
        int k0 = j * BK;
        f16* pa = sA + buf * BM * APITCH;
        f16* pb = sB + buf * BK * BPITCH;
        uint32_t da0 = (uint32_t)__cvta_generic_to_shared(pa + a_row * APITCH + a_col);
        uint32_t da1 = (uint32_t)__cvta_generic_to_shared(pa + (a_row + 64) * APITCH + a_col);
        const f16* ga0 = Ab + (size_t)a_row * aStride + k0 + a_col;
        const f16* ga1 = Ab + (size_t)(a_row + 64) * aStride + k0 + a_col;
        asm volatile("cp.async.cg.shared.global [%0], [%1], 16;" :: "r"(da0), "l"(ga0));
        asm volatile("cp.async.cg.shared.global [%0], [%1], 16;" :: "r"(da1), "l"(ga1));
        uint32_t db0 = (uint32_t)__cvta_generic_to_shared(pb + b_row * BPITCH + b_col);
        uint32_t db1 = (uint32_t)__cvta_generic_to_shared(pb + (b_row + 16) * BPITCH + b_col);
        const f16* gb0 = Bb + (size_t)(k0 + b_row) * N + b_col;
        const f16* gb1 = Bb + (size_t)(k0 + b_row + 16) * N + b_col;
        asm volatile("cp.async.cg.shared.global [%0], [%1], 16;" :: "r"(db0), "l"(gb0));
        asm volatile("cp.async.cg.shared.global [%0], [%1], 16;" :: "r"(db1), "l"(gb1));
        asm volatile("cp.async.commit_group;");
    };

    int nc = kLen / BK;
    issue(0);
    if (nc > 1) issue(1);
    for (int s = 0; s < nc; s++) {
        if (s < nc - 1) { asm volatile("cp.async.wait_group 1;"); }
        else            { asm volatile("cp.async.wait_group 0;"); }
        __syncthreads();
        if (s + 2 < nc) issue(s + 2);
        int buf = s % STG;
        f16* pa = sA + buf * BM * APITCH;
        f16* pb = sB + buf * BK * BPITCH;
#pragma unroll
        for (int kk = 0; kk < 2; kk++) {
            int k = kk * 16;
            uint32_t ar[4][4], br[2][4];
#pragma unroll
            for (int mi = 0; mi < 4; mi++) {
                int row = wm + mi * 16 + (lane & 7) + ((lane >> 3) & 1) * 8;
                int col = k + (lane >> 4) * 8;
                uint32_t addr = (uint32_t)__cvta_generic_to_shared(pa + row * APITCH + col);
                asm volatile("ldmatrix.sync.aligned.m8n8.x4.shared.b16 {%0,%1,%2,%3}, [%4];"
                             : "=r"(ar[mi][0]), "=r"(ar[mi][1]), "=r"(ar[mi][2]), "=r"(ar[mi][3])
                             : "r"(addr));
            }
#pragma unroll
            for (int n2 = 0; n2 < 2; n2++) {
                int rrow = k + (lane & 7) + ((lane >> 3) & 1) * 8;
                int rcol = wn + n2 * 16 + (lane >> 4) * 8;
                uint32_t addr = (uint32_t)__cvta_generic_to_shared(pb + rrow * BPITCH + rcol);
                asm volatile("ldmatrix.sync.aligned.m8n8.x4.trans.shared.b16 {%0,%1,%2,%3}, [%4];"
                             : "=r"(br[n2][0]), "=r"(br[n2][1]), "=r"(br[n2][2]), "=r"(br[n2][3])
                             : "r"(addr));
            }
#pragma unroll
            for (int mi = 0; mi < 4; mi++)
#pragma unroll
                for (int ni = 0; ni < 4; ni++) {
                    uint32_t b0 = br[ni >> 1][(ni & 1) * 2];
                    uint32_t b1 = br[ni >> 1][(ni & 1) * 2 + 1];
                    asm volatile(
                        "mma.sync.aligned.m16n8k16.row.col.f32.f16.f16.f32 "
                        "{%0,%1,%2,%3}, {%4,%5,%6,%7}, {%8,%9}, {%0,%1,%2,%3};"
                        : "+f"(acc[mi][ni][0]), "+f"(acc[mi][ni][1]),
                          "+f"(acc[mi][ni][2]), "+f"(acc[mi][ni][3])
                        : "r"(ar[mi][0]), "r"(ar[mi][1]), "r"(ar[mi][2]), "r"(ar[mi][3]),
                          "r"(b0), "r"(b1));
                }
        }
        __syncthreads();
    }
    if (OUT == 0) {
        float* Cb = (float*)Cbase + bz * cStride + (size_t)(by * BM + wm) * N + bx * BN + wn;
#pragma unroll
        for (int mi = 0; mi < 4; mi++)
#pragma unroll
            for (int ni = 0; ni < 4; ni++) {
                int r0 = mi * 16 + (lane >> 2);
                int c0 = ni * 8 + (lane & 3) * 2;
                *(float2*)(Cb + (size_t)r0 * N + c0)       = make_float2(acc[mi][ni][0], acc[mi][ni][1]);
                *(float2*)(Cb + (size_t)(r0 + 8) * N + c0) = make_float2(acc[mi][ni][2], acc[mi][ni][3]);
            }
    } else {
        f16* Cb = (f16*)Cbase + (size_t)(by * BM + wm) * N + bx * BN + wn;
#pragma unroll
        for (int mi = 0; mi < 4; mi++)
#pragma unroll
            for (int ni = 0; ni < 4; ni++) {
                int r0 = mi * 16 + (lane >> 2);
                int c0 = ni * 8 + (lane & 3) * 2;
                *(__half2*)(Cb + (size_t)r0 * N + c0)       = __floats2half2_rn(acc[mi][ni][0], acc[mi][ni][1]);
                *(__half2*)(Cb + (size_t)(r0 + 8) * N + c0) = __floats2half2_rn(acc[mi][ni][2], acc[mi][ni][3]);
            }
        // ---- fused layer-1 attention dots (warp's 32 cols lie in one head) ----
        int gcol0 = bx * BN + wn;            // global col of warp slice
        int head = gcol0 >> 6;               // HID = 64
        const float* as = att_src + head * HID;
        const float* ad = att_dst + head * HID;
        int cbase = (gcol0 & 63) + (lane & 3) * 2;   // channel of q=0 within head
#pragma unroll
        for (int mi = 0; mi < 4; mi++) {
#pragma unroll
            for (int rr = 0; rr < 2; rr++) {
                float ssum = 0.f, dsum = 0.f;
#pragma unroll
                for (int ni = 0; ni < 4; ni++) {
#pragma unroll
                    for (int q = 0; q < 2; q++) {
                        int ch = cbase + ni * 8 + q;
                        float v = acc[mi][ni][rr * 2 + q];
                        ssum += v * as[ch];
                        dsum += v * ad[ch];
                    }
                }
                ssum += __shfl_xor_sync(0xffffffffu, ssum, 1);
                ssum += __shfl_xor_sync(0xffffffffu, ssum, 2);
                dsum += __shfl_xor_sync(0xffffffffu, dsum, 1);
                dsum += __shfl_xor_sync(0xffffffffu, dsum, 2);
                if ((lane & 3) == 0) {
                    int n = by * BM + wm + mi * 16 + (lane >> 2) + rr * 8;
                    atomicAdd(&g_A1s[n * IN_HEAD + head], ssum);
                    atomicAdd(&g_A1d[n * IN_HEAD + head], dsum);
                }
            }
        }
    }
}

// ---------------- fused split-K reduce (4-way) + fp16 H2 store + layer-2 dots ----------------
__global__ void k_red_dots2(const float* __restrict__ att_src, const float* __restrict__ att_dst) {
    int n = blockIdx.x;
    int t = threadIdx.x, lane = t & 31, h = t >> 5;
    const size_t stride4 = (size_t)N_NODES * F2 / 4;
    const float4* p = (const float4*)g_Pk + (size_t)n * (F2 / 4);

    float4 v = p[t];
#pragma unroll
    for (int z = 1; z < KSPLIT; z++) {
        float4 a = p[z * stride4 + t];
        v.x += a.x; v.y += a.y; v.z += a.z; v.w += a.w;
    }
    __half2* h2 = (__half2*)g_H2h + (size_t)n * (F2 / 2);
    h2[2 * t]     = __floats2half2_rn(v.x, v.y);
    h2[2 * t + 1] = __floats2half2_rn(v.z, v.w);

    int c0 = lane * 4;
    const float* as = att_src + h * OUT_FEAT + c0;
    const float* ad = att_dst + h * OUT_FEAT + c0;
    float sa = v.x * as[0] + v.y * as[1] + v.z * as[2] + v.w * as[3];
    float sd = v.x * ad[0] + v.y * ad[1] + v.z * ad[2] + v.w * ad[3];
#pragma unroll
    for (int o = 16; o > 0; o >>= 1) {
        sa += __shfl_xor_sync(0xffffffffu, sa, o);
        sd += __shfl_xor_sync(0xffffffffu, sd, o);
    }
    if (lane == 0) {
        g_A2s[n * OUT_HEAD + h] = sa;
        g_A2d[n * OUT_HEAD + h] = sd;
    }
}

__device__ __forceinline__ float leaky(float x) { return x > 0.f ? x : NEG_SLOPE * x; }

// ---------------- Layer-1 softmax + aggregation + bias + elu -> fp16 ----------------
__global__ void k_agg1(const float* __restrict__ b1) {
    int n = blockIdx.x;
    int t = threadIdx.x;
    int h = t & 63, slot = t >> 6;
    int beg = g_offs[n], end = g_offs[n + 1];
    float adst = g_A1d[n * IN_HEAD + h];

    __shared__ float red[4][64];
    __shared__ float sm_m[64], sm_inv[64];
    __shared__ int   srcb[32];
    __shared__ float alpha[32][64];

    float mx = -1e30f;
    for (int j = beg + slot; j < end; j += 4) {
        int s = g_esrc[j];
        mx = fmaxf(mx, leaky(g_A1s[s * IN_HEAD + h] + adst));
    }
    red[slot][h] = mx;
    __syncthreads();
    if (slot == 0) {
        sm_m[h] = fmaxf(fmaxf(red[0][h], red[1][h]), fmaxf(red[2][h], red[3][h]));
    }
    __syncthreads();
    float M = sm_m[h];

    float sum = 0.f;
    for (int j = beg + slot; j < end; j += 4) {
        int s = g_esrc[j];
        sum += expf(leaky(g_A1s[s * IN_HEAD + h] + adst) - M);
    }
    red[slot][h] = sum;
    __syncthreads();
    if (slot == 0) {
        float d = red[0][h] + red[1][h] + red[2][h] + red[3][h];
        sm_inv[h] = 1.0f / (d + GAT_EPS);
    }
    __syncthreads();
    float INV = sm_inv[h];

    int c2 = t & 31, g = t >> 5;   // half2 pair, head group of 8
    float2 acc[8];
#pragma unroll
    for (int k = 0; k < 8; k++) acc[k] = make_float2(0.f, 0.f);

    for (int jb = beg; jb < end; jb += 32) {
        int cnt = min(32, end - jb);
        if (t < cnt) srcb[t] = g_esrc[jb + t];
        __syncthreads();
        for (int j = slot; j < cnt; j += 4) {
            int s = srcb[j];
            float e = leaky(g_A1s[s * IN_HEAD + h] + adst);
            alpha[j][h] = expf(e - M) * INV;
        }
        __syncthreads();
        int j = 0;
        for (; j + 1 < cnt; j += 2) {
            const __half2* rowA = (const __half2*)(g_H1h + (size_t)srcb[j] * F1);
            const __half2* rowB = (const __half2*)(g_H1h + (size_t)srcb[j + 1] * F1);
#pragma unroll
            for (int k = 0; k < 8; k++) {
                int hh = g * 8 + k;
                float2 fA = __half22float2(rowA[hh * 32 + c2]);
                float2 fB = __half22float2(rowB[hh * 32 + c2]);
                float aA = alpha[j][hh], aB = alpha[j + 1][hh];
                acc[k].x += aA * fA.x + aB * fB.x;
                acc[k].y += aA * fA.y + aB * fB.y;
            }
        }
        if (j < cnt) {
            const __half2* row = (const __half2*)(g_H1h + (size_t)srcb[j] * F1);
#pragma unroll
            for (int k = 0; k < 8; k++) {
                int hh = g * 8 + k;
                float2 f = __half22float2(row[hh * 32 + c2]);
                float a = alpha[j][hh];
                acc[k].x += a * f.x;
                acc[k].y += a * f.y;
            }
        }
        __syncthreads();
    }
    __half2* rowo = (__half2*)(g_H1ae + (size_t)n * F1);
#pragma unroll
    for (int k = 0; k < 8; k++) {
        int hh = g * 8 + k;
        float vx = acc[k].x + b1[hh * HID + 2 * c2];
        float vy = acc[k].y + b1[hh * HID + 2 * c2 + 1];
        vx = vx > 0.f ? vx : expm1f(vx);
        vy = vy > 0.f ? vy : expm1f(vy);
        rowo[hh * 32 + c2] = __floats2half2_rn(vx, vy);
    }
}

// ---------------- Layer-2 softmax + aggregation + head-mean + bias ----------------
__global__ void k_agg2(const float* __restrict__ b2) {
    int n = blockIdx.x;
    int t = threadIdx.x;
    int beg = g_offs[n], end = g_offs[n + 1];

    __shared__ float sm_m[OUT_HEAD], sm_inv[OUT_HEAD];
    __shared__ int   srcb[16];
    __shared__ float alpha[16][OUT_HEAD];

    if (t < OUT_HEAD) {
        float adst = g_A2d[n * OUT_HEAD + t];
        float mx = -1e30f;
        for (int j = beg; j < end; j++)
            mx = fmaxf(mx, leaky(g_A2s[g_esrc[j] * OUT_HEAD + t] + adst));
        float sum = 0.f;
        for (int j = beg; j < end; j++)
            sum += expf(leaky(g_A2s[g_esrc[j] * OUT_HEAD + t] + adst) - mx);
        sm_m[t] = mx;
        sm_inv[t] = 1.0f / (sum + GAT_EPS);
    }
    __syncthreads();

    float acc[OUT_HEAD] = {0.f, 0.f, 0.f, 0.f, 0.f};
    for (int jb = beg; jb < end; jb += 16) {
        int cnt = min(16, end - jb);
        if (t < cnt) srcb[t] = g_esrc[jb + t];
        __syncthreads();
        if (t < cnt * OUT_HEAD) {
            int j = t / OUT_HEAD, hh = t % OUT_HEAD;
            int s = srcb[j];
            float e = leaky(g_A2s[s * OUT_HEAD + hh] + g_A2d[n * OUT_HEAD + hh]);
            alpha[j][hh] = expf(e - sm_m[hh]) * sm_inv[hh];
        }
        __syncthreads();
        for (int j = 0; j < cnt; j++) {
            const f16* row = g_H2h + (size_t)srcb[j] * F2;
#pragma unroll
            for (int hh = 0; hh < OUT_HEAD; hh++)
                acc[hh] += alpha[j][hh] * __half2float(row[hh * OUT_FEAT + t]);
        }
        __syncthreads();
    }
    float o = (acc[0] + acc[1] + acc[2] + acc[3] + acc[4]) * 0.2f + b2[t];
    g_H2o[(size_t)n * OUT_FEAT + t] = o;
}

// ---------------- Final node-mean + tanh ----------------
__global__ void k_part() {
    int b = blockIdx.x, c = threadIdx.x;
    float s = 0.f;
    for (int i = 0; i < N_NODES / 32; i++)
        s += g_H2o[(size_t)(b * (N_NODES / 32) + i) * OUT_FEAT + c];
    g_part[b * OUT_FEAT + c] = s;
}

__global__ void k_final(float* __restrict__ out) {
    int c = threadIdx.x;
    float s = 0.f;
#pragma unroll
    for (int b = 0; b < 32; b++) s += g_part[b * OUT_FEAT + c];
    out[c] = tanhf(s / (float)N_NODES);
}

// ---------------- Launch ----------------
extern "C" void kernel_launch(void* const* d_in, const int* in_sizes, int n_in,
                              void* d_out, int out_size) {
    const float* x        = (const float*)d_in[0];
    const void*  ei       = d_in[1];
    const float* W1       = (const float*)d_in[2];
    const float* att_src1 = (const float*)d_in[3];
    const float* att_dst1 = (const float*)d_in[4];
    const float* b1       = (const float*)d_in[5];
    const float* W2       = (const float*)d_in[6];
    const float* att_src2 = (const float*)d_in[7];
    const float* att_dst2 = (const float*)d_in[8];
    const float* b2       = (const float*)d_in[9];
    float* out = (float*)d_out;

    static f16*   s_H1h  = nullptr;
    static float* s_Pk   = nullptr;
    static f16*   s_xh   = nullptr;
    static f16*   s_W1h  = nullptr;
    static f16*   s_H1ae = nullptr;
    static f16*   s_W2h  = nullptr;
    static cudaStream_t s2 = nullptr;
    static cudaEvent_t  evFork = nullptr, evJoin = nullptr;
    static bool   s_init = false;
    if (!s_init) {
        cudaGetSymbolAddress((void**)&s_H1h,  g_H1h);
        cudaGetSymbolAddress((void**)&s_Pk,   g_Pk);
        cudaGetSymbolAddress((void**)&s_xh,   g_xh);
        cudaGetSymbolAddress((void**)&s_W1h,  g_W1h);
        cudaGetSymbolAddress((void**)&s_H1ae, g_H1ae);
        cudaGetSymbolAddress((void**)&s_W2h,  g_W2h);
        cudaFuncSetAttribute(hgemm<0>, cudaFuncAttributeMaxDynamicSharedMemorySize, HG_SMEM);
        cudaFuncSetAttribute(hgemm<1>, cudaFuncAttributeMaxDynamicSharedMemorySize, HG_SMEM);
        cudaStreamCreateWithFlags(&s2, cudaStreamNonBlocking);
        cudaEventCreateWithFlags(&evFork, cudaEventDisableTiming);
        cudaEventCreateWithFlags(&evJoin, cudaEventDisableTiming);
        s_init = true;
    }

    // ---- fork: CSR chain + W2 convert on s2, concurrent with GEMM1 path ----
    cudaEventRecord(evFork, 0);
    cudaStreamWaitEvent(s2, evFork, 0);

    k_init   <<<(N_NODES + 256) / 256, 256, 0, s2>>>((const int*)ei);
    k_count  <<<(E2 + 255) / 256, 256, 0, s2>>>(ei);
    k_scan   <<<1, 1024, 0, s2>>>();
    k_scatter<<<(E2 + 255) / 256, 256, 0, s2>>>(ei);
    k_cvt_W2 <<<((F1 * F2 / 4) + 255) / 256, 256, 0, s2>>>(W2);
    cudaEventRecord(evJoin, s2);

    // ---- main stream: GEMM1 path (k_cvt_x also zeroes A1s/A1d) ----
    k_cvt_x <<<(N_NODES * IN_FEAT / 4) / 256, 256>>>(x);
    k_cvt_W1<<<(IN_FEAT * F1 / 4) / 256, 256>>>(W1);

    // GEMM1: H1h = x_f16 @ W1_f16, K=256, fp16 out + fused layer-1 dots
    hgemm<1><<<dim3(F1 / BN, N_NODES / BM, 1), 256, HG_SMEM>>>(
        s_xh, s_W1h, s_H1h, 0, F1, IN_FEAT, IN_FEAT, att_src1, att_dst1);

    // ---- join: agg1 needs CSR; GEMM2 needs W2h ----
    cudaStreamWaitEvent(0, evJoin, 0);

    k_agg1<<<N_NODES, 256>>>(b1);

    // GEMM2: split-K=4, kLen=1024 (640 CTAs -> better wave fill)
    hgemm<0><<<dim3(F2 / BN, N_NODES / BM, KSPLIT), 256, HG_SMEM>>>(
        s_H1ae, s_W2h, s_Pk, (size_t)N_NODES * F2, F2, F1, F1 / KSPLIT, nullptr, nullptr);

    // fused: H2h = sum(Pk) (fp16) + layer-2 attention dots
    k_red_dots2<<<N_NODES, 160>>>(att_src2, att_dst2);

    k_agg2<<<N_NODES, 128>>>(b2);

    k_part<<<32, 128>>>();
    k_final<<<1, 128>>>(out);
}

// round 13
// speedup vs baseline: 4.9464x; 1.0120x over previous
#include <cuda_runtime.h>
#include <cuda_fp16.h>
#include <stdint.h>
#include <math.h>

typedef __half f16;

// ---------------- Problem constants ----------------
#define N_NODES 4096
#define N_EDGES 32768
#define E2      (N_EDGES + N_NODES)   // with self loops = 36864
#define IN_FEAT 256
#define HID     64
#define IN_HEAD 64
#define OUT_FEAT 128
#define OUT_HEAD 5
#define F1      (IN_HEAD * HID)       // 4096
#define F2      (OUT_HEAD * OUT_FEAT) // 640
#define NEG_SLOPE 0.2f
#define GAT_EPS 1e-16f
#define KSPLIT  4

// ---------------- Device scratch ----------------
__device__ int   g_is64;
__device__ int   g_counts[N_NODES + 1];
__device__ int   g_offs[N_NODES + 1];
__device__ int   g_cursor[N_NODES];
__device__ int   g_esrc[E2];
__device__ f16   g_H1h[(size_t)N_NODES * F1];     // x @ W1 in fp16 (32 MB)
__device__ float g_A1s[(size_t)N_NODES * IN_HEAD];
__device__ float g_A1d[(size_t)N_NODES * IN_HEAD];
__device__ float g_Pk [(size_t)KSPLIT * N_NODES * F2];  // split-K partials (40 MB)
__device__ f16   g_H2h[(size_t)N_NODES * F2];     // H1a @ W2 in fp16 (5 MB)
__device__ float g_A2s[(size_t)N_NODES * OUT_HEAD];
__device__ float g_A2d[(size_t)N_NODES * OUT_HEAD];
__device__ float g_H2o[(size_t)N_NODES * OUT_FEAT];
__device__ float g_part[32 * OUT_FEAT];

// fp16 operands
__device__ f16   g_xh  [(size_t)N_NODES * IN_FEAT]; // 2 MB
__device__ f16   g_W1h [(size_t)IN_FEAT * F1];      // 2 MB
__device__ f16   g_H1ae[(size_t)N_NODES * F1];      // 32 MB (elu(agg1+b1) fp16)
__device__ f16   g_W2h [(size_t)F1 * F2];           // 5.2 MB

// ---------------- init: zero counts + int64/int32 detect ----------------
__global__ void k_init(const int* ei32) {
    int i = blockIdx.x * blockDim.x + threadIdx.x;
    if (i <= N_NODES) g_counts[i] = 0;
    if (blockIdx.x == 0 && threadIdx.x < 32) {
        int v = ei32[2 * threadIdx.x + 1];
        unsigned any = __ballot_sync(0xffffffffu, v != 0);
        if (threadIdx.x == 0) g_is64 = (any == 0) ? 1 : 0;
    }
}

__device__ __forceinline__ int load_ei(const void* ei, int idx) {
    if (g_is64) return (int)((const long long*)ei)[idx];
    return ((const int*)ei)[idx];
}

// ---------------- CSR build ----------------
__global__ void k_count(const void* ei) {
    int i = blockIdx.x * blockDim.x + threadIdx.x;
    if (i >= E2) return;
    int dst = (i < N_EDGES) ? load_ei(ei, N_EDGES + i) : (i - N_EDGES);
    atomicAdd(&g_counts[dst], 1);
}

__global__ void k_scan() {   // 1 block, 1024 threads; scan 4096 counts
    __shared__ int buf[2][1024];
    int t = threadIdx.x;
    int c0 = g_counts[4 * t], c1 = g_counts[4 * t + 1];
    int c2 = g_counts[4 * t + 2], c3 = g_counts[4 * t + 3];
    int s = c0 + c1 + c2 + c3;
    buf[0][t] = s;
    __syncthreads();
    int pin = 0;
    for (int off = 1; off < 1024; off <<= 1) {
        int v = buf[pin][t];
        if (t >= off) v += buf[pin][t - off];
        buf[pin ^ 1][t] = v;
        pin ^= 1;
        __syncthreads();
    }
    int incl = buf[pin][t];
    int base = incl - s;
    g_offs[4 * t]     = base;
    g_offs[4 * t + 1] = base + c0;
    g_offs[4 * t + 2] = base + c0 + c1;
    g_offs[4 * t + 3] = base + c0 + c1 + c2;
    g_cursor[4 * t]     = base;
    g_cursor[4 * t + 1] = base + c0;
    g_cursor[4 * t + 2] = base + c0 + c1;
    g_cursor[4 * t + 3] = base + c0 + c1 + c2;
    if (t == 1023) g_offs[N_NODES] = incl;
}

__global__ void k_scatter(const void* ei) {
    int i = blockIdx.x * blockDim.x + threadIdx.x;
    if (i >= E2) return;
    int src, dst;
    if (i < N_EDGES) { src = load_ei(ei, i); dst = load_ei(ei, N_EDGES + i); }
    else             { src = i - N_EDGES;    dst = i - N_EDGES; }
    int pos = atomicAdd(&g_cursor[dst], 1);
    g_esrc[pos] = src;
}

// ---------------- fp16 convert kernels (vectorized) ----------------
__global__ void k_cvt_x(const float* __restrict__ x) {
    int i = blockIdx.x * blockDim.x + threadIdx.x;   // 262144 threads
    float4 v = ((const float4*)x)[i];
    __half2* o = (__half2*)g_xh;
    o[2 * i]     = __floats2half2_rn(v.x, v.y);
    o[2 * i + 1] = __floats2half2_rn(v.z, v.w);
    g_A1s[i] = 0.f;                                  // N_NODES*IN_HEAD == 262144
    g_A1d[i] = 0.f;
}

__global__ void k_cvt_W1(const float* __restrict__ W) {
    int i = blockIdx.x * blockDim.x + threadIdx.x;
    float4 v = ((const float4*)W)[i];
    __half2* o = (__half2*)g_W1h;
    o[2 * i]     = __floats2half2_rn(v.x, v.y);
    o[2 * i + 1] = __floats2half2_rn(v.z, v.w);
}

__global__ void k_cvt_W2(const float* __restrict__ W) {
    int i = blockIdx.x * blockDim.x + threadIdx.x;
    if (i >= (F1 * F2) / 4) return;
    float4 v = ((const float4*)W)[i];
    __half2* o = (__half2*)g_W2h;
    o[2 * i]     = __floats2half2_rn(v.x, v.y);
    o[2 * i + 1] = __floats2half2_rn(v.z, v.w);
}

// ---------------- shared GEMM geometry ----------------
#define BM 128
#define BN 128
#define BK 32
#define STG 3
#define APITCH (BK + 8)
#define BPITCH (BN + 8)
#define HG_SMEM (STG * (BM * APITCH + BK * BPITCH) * 2)

// ---------------- GEMM1: 8 warps, warp tile 64x32, fp16 out + fused dots1 ----------------
__global__ __launch_bounds__(256, 2)
void hgemm1(const f16* __restrict__ A, const f16* __restrict__ B,
            f16* __restrict__ C, int N, int aStride, int kLen,
            const float* __restrict__ att_src, const float* __restrict__ att_dst) {
    extern __shared__ f16 smbuf[];
    f16* sA = smbuf;
    f16* sB = smbuf + STG * BM * APITCH;
    int t = threadIdx.x, lane = t & 31, warp = t >> 5;
    int wm = (warp >> 2) * 64;
    int wn = (warp & 3) * 32;
    int bx = blockIdx.x, by = blockIdx.y;
    const f16* Ab = A + (size_t)(by * BM) * aStride;
    const f16* Bb = B + bx * BN;

    int a_row = t >> 2;
    int a_col = (t & 3) * 8;
    int b_row = t >> 4;
    int b_col = (t & 15) * 8;

    float acc[4][4][4];
#pragma unroll
    for (int i = 0; i < 4; i++)
#pragma unroll
        for (int j = 0; j < 4; j++)
#pragma unroll
            for (int r = 0; r < 4; r++) acc[i][j][r] = 0.f;

    auto issue = [&](int j) {
        int buf = j % STG;
        int k0 = j * BK;
        f16* pa = sA + buf * BM * APITCH;
        f16* pb = sB + buf * BK * BPITCH;
        uint32_t da0 = (uint32_t)__cvta_generic_to_shared(pa + a_row * APITCH + a_col);
        uint32_t da1 = (uint32_t)__cvta_generic_to_shared(pa + (a_row + 64) * APITCH + a_col);
        const f16* ga0 = Ab + (size_t)a_row * aStride + k0 + a_col;
        const f16* ga1 = Ab + (size_t)(a_row + 64) * aStride + k0 + a_col;
        asm volatile("cp.async.cg.shared.global [%0], [%1], 16;" :: "r"(da0), "l"(ga0));
        asm volatile("cp.async.cg.shared.global [%0], [%1], 16;" :: "r"(da1), "l"(ga1));
        uint32_t db0 = (uint32_t)__cvta_generic_to_shared(pb + b_row * BPITCH + b_col);
        uint32_t db1 = (uint32_t)__cvta_generic_to_shared(pb + (b_row + 16) * BPITCH + b_col);
        const f16* gb0 = Bb + (size_t)(k0 + b_row) * N + b_col;
        const f16* gb1 = Bb + (size_t)(k0 + b_row + 16) * N + b_col;
        asm volatile("cp.async.cg.shared.global [%0], [%1], 16;" :: "r"(db0), "l"(gb0));
        asm volatile("cp.async.cg.shared.global [%0], [%1], 16;" :: "r"(db1), "l"(gb1));
        asm volatile("cp.async.commit_group;");
    };

    int nc = kLen / BK;
    issue(0);
    if (nc > 1) issue(1);
    for (int s = 0; s < nc; s++) {
        if (s < nc - 1) { asm volatile("cp.async.wait_group 1;"); }
        else            { asm volatile("cp.async.wait_group 0;"); }
        __syncthreads();
        if (s + 2 < nc) issue(s + 2);
        int buf = s % STG;
        f16* pa = sA + buf * BM * APITCH;
        f16* pb = sB + buf * BK * BPITCH;
#pragma unroll
        for (int kk = 0; kk < 2; kk++) {
            int k = kk * 16;
            uint32_t ar[4][4], br[2][4];
#pragma unroll
            for (int mi = 0; mi < 4; mi++) {
                int row = wm + mi * 16 + (lane & 7) + ((lane >> 3) & 1) * 8;
                int col = k + (lane >> 4) * 8;
                uint32_t addr = (uint32_t)__cvta_generic_to_shared(pa + row * APITCH + col);
                asm volatile("ldmatrix.sync.aligned.m8n8.x4.shared.b16 {%0,%1,%2,%3}, [%4];"
                             : "=r"(ar[mi][0]), "=r"(ar[mi][1]), "=r"(ar[mi][2]), "=r"(ar[mi][3])
                             : "r"(addr));
            }
#pragma unroll
            for (int n2 = 0; n2 < 2; n2++) {
                int rrow = k + (lane & 7) + ((lane >> 3) & 1) * 8;
                int rcol = wn + n2 * 16 + (lane >> 4) * 8;
                uint32_t addr = (uint32_t)__cvta_generic_to_shared(pb + rrow * BPITCH + rcol);
                asm volatile("ldmatrix.sync.aligned.m8n8.x4.trans.shared.b16 {%0,%1,%2,%3}, [%4];"
                             : "=r"(br[n2][0]), "=r"(br[n2][1]), "=r"(br[n2][2]), "=r"(br[n2][3])
                             : "r"(addr));
            }
#pragma unroll
            for (int mi = 0; mi < 4; mi++)
#pragma unroll
                for (int ni = 0; ni < 4; ni++) {
                    uint32_t b0 = br[ni >> 1][(ni & 1) * 2];
                    uint32_t b1 = br[ni >> 1][(ni & 1) * 2 + 1];
                    asm volatile(
                        "mma.sync.aligned.m16n8k16.row.col.f32.f16.f16.f32 "
                        "{%0,%1,%2,%3}, {%4,%5,%6,%7}, {%8,%9}, {%0,%1,%2,%3};"
                        : "+f"(acc[mi][ni][0]), "+f"(acc[mi][ni][1]),
                          "+f"(acc[mi][ni][2]), "+f"(acc[mi][ni][3])
                        : "r"(ar[mi][0]), "r"(ar[mi][1]), "r"(ar[mi][2]), "r"(ar[mi][3]),
                          "r"(b0), "r"(b1));
                }
        }
        __syncthreads();
    }
    f16* Cb = C + (size_t)(by * BM + wm) * N + bx * BN + wn;
#pragma unroll
    for (int mi = 0; mi < 4; mi++)
#pragma unroll
        for (int ni = 0; ni < 4; ni++) {
            int r0 = mi * 16 + (lane >> 2);
            int c0 = ni * 8 + (lane & 3) * 2;
            *(__half2*)(Cb + (size_t)r0 * N + c0)       = __floats2half2_rn(acc[mi][ni][0], acc[mi][ni][1]);
            *(__half2*)(Cb + (size_t)(r0 + 8) * N + c0) = __floats2half2_rn(acc[mi][ni][2], acc[mi][ni][3]);
        }
    // ---- fused layer-1 attention dots (warp's 32 cols lie in one head) ----
    int gcol0 = bx * BN + wn;
    int head = gcol0 >> 6;               // HID = 64
    const float* as = att_src + head * HID;
    const float* ad = att_dst + head * HID;
    int cbase = (gcol0 & 63) + (lane & 3) * 2;
#pragma unroll
    for (int mi = 0; mi < 4; mi++) {
#pragma unroll
        for (int rr = 0; rr < 2; rr++) {
            float ssum = 0.f, dsum = 0.f;
#pragma unroll
            for (int ni = 0; ni < 4; ni++) {
#pragma unroll
                for (int q = 0; q < 2; q++) {
                    int ch = cbase + ni * 8 + q;
                    float v = acc[mi][ni][rr * 2 + q];
                    ssum += v * as[ch];
                    dsum += v * ad[ch];
                }
            }
            ssum += __shfl_xor_sync(0xffffffffu, ssum, 1);
            ssum += __shfl_xor_sync(0xffffffffu, ssum, 2);
            dsum += __shfl_xor_sync(0xffffffffu, dsum, 1);
            dsum += __shfl_xor_sync(0xffffffffu, dsum, 2);
            if ((lane & 3) == 0) {
                int n = by * BM + wm + mi * 16 + (lane >> 2) + rr * 8;
                atomicAdd(&g_A1s[n * IN_HEAD + head], ssum);
                atomicAdd(&g_A1d[n * IN_HEAD + head], dsum);
            }
        }
    }
}

// ---------------- GEMM2: 4 warps, warp tile 64x64 (fewer LDSM per MMA), fp32 out ----------------
__global__ __launch_bounds__(128, 2)
void hgemm2(const f16* __restrict__ A, const f16* __restrict__ B,
            float* __restrict__ Cbase, size_t cStride,
            int N, int aStride, int kLen) {
    extern __shared__ f16 smbuf[];
    f16* sA = smbuf;
    f16* sB = smbuf + STG * BM * APITCH;
    int t = threadIdx.x, lane = t & 31, warp = t >> 5;
    int wm = (warp >> 1) * 64;   // 0 or 64
    int wn = (warp & 1) * 64;    // 0 or 64
    int bx = blockIdx.x, by = blockIdx.y, bz = blockIdx.z;
    int kOff = bz * kLen;
    const f16* Ab = A + (size_t)(by * BM) * aStride + kOff;
    const f16* Bb = B + (size_t)kOff * N + bx * BN;

    float acc[4][8][4];
#pragma unroll
    for (int i = 0; i < 4; i++)
#pragma unroll
        for (int j = 0; j < 8; j++)
#pragma unroll
            for (int r = 0; r < 4; r++) acc[i][j][r] = 0.f;

    auto issue = [&](int j) {
        int buf = j % STG;
        int k0 = j * BK;
        f16* pa = sA + buf * BM * APITCH;
        f16* pb = sB + buf * BK * BPITCH;
#pragma unroll
        for (int i = 0; i < 4; i++) {          // A: 128x32 = 512 chunks of 16B
            int id = t + 128 * i;
            int row = id >> 2, c = (id & 3) * 8;
            uint32_t d = (uint32_t)__cvta_generic_to_shared(pa + row * APITCH + c);
            const f16* g = Ab + (size_t)row * aStride + k0 + c;
            asm volatile("cp.async.cg.shared.global [%0], [%1], 16;" :: "r"(d), "l"(g));
        }
#pragma unroll
        for (int i = 0; i < 4; i++) {          // B: 32x128 = 512 chunks of 16B
            int id = t + 128 * i;
            int row = id >> 4, c = (id & 15) * 8;
            uint32_t d = (uint32_t)__cvta_generic_to_shared(pb + row * BPITCH + c);
            const f16* g = Bb + (size_t)(k0 + row) * N + c;
            asm volatile("cp.async.cg.shared.global [%0], [%1], 16;" :: "r"(d), "l"(g));
        }
        asm volatile("cp.async.commit_group;");
    };

    int nc = kLen / BK;
    issue(0);
    if (nc > 1) issue(1);
    for (int s = 0; s < nc; s++) {
        if (s < nc - 1) { asm volatile("cp.async.wait_group 1;"); }
        else            { asm volatile("cp.async.wait_group 0;"); }
        __syncthreads();
        if (s + 2 < nc) issue(s + 2);
        int buf = s % STG;
        f16* pa = sA + buf * BM * APITCH;
        f16* pb = sB + buf * BK * BPITCH;
#pragma unroll
        for (int kk = 0; kk < 2; kk++) {
            int k = kk * 16;
            uint32_t ar[4][4], br[4][4];
#pragma unroll
            for (int mi = 0; mi < 4; mi++) {
                int row = wm + mi * 16 + (lane & 7) + ((lane >> 3) & 1) * 8;
                int col = k + (lane >> 4) * 8;
                uint32_t addr = (uint32_t)__cvta_generic_to_shared(pa + row * APITCH + col);
                asm volatile("ldmatrix.sync.aligned.m8n8.x4.shared.b16 {%0,%1,%2,%3}, [%4];"
                             : "=r"(ar[mi][0]), "=r"(ar[mi][1]), "=r"(ar[mi][2]), "=r"(ar[mi][3])
                             : "r"(addr));
            }
#pragma unroll
            for (int n2 = 0; n2 < 4; n2++) {
                int rrow = k + (lane & 7) + ((lane >> 3) & 1) * 8;
                int rcol = wn + n2 * 16 + (lane >> 4) * 8;
                uint32_t addr = (uint32_t)__cvta_generic_to_shared(pb + rrow * BPITCH + rcol);
                asm volatile("ldmatrix.sync.aligned.m8n8.x4.trans.shared.b16 {%0,%1,%2,%3}, [%4];"
                             : "=r"(br[n2][0]), "=r"(br[n2][1]), "=r"(br[n2][2]), "=r"(br[n2][3])
                             : "r"(addr));
            }
#pragma unroll
            for (int mi = 0; mi < 4; mi++)
#pragma unroll
                for (int ni = 0; ni < 8; ni++) {
                    uint32_t b0 = br[ni >> 1][(ni & 1) * 2];
                    uint32_t b1 = br[ni >> 1][(ni & 1) * 2 + 1];
                    asm volatile(
                        "mma.sync.aligned.m16n8k16.row.col.f32.f16.f16.f32 "
                        "{%0,%1,%2,%3}, {%4,%5,%6,%7}, {%8,%9}, {%0,%1,%2,%3};"
                        : "+f"(acc[mi][ni][0]), "+f"(acc[mi][ni][1]),
                          "+f"(acc[mi][ni][2]), "+f"(acc[mi][ni][3])
                        : "r"(ar[mi][0]), "r"(ar[mi][1]), "r"(ar[mi][2]), "r"(ar[mi][3]),
                          "r"(b0), "r"(b1));
                }
        }
        __syncthreads();
    }
    float* Cb = Cbase + bz * cStride + (size_t)(by * BM + wm) * N + bx * BN + wn;
#pragma unroll
    for (int mi = 0; mi < 4; mi++)
#pragma unroll
        for (int ni = 0; ni < 8; ni++) {
            int r0 = mi * 16 + (lane >> 2);
            int c0 = ni * 8 + (lane & 3) * 2;
            *(float2*)(Cb + (size_t)r0 * N + c0)       = make_float2(acc[mi][ni][0], acc[mi][ni][1]);
            *(float2*)(Cb + (size_t)(r0 + 8) * N + c0) = make_float2(acc[mi][ni][2], acc[mi][ni][3]);
        }
}

// ---------------- fused split-K reduce (4-way) + fp16 H2 store + layer-2 dots ----------------
__global__ void k_red_dots2(const float* __restrict__ att_src, const float* __restrict__ att_dst) {
    int n = blockIdx.x;
    int t = threadIdx.x, lane = t & 31, h = t >> 5;
    const size_t stride4 = (size_t)N_NODES * F2 / 4;
    const float4* p = (const float4*)g_Pk + (size_t)n * (F2 / 4);

    float4 v = p[t];
#pragma unroll
    for (int z = 1; z < KSPLIT; z++) {
        float4 a = p[z * stride4 + t];
        v.x += a.x; v.y += a.y; v.z += a.z; v.w += a.w;
    }
    __half2* h2 = (__half2*)g_H2h + (size_t)n * (F2 / 2);
    h2[2 * t]     = __floats2half2_rn(v.x, v.y);
    h2[2 * t + 1] = __floats2half2_rn(v.z, v.w);

    int c0 = lane * 4;
    const float* as = att_src + h * OUT_FEAT + c0;
    const float* ad = att_dst + h * OUT_FEAT + c0;
    float sa = v.x * as[0] + v.y * as[1] + v.z * as[2] + v.w * as[3];
    float sd = v.x * ad[0] + v.y * ad[1] + v.z * ad[2] + v.w * ad[3];
#pragma unroll
    for (int o = 16; o > 0; o >>= 1) {
        sa += __shfl_xor_sync(0xffffffffu, sa, o);
        sd += __shfl_xor_sync(0xffffffffu, sd, o);
    }
    if (lane == 0) {
        g_A2s[n * OUT_HEAD + h] = sa;
        g_A2d[n * OUT_HEAD + h] = sd;
    }
}

__device__ __forceinline__ float leaky(float x) { return x > 0.f ? x : NEG_SLOPE * x; }

// ---------------- Layer-1 softmax + aggregation + bias + elu -> fp16 ----------------
__global__ void k_agg1(const float* __restrict__ b1) {
    int n = blockIdx.x;
    int t = threadIdx.x;
    int h = t & 63, slot = t >> 6;
    int beg = g_offs[n], end = g_offs[n + 1];
    float adst = g_A1d[n * IN_HEAD + h];

    __shared__ float red[4][64];
    __shared__ float sm_m[64], sm_inv[64];
    __shared__ int   srcb[32];
    __shared__ float alpha[32][64];

    float mx = -1e30f;
    for (int j = beg + slot; j < end; j += 4) {
        int s = g_esrc[j];
        mx = fmaxf(mx, leaky(g_A1s[s * IN_HEAD + h] + adst));
    }
    red[slot][h] = mx;
    __syncthreads();
    if (slot == 0) {
        sm_m[h] = fmaxf(fmaxf(red[0][h], red[1][h]), fmaxf(red[2][h], red[3][h]));
    }
    __syncthreads();
    float M = sm_m[h];

    float sum = 0.f;
    for (int j = beg + slot; j < end; j += 4) {
        int s = g_esrc[j];
        sum += expf(leaky(g_A1s[s * IN_HEAD + h] + adst) - M);
    }
    red[slot][h] = sum;
    __syncthreads();
    if (slot == 0) {
        float d = red[0][h] + red[1][h] + red[2][h] + red[3][h];
        sm_inv[h] = 1.0f / (d + GAT_EPS);
    }
    __syncthreads();
    float INV = sm_inv[h];

    int c2 = t & 31, g = t >> 5;   // half2 pair, head group of 8
    float2 acc[8];
#pragma unroll
    for (int k = 0; k < 8; k++) acc[k] = make_float2(0.f, 0.f);

    for (int jb = beg; jb < end; jb += 32) {
        int cnt = min(32, end - jb);
        if (t < cnt) srcb[t] = g_esrc[jb + t];
        __syncthreads();
        for (int j = slot; j < cnt; j += 4) {
            int s = srcb[j];
            float e = leaky(g_A1s[s * IN_HEAD + h] + adst);
            alpha[j][h] = expf(e - M) * INV;
        }
        __syncthreads();
        int j = 0;
        for (; j + 3 < cnt; j += 4) {
            const __half2* r0 = (const __half2*)(g_H1h + (size_t)srcb[j] * F1);
            const __half2* r1 = (const __half2*)(g_H1h + (size_t)srcb[j + 1] * F1);
            const __half2* r2 = (const __half2*)(g_H1h + (size_t)srcb[j + 2] * F1);
            const __half2* r3 = (const __half2*)(g_H1h + (size_t)srcb[j + 3] * F1);
#pragma unroll
            for (int k = 0; k < 8; k++) {
                int hh = g * 8 + k;
                int idx = hh * 32 + c2;
                float2 f0 = __half22float2(r0[idx]);
                float2 f1 = __half22float2(r1[idx]);
                float2 f2 = __half22float2(r2[idx]);
                float2 f3 = __half22float2(r3[idx]);
                float a0 = alpha[j][hh], a1 = alpha[j + 1][hh];
                float a2 = alpha[j + 2][hh], a3 = alpha[j + 3][hh];
                acc[k].x += a0 * f0.x + a1 * f1.x + a2 * f2.x + a3 * f3.x;
                acc[k].y += a0 * f0.y + a1 * f1.y + a2 * f2.y + a3 * f3.y;
            }
        }
        for (; j < cnt; j++) {
            const __half2* row = (const __half2*)(g_H1h + (size_t)srcb[j] * F1);
#pragma unroll
            for (int k = 0; k < 8; k++) {
                int hh = g * 8 + k;
                float2 f = __half22float2(row[hh * 32 + c2]);
                float a = alpha[j][hh];
                acc[k].x += a * f.x;
                acc[k].y += a * f.y;
            }
        }
        __syncthreads();
    }
    __half2* rowo = (__half2*)(g_H1ae + (size_t)n * F1);
#pragma unroll
    for (int k = 0; k < 8; k++) {
        int hh = g * 8 + k;
        float vx = acc[k].x + b1[hh * HID + 2 * c2];
        float vy = acc[k].y + b1[hh * HID + 2 * c2 + 1];
        vx = vx > 0.f ? vx : expm1f(vx);
        vy = vy > 0.f ? vy : expm1f(vy);
        rowo[hh * 32 + c2] = __floats2half2_rn(vx, vy);
    }
}

// ---------------- Layer-2 softmax + aggregation + head-mean + bias ----------------
__global__ void k_agg2(const float* __restrict__ b2) {
    int n = blockIdx.x;
    int t = threadIdx.x;
    int beg = g_offs[n], end = g_offs[n + 1];

    __shared__ float sm_m[OUT_HEAD], sm_inv[OUT_HEAD];
    __shared__ int   srcb[16];
    __shared__ float alpha[16][OUT_HEAD];

    if (t < OUT_HEAD) {
        float adst = g_A2d[n * OUT_HEAD + t];
        float mx = -1e30f;
        for (int j = beg; j < end; j++)
            mx = fmaxf(mx, leaky(g_A2s[g_esrc[j] * OUT_HEAD + t] + adst));
        float sum = 0.f;
        for (int j = beg; j < end; j++)
            sum += expf(leaky(g_A2s[g_esrc[j] * OUT_HEAD + t] + adst) - mx);
        sm_m[t] = mx;
        sm_inv[t] = 1.0f / (sum + GAT_EPS);
    }
    __syncthreads();

    float acc[OUT_HEAD] = {0.f, 0.f, 0.f, 0.f, 0.f};
    for (int jb = beg; jb < end; jb += 16) {
        int cnt = min(16, end - jb);
        if (t < cnt) srcb[t] = g_esrc[jb + t];
        __syncthreads();
        if (t < cnt * OUT_HEAD) {
            int j = t / OUT_HEAD, hh = t % OUT_HEAD;
            int s = srcb[j];
            float e = leaky(g_A2s[s * OUT_HEAD + hh] + g_A2d[n * OUT_HEAD + hh]);
            alpha[j][hh] = expf(e - sm_m[hh]) * sm_inv[hh];
        }
        __syncthreads();
        for (int j = 0; j < cnt; j++) {
            const f16* row = g_H2h + (size_t)srcb[j] * F2;
#pragma unroll
            for (int hh = 0; hh < OUT_HEAD; hh++)
                acc[hh] += alpha[j][hh] * __half2float(row[hh * OUT_FEAT + t]);
        }
        __syncthreads();
    }
    float o = (acc[0] + acc[1] + acc[2] + acc[3] + acc[4]) * 0.2f + b2[t];
    g_H2o[(size_t)n * OUT_FEAT + t] = o;
}

// ---------------- Final node-mean + tanh ----------------
__global__ void k_part() {
    int b = blockIdx.x, c = threadIdx.x;
    float s = 0.f;
    for (int i = 0; i < N_NODES / 32; i++)
        s += g_H2o[(size_t)(b * (N_NODES / 32) + i) * OUT_FEAT + c];
    g_part[b * OUT_FEAT + c] = s;
}

__global__ void k_final(float* __restrict__ out) {
    int c = threadIdx.x;
    float s = 0.f;
#pragma unroll
    for (int b = 0; b < 32; b++) s += g_part[b * OUT_FEAT + c];
    out[c] = tanhf(s / (float)N_NODES);
}

// ---------------- Launch ----------------
extern "C" void kernel_launch(void* const* d_in, const int* in_sizes, int n_in,
                              void* d_out, int out_size) {
    const float* x        = (const float*)d_in[0];
    const void*  ei       = d_in[1];
    const float* W1       = (const float*)d_in[2];
    const float* att_src1 = (const float*)d_in[3];
    const float* att_dst1 = (const float*)d_in[4];
    const float* b1       = (const float*)d_in[5];
    const float* W2       = (const float*)d_in[6];
    const float* att_src2 = (const float*)d_in[7];
    const float* att_dst2 = (const float*)d_in[8];
    const float* b2       = (const float*)d_in[9];
    float* out = (float*)d_out;

    static f16*   s_H1h  = nullptr;
    static float* s_Pk   = nullptr;
    static f16*   s_xh   = nullptr;
    static f16*   s_W1h  = nullptr;
    static f16*   s_H1ae = nullptr;
    static f16*   s_W2h  = nullptr;
    static cudaStream_t s2 = nullptr;
    static cudaEvent_t  evFork = nullptr, evJoin = nullptr;
    static bool   s_init = false;
    if (!s_init) {
        cudaGetSymbolAddress((void**)&s_H1h,  g_H1h);
        cudaGetSymbolAddress((void**)&s_Pk,   g_Pk);
        cudaGetSymbolAddress((void**)&s_xh,   g_xh);
        cudaGetSymbolAddress((void**)&s_W1h,  g_W1h);
        cudaGetSymbolAddress((void**)&s_H1ae, g_H1ae);
        cudaGetSymbolAddress((void**)&s_W2h,  g_W2h);
        cudaFuncSetAttribute(hgemm1, cudaFuncAttributeMaxDynamicSharedMemorySize, HG_SMEM);
        cudaFuncSetAttribute(hgemm2, cudaFuncAttributeMaxDynamicSharedMemorySize, HG_SMEM);
        cudaStreamCreateWithFlags(&s2, cudaStreamNonBlocking);
        cudaEventCreateWithFlags(&evFork, cudaEventDisableTiming);
        cudaEventCreateWithFlags(&evJoin, cudaEventDisableTiming);
        s_init = true;
    }

    // ---- fork: CSR chain + W2 convert on s2, concurrent with GEMM1 path ----
    cudaEventRecord(evFork, 0);
    cudaStreamWaitEvent(s2, evFork, 0);

    k_init   <<<(N_NODES + 256) / 256, 256, 0, s2>>>((const int*)ei);
    k_count  <<<(E2 + 255) / 256, 256, 0, s2>>>(ei);
    k_scan   <<<1, 1024, 0, s2>>>();
    k_scatter<<<(E2 + 255) / 256, 256, 0, s2>>>(ei);
    k_cvt_W2 <<<((F1 * F2 / 4) + 255) / 256, 256, 0, s2>>>(W2);
    cudaEventRecord(evJoin, s2);

    // ---- main stream: GEMM1 path (k_cvt_x also zeroes A1s/A1d) ----
    k_cvt_x <<<(N_NODES * IN_FEAT / 4) / 256, 256>>>(x);
    k_cvt_W1<<<(IN_FEAT * F1 / 4) / 256, 256>>>(W1);

    // GEMM1: H1h = x_f16 @ W1_f16, K=256, fp16 out + fused layer-1 dots
    hgemm1<<<dim3(F1 / BN, N_NODES / BM), 256, HG_SMEM>>>(
        s_xh, s_W1h, s_H1h, F1, IN_FEAT, IN_FEAT, att_src1, att_dst1);

    // ---- join: agg1 needs CSR; GEMM2 needs W2h ----
    cudaStreamWaitEvent(0, evJoin, 0);

    k_agg1<<<N_NODES, 256>>>(b1);

    // GEMM2: 64x64 warp tiles, split-K=4, kLen=1024 (640 CTAs)
    hgemm2<<<dim3(F2 / BN, N_NODES / BM, KSPLIT), 128, HG_SMEM>>>(
        s_H1ae, s_W2h, s_Pk, (size_t)N_NODES * F2, F2, F1, F1 / KSPLIT);

    // fused: H2h = sum(Pk) (fp16) + layer-2 attention dots
    k_red_dots2<<<N_NODES, 160>>>(att_src2, att_dst2);

    k_agg2<<<N_NODES, 128>>>(b2);

    k_part<<<32, 128>>>();
    k_final<<<1, 128>>>(out);
}